// round 8
// baseline (speedup 1.0000x reference)
#include <cuda_runtime.h>
#include <cuda_bf16.h>
#include <cstdint>
#include <stdint.h>
#include <math.h>

typedef unsigned short ushort_t;

// ---------------------------------------------------------------------------
// Scratch: pre-split bf16 hi/lo buffers (uint2 = 4 bf16), no allocations
// ---------------------------------------------------------------------------
__device__ uint2 g_khi[12582912], g_klo[12582912];   // kf    48x256x4096
__device__ uint2 g_ehi[12582912], g_elo[12582912];   // exp'd kf
__device__ uint2 g_qhi[4194304],  g_qlo[4194304];    // query 16x256x4096
__device__ uint2 g_eqh[4194304],  g_eql[4194304];    // exp'd query
__device__ uint2 g_rhi[25165824], g_rlo[25165824];   // refs  48x512x4096
__device__ uint2 g_xhi[8388608],  g_xlo[8388608];    // x     16x512x4096
__device__ uint2 g_kwh[32768],    g_kwl[32768];      // K_w   256x512
__device__ uint2 g_fwh[98304],    g_fwl[98304];      // f_w   512x768
__device__ uint2 g_kpbh[786432],  g_kpbl[786432];    // kpbs  16x768x256
__device__ uint2 g_qpbh[262144],  g_qpbl[262144];    // qpb   16x256x256
__device__ uint2 g_shi[786432],   g_slo[786432];     // softmax(sim) 16x256x768
__device__ uint2 g_vhi[262144],   g_vlo[262144];     // proto 16x256x256
__device__ uint2 g_cmh[4194304],  g_cml[4194304];    // cm*qcol 16x256x4096
__device__ float g_sim[16 * 256 * 768];
__device__ float g_value[16 * 256 * 256];
__device__ float g_kmax[48 * 256], g_kinv[48 * 256];
__device__ float g_qmax[16 * 256], g_qinvs[16 * 256];
__device__ float g_qcol[16 * 4096];
__device__ float g_mean[512], g_istd[512];

// ---------------------------------------------------------------------------
// helpers
// ---------------------------------------------------------------------------
__device__ __forceinline__ uint32_t smem_u32(const void* p) {
    uint32_t a;
    asm("{ .reg .u64 t; cvta.to.shared.u64 t, %1; cvt.u32.u64 %0, t; }" : "=r"(a) : "l"(p));
    return a;
}
__device__ __forceinline__ void ldmat4(uint32_t& r0, uint32_t& r1, uint32_t& r2, uint32_t& r3,
                                       uint32_t addr) {
    asm volatile("ldmatrix.sync.aligned.m8n8.x4.shared.b16 {%0,%1,%2,%3}, [%4];"
                 : "=r"(r0), "=r"(r1), "=r"(r2), "=r"(r3) : "r"(addr));
}
__device__ __forceinline__ void mma16816(float* d, const uint32_t* a, const uint32_t* b) {
    asm volatile(
        "mma.sync.aligned.m16n8k16.row.col.f32.bf16.bf16.f32 "
        "{%0,%1,%2,%3}, {%4,%5,%6,%7}, {%8,%9}, {%0,%1,%2,%3};"
        : "+f"(d[0]), "+f"(d[1]), "+f"(d[2]), "+f"(d[3])
        : "r"(a[0]), "r"(a[1]), "r"(a[2]), "r"(a[3]), "r"(b[0]), "r"(b[1]));
}
__device__ __forceinline__ uint32_t prmt(uint32_t a, uint32_t b, uint32_t sel) {
    uint32_t r;
    asm("prmt.b32 %0, %1, %2, %3;" : "=r"(r) : "r"(a), "r"(b), "r"(sel));
    return r;
}
__device__ __forceinline__ uint32_t pack_hi2(float a, float b) {
    return prmt(__float_as_uint(a), __float_as_uint(b), 0x7632);
}
__device__ __forceinline__ float fhi(float f) {
    return __uint_as_float(__float_as_uint(f) & 0xFFFF0000u);
}
__device__ __forceinline__ void split4(float4 f, uint2& hi, uint2& lo) {
    hi = make_uint2(pack_hi2(f.x, f.y), pack_hi2(f.z, f.w));
    lo = make_uint2(pack_hi2(f.x - fhi(f.x), f.y - fhi(f.y)),
                    pack_hi2(f.z - fhi(f.z), f.w - fhi(f.w)));
}
__device__ __forceinline__ float bf_a(uint32_t w) { return __uint_as_float(w << 16); }
__device__ __forceinline__ float bf_b(uint32_t w) { return __uint_as_float(w & 0xFFFF0000u); }

// smem geometry (per buffer): A parts 128 rows, B parts 64 rows, 80 B rows.
static constexpr int ROWB    = 80;
static constexpr int A_PART  = 128 * ROWB;
static constexpr int B_PART  = 64 * ROWB;
static constexpr int OFF_A1  = 0;
static constexpr int OFF_A2  = A_PART;
static constexpr int OFF_B1  = 2 * A_PART;
static constexpr int OFF_B2  = 2 * A_PART + B_PART;
static constexpr int BUFB    = 2 * A_PART + 2 * B_PART;   // 30720
static constexpr int TG_SMEM = 2 * BUFB;                  // 61440

// ---------------------------------------------------------------------------
// Pure-bf16 split-2 GEMM. All operands pre-split (hi/lo bf16).
//   A: [M,K] row-major. TB: B [N,K]; !TB: B [K,N].
//   CONCAT (!TB): k >= Ksplit reads B2hi/B2lo.
//   EPI: 0 = fp32 C (+bias, *alpha); 1 = split bf16 Chi/Clo; 2 = split + colscale
// CTA 128x64, K chunks of 32; 8 warps 4(m)x2(n); 2 CTAs/SM.
// ---------------------------------------------------------------------------
template<bool TB, bool HASBIAS, bool CONCAT, int EPI>
__global__ void __launch_bounds__(256, 2) bgemm(
    const ushort_t* __restrict__ Ahi, const ushort_t* __restrict__ Alo,
    const ushort_t* __restrict__ Bhi, const ushort_t* __restrict__ Blo,
    float* __restrict__ C, ushort_t* __restrict__ Chi, ushort_t* __restrict__ Clo,
    int M, int N, int K, long sAz, long sBz,
    int modB, long sCb, long sCr, int ldc,
    const float* __restrict__ bias,
    const ushort_t* __restrict__ B2hi, const ushort_t* __restrict__ B2lo,
    long sB2z, int Ksplit,
    const float* __restrict__ colscale, float alpha)
{
    extern __shared__ char smem[];
    const uint32_t sb = smem_u32(smem);
    const int tid = threadIdx.x;
    const int wid = tid >> 5;
    const int lane = tid & 31;
    const int z = blockIdx.z;
    const int bm = blockIdx.y * 128;
    const int bn = blockIdx.x * 64;

    const int ar = tid >> 3;
    const int ac4 = tid & 7;
    const ushort_t* pAh = Ahi + (long)z * sAz + (long)(bm + ar) * K + ac4 * 4;
    const ushort_t* pAl = Alo + (long)z * sAz + (long)(bm + ar) * K + ac4 * 4;

    const ushort_t* pBh = nullptr;
    const ushort_t* pBl = nullptr;
    int bkp = 0, bn4 = 0;
    if (TB) {
        pBh = Bhi + (long)z * sBz + (long)(bn + ar) * K + ac4 * 4;
        pBl = Blo + (long)z * sBz + (long)(bn + ar) * K + ac4 * 4;
    } else {
        bkp = tid & 15;
        bn4 = tid >> 4;
    }

    const int nch = K >> 5;

    uint2 ah[4], al_[4], bh2[2], bl2[2];

    auto loadA = [&](int ch) {
        #pragma unroll
        for (int j = 0; j < 4; j++) {
            ah[j]  = *reinterpret_cast<const uint2*>(pAh + ch * 32 + (long)(32 * j) * K);
            al_[j] = *reinterpret_cast<const uint2*>(pAl + ch * 32 + (long)(32 * j) * K);
        }
    };
    auto loadB = [&](int ch) {
        if (TB) {
            #pragma unroll
            for (int j = 0; j < 2; j++) {
                bh2[j] = *reinterpret_cast<const uint2*>(pBh + ch * 32 + (long)(32 * j) * K);
                bl2[j] = *reinterpret_cast<const uint2*>(pBl + ch * 32 + (long)(32 * j) * K);
            }
        } else {
            const int kg = ch * 32 + 2 * bkp;
            const ushort_t *sh, *sl;
            if (CONCAT && kg >= Ksplit) {
                sh = B2hi + (long)z * sB2z + (long)(kg - Ksplit) * N + bn + bn4 * 4;
                sl = B2lo + (long)z * sB2z + (long)(kg - Ksplit) * N + bn + bn4 * 4;
            } else {
                sh = Bhi + (long)z * sBz + (long)kg * N + bn + bn4 * 4;
                sl = Blo + (long)z * sBz + (long)kg * N + bn + bn4 * 4;
            }
            bh2[0] = *reinterpret_cast<const uint2*>(sh);
            bh2[1] = *reinterpret_cast<const uint2*>(sh + N);
            bl2[0] = *reinterpret_cast<const uint2*>(sl);
            bl2[1] = *reinterpret_cast<const uint2*>(sl + N);
        }
    };
    auto stash = [&](int buf) {
        char* base = smem + buf * BUFB;
        #pragma unroll
        for (int j = 0; j < 4; j++) {
            const int off = (ar + 32 * j) * ROWB + ac4 * 8;
            *reinterpret_cast<uint2*>(base + OFF_A1 + off) = ah[j];
            *reinterpret_cast<uint2*>(base + OFF_A2 + off) = al_[j];
        }
        if (TB) {
            #pragma unroll
            for (int j = 0; j < 2; j++) {
                const int off = (ar + 32 * j) * ROWB + ac4 * 8;
                *reinterpret_cast<uint2*>(base + OFF_B1 + off) = bh2[j];
                *reinterpret_cast<uint2*>(base + OFF_B2 + off) = bl2[j];
            }
        } else {
            // transpose k-pairs into [n][k] layout: PRMT selects per-n bf16 halves
            const uint32_t selL = 0x5410, selH = 0x7632;
            uint32_t h0 = prmt(bh2[0].x, bh2[1].x, selL);
            uint32_t h1 = prmt(bh2[0].x, bh2[1].x, selH);
            uint32_t h2 = prmt(bh2[0].y, bh2[1].y, selL);
            uint32_t h3 = prmt(bh2[0].y, bh2[1].y, selH);
            uint32_t l0 = prmt(bl2[0].x, bl2[1].x, selL);
            uint32_t l1 = prmt(bl2[0].x, bl2[1].x, selH);
            uint32_t l2 = prmt(bl2[0].y, bl2[1].y, selL);
            uint32_t l3 = prmt(bl2[0].y, bl2[1].y, selH);
            const int ob = (bn4 * 4) * ROWB + bkp * 4;
            *reinterpret_cast<uint32_t*>(base + OFF_B1 + ob)            = h0;
            *reinterpret_cast<uint32_t*>(base + OFF_B1 + ob + ROWB)     = h1;
            *reinterpret_cast<uint32_t*>(base + OFF_B1 + ob + 2 * ROWB) = h2;
            *reinterpret_cast<uint32_t*>(base + OFF_B1 + ob + 3 * ROWB) = h3;
            *reinterpret_cast<uint32_t*>(base + OFF_B2 + ob)            = l0;
            *reinterpret_cast<uint32_t*>(base + OFF_B2 + ob + ROWB)     = l1;
            *reinterpret_cast<uint32_t*>(base + OFF_B2 + ob + 2 * ROWB) = l2;
            *reinterpret_cast<uint32_t*>(base + OFF_B2 + ob + 3 * ROWB) = l3;
        }
    };

    loadA(0); loadB(0);
    stash(0);
    __syncthreads();

    float d[2][4][4];
    #pragma unroll
    for (int i = 0; i < 2; i++)
        #pragma unroll
        for (int j = 0; j < 4; j++)
            #pragma unroll
            for (int q = 0; q < 4; q++) d[i][j][q] = 0.f;

    const int wm = (wid >> 1) * 32;
    const int wn = (wid & 1) * 32;
    const int lr = lane & 15;
    const int lc = lane >> 4;

    for (int ch = 0; ch < nch; ch++) {
        const bool hasNext = (ch + 1 < nch);
        if (hasNext) { loadA(ch + 1); loadB(ch + 1); }

        const uint32_t base = sb + (ch & 1) * BUFB;
        #pragma unroll
        for (int ks = 0; ks < 2; ks++) {
            const uint32_t koff = ks * 32 + lc * 16;
            uint32_t fah[2][4], fal[2][4], fbh[4][2], fbl[4][2];
            #pragma unroll
            for (int mt = 0; mt < 2; mt++)
                ldmat4(fah[mt][0], fah[mt][1], fah[mt][2], fah[mt][3],
                       base + OFF_A1 + (wm + mt * 16 + lr) * ROWB + koff);
            #pragma unroll
            for (int bt = 0; bt < 2; bt++) {
                uint32_t r0, r1, r2, r3;
                ldmat4(r0, r1, r2, r3, base + OFF_B1 + (wn + bt * 16 + lr) * ROWB + koff);
                fbh[2 * bt][0] = r0; fbh[2 * bt][1] = r2;
                fbh[2 * bt + 1][0] = r1; fbh[2 * bt + 1][1] = r3;
            }
            #pragma unroll
            for (int mt = 0; mt < 2; mt++)
                #pragma unroll
                for (int nt = 0; nt < 4; nt++) mma16816(d[mt][nt], fah[mt], fbh[nt]);
            #pragma unroll
            for (int bt = 0; bt < 2; bt++) {
                uint32_t r0, r1, r2, r3;
                ldmat4(r0, r1, r2, r3, base + OFF_B2 + (wn + bt * 16 + lr) * ROWB + koff);
                fbl[2 * bt][0] = r0; fbl[2 * bt][1] = r2;
                fbl[2 * bt + 1][0] = r1; fbl[2 * bt + 1][1] = r3;
            }
            #pragma unroll
            for (int mt = 0; mt < 2; mt++)
                #pragma unroll
                for (int nt = 0; nt < 4; nt++) mma16816(d[mt][nt], fah[mt], fbl[nt]);
            #pragma unroll
            for (int mt = 0; mt < 2; mt++)
                ldmat4(fal[mt][0], fal[mt][1], fal[mt][2], fal[mt][3],
                       base + OFF_A2 + (wm + mt * 16 + lr) * ROWB + koff);
            #pragma unroll
            for (int mt = 0; mt < 2; mt++)
                #pragma unroll
                for (int nt = 0; nt < 4; nt++) mma16816(d[mt][nt], fal[mt], fbh[nt]);
        }
        if (hasNext) stash((ch + 1) & 1);
        __syncthreads();
    }

    // epilogue
    const long coff = (long)(z % modB) * sCb + (long)(z / modB) * sCr;
    #pragma unroll
    for (int mt = 0; mt < 2; mt++) {
        const int r0 = bm + wm + mt * 16 + (lane >> 2);
        const float bi0 = HASBIAS ? bias[r0] : 0.f;
        const float bi8 = HASBIAS ? bias[r0 + 8] : 0.f;
        #pragma unroll
        for (int nt = 0; nt < 4; nt++) {
            const int c0 = bn + wn + nt * 8 + (lane & 3) * 2;
            float v0 = d[mt][nt][0] * alpha + bi0;
            float v1 = d[mt][nt][1] * alpha + bi0;
            float v2 = d[mt][nt][2] * alpha + bi8;
            float v3 = d[mt][nt][3] * alpha + bi8;
            if (EPI == 2) {
                const float2 cs = *reinterpret_cast<const float2*>(colscale + (long)z * N + c0);
                v0 *= cs.x; v1 *= cs.y; v2 *= cs.x; v3 *= cs.y;
            }
            if (EPI == 0) {
                float* p0 = C + coff + (long)r0 * ldc + c0;
                float* p1 = C + coff + (long)(r0 + 8) * ldc + c0;
                *reinterpret_cast<float2*>(p0) = make_float2(v0, v1);
                *reinterpret_cast<float2*>(p1) = make_float2(v2, v3);
            } else {
                const long o0 = coff + (long)r0 * ldc + c0;
                const long o1 = coff + (long)(r0 + 8) * ldc + c0;
                *reinterpret_cast<uint32_t*>(Chi + o0) = pack_hi2(v0, v1);
                *reinterpret_cast<uint32_t*>(Clo + o0) = pack_hi2(v0 - fhi(v0), v1 - fhi(v1));
                *reinterpret_cast<uint32_t*>(Chi + o1) = pack_hi2(v2, v3);
                *reinterpret_cast<uint32_t*>(Clo + o1) = pack_hi2(v2 - fhi(v2), v3 - fhi(v3));
            }
        }
    }
}

// ---------------------------------------------------------------------------
// convert / reduction kernels
// ---------------------------------------------------------------------------
__global__ void split_pass(const float4* __restrict__ in, uint2* __restrict__ hi,
                           uint2* __restrict__ lo, long n)
{
    const long i = (long)blockIdx.x * blockDim.x + threadIdx.x;
    if (i >= n) return;
    uint2 h, l;
    split4(in[i], h, l);
    hi[i] = h; lo[i] = l;
}

__device__ __forceinline__ float blockReduce(float v, bool ismax) {
    __shared__ float sh[32];
    __syncthreads();
    int lane = threadIdx.x & 31, wid = threadIdx.x >> 5;
    #pragma unroll
    for (int o = 16; o; o >>= 1) {
        float t = __shfl_xor_sync(0xffffffffu, v, o);
        v = ismax ? fmaxf(v, t) : (v + t);
    }
    if (lane == 0) sh[wid] = v;
    __syncthreads();
    int nw = (blockDim.x + 31) >> 5;
    if (wid == 0) {
        v = (lane < nw) ? sh[lane] : (ismax ? -1e30f : 0.f);
        #pragma unroll
        for (int o = 16; o; o >>= 1) {
            float t = __shfl_xor_sync(0xffffffffu, v, o);
            v = ismax ? fmaxf(v, t) : (v + t);
        }
        if (lane == 0) sh[0] = v;
    }
    __syncthreads();
    return sh[0];
}

// row stats over split bf16 rows of length 4096 (1024 uint2)
__global__ void row_stats_split(const uint2* __restrict__ hi, const uint2* __restrict__ lo,
                                float* __restrict__ omax, float* __restrict__ oinv)
{
    const long row = blockIdx.x;
    const long base = row * 1024;
    float m = -1e30f;
    for (int q = threadIdx.x; q < 1024; q += 256) {
        const uint2 h = hi[base + q], l = lo[base + q];
        m = fmaxf(m, fmaxf(fmaxf(bf_a(h.x) + bf_a(l.x), bf_b(h.x) + bf_b(l.x)),
                           fmaxf(bf_a(h.y) + bf_a(l.y), bf_b(h.y) + bf_b(l.y))));
    }
    m = blockReduce(m, true);
    float s = 0.f;
    for (int q = threadIdx.x; q < 1024; q += 256) {
        const uint2 h = hi[base + q], l = lo[base + q];
        s += __expf(bf_a(h.x) + bf_a(l.x) - m) + __expf(bf_b(h.x) + bf_b(l.x) - m)
           + __expf(bf_a(h.y) + bf_a(l.y) - m) + __expf(bf_b(h.y) + bf_b(l.y) - m);
    }
    s = blockReduce(s, false);
    if (threadIdx.x == 0) { omax[row] = m; oinv[row] = 1.f / s; }
}

// exp transform: e = exp(v - max)*inv, re-split; rows of 4096
__global__ void exp_split(const uint2* __restrict__ hi, const uint2* __restrict__ lo,
                          const float* __restrict__ rmax, const float* __restrict__ rinv,
                          uint2* __restrict__ ehi, uint2* __restrict__ elo)
{
    const long row = blockIdx.x;
    const float m = rmax[row], iv = rinv[row];
    const long base = row * 1024;
    for (int q = threadIdx.x; q < 1024; q += 256) {
        const uint2 h = hi[base + q], l = lo[base + q];
        float4 e;
        e.x = __expf(bf_a(h.x) + bf_a(l.x) - m) * iv;
        e.y = __expf(bf_b(h.x) + bf_b(l.x) - m) * iv;
        e.z = __expf(bf_a(h.y) + bf_a(l.y) - m) * iv;
        e.w = __expf(bf_b(h.y) + bf_b(l.y) - m) * iv;
        uint2 oh, ol;
        split4(e, oh, ol);
        ehi[base + q] = oh; elo[base + q] = ol;
    }
}

// softmax over fp32 rows (len), output split bf16
__global__ void softmax_split(const float* __restrict__ X, ushort_t* __restrict__ hi,
                              ushort_t* __restrict__ lo, int len)
{
    const long row = blockIdx.x;
    const float* x = X + row * len;
    float m = -1e30f;
    for (int i = threadIdx.x; i < len; i += blockDim.x) m = fmaxf(m, x[i]);
    m = blockReduce(m, true);
    float s = 0.f;
    for (int i = threadIdx.x; i < len; i += blockDim.x) s += __expf(x[i] - m);
    s = blockReduce(s, false);
    const float inv = 1.f / s;
    for (int i = threadIdx.x; i < len; i += blockDim.x) {
        const float e = __expf(x[i] - m) * inv;
        const float r = e - fhi(e);
        hi[row * len + i] = (ushort_t)(__float_as_uint(e) >> 16);
        lo[row * len + i] = (ushort_t)(__float_as_uint(r) >> 16);
    }
}

// L2-normalize fp32 rows of 256, output split bf16
__global__ void norm_split(const float* __restrict__ V, ushort_t* __restrict__ hi,
                           ushort_t* __restrict__ lo)
{
    const long row = blockIdx.x;
    const float x = V[row * 256 + threadIdx.x];
    const float s = blockReduce(x * x, false);
    const float y = x * rsqrtf(s);
    const float r = y - fhi(y);
    hi[row * 256 + threadIdx.x] = (ushort_t)(__float_as_uint(y) >> 16);
    lo[row * 256 + threadIdx.x] = (ushort_t)(__float_as_uint(r) >> 16);
}

__global__ void qcol_norm(const float* __restrict__ q, float* __restrict__ out)
{
    const int b = blockIdx.y;
    const int n = blockIdx.x * 256 + threadIdx.x;
    const float* p = q + (long)b * 256 * 4096 + n;
    float s = 0.f;
    #pragma unroll 8
    for (int c = 0; c < 256; c++) { float v = p[(long)c * 4096]; s += v * v; }
    out[b * 4096 + n] = 1.f / sqrtf(s);
}

__global__ void bn_stats(const float* __restrict__ y, float* __restrict__ mean,
                         float* __restrict__ istd)
{
    const int o = blockIdx.x;
    float s = 0.f, s2 = 0.f;
    for (int b = 0; b < 16; b++) {
        const float* p = y + ((long)b * 512 + o) * 4096;
        for (int i = threadIdx.x; i < 4096; i += 256) {
            float v = p[i]; s += v; s2 += v * v;
        }
    }
    s = blockReduce(s, false);
    s2 = blockReduce(s2, false);
    if (threadIdx.x == 0) {
        float mu = s * (1.f / 65536.f);
        mean[o] = mu;
        istd[o] = 1.f / sqrtf(s2 * (1.f / 65536.f) - mu * mu + 1e-5f);
    }
}

__global__ void bn_apply(float* __restrict__ y, const float* __restrict__ mean,
                         const float* __restrict__ istd, const float* __restrict__ g,
                         const float* __restrict__ b)
{
    const long i = (long)blockIdx.x * 256 + threadIdx.x;
    const int o = (int)((i >> 12) & 511);
    float v = (y[i] - mean[o]) * istd[o] * g[o] + b[o];
    y[i] = v > 0.f ? v : 0.f;
}

// ---------------------------------------------------------------------------
// Host orchestration
// ---------------------------------------------------------------------------
struct Scratch {
    ushort_t *khi, *klo, *ehi, *elo, *qhi, *qlo, *eqh, *eql, *rhi, *rlo, *xhi, *xlo;
    ushort_t *kwh, *kwl, *fwh, *fwl, *kpbh, *kpbl, *qpbh, *qpbl, *shi, *slo, *vhi, *vlo, *cmh, *cml;
    float *sim, *value, *kmax, *kinv, *qmax, *qinvs, *qcol, *mean, *istd;
};

static Scratch fetch_scratch() {
    Scratch s;
    cudaGetSymbolAddress((void**)&s.khi, g_khi);   cudaGetSymbolAddress((void**)&s.klo, g_klo);
    cudaGetSymbolAddress((void**)&s.ehi, g_ehi);   cudaGetSymbolAddress((void**)&s.elo, g_elo);
    cudaGetSymbolAddress((void**)&s.qhi, g_qhi);   cudaGetSymbolAddress((void**)&s.qlo, g_qlo);
    cudaGetSymbolAddress((void**)&s.eqh, g_eqh);   cudaGetSymbolAddress((void**)&s.eql, g_eql);
    cudaGetSymbolAddress((void**)&s.rhi, g_rhi);   cudaGetSymbolAddress((void**)&s.rlo, g_rlo);
    cudaGetSymbolAddress((void**)&s.xhi, g_xhi);   cudaGetSymbolAddress((void**)&s.xlo, g_xlo);
    cudaGetSymbolAddress((void**)&s.kwh, g_kwh);   cudaGetSymbolAddress((void**)&s.kwl, g_kwl);
    cudaGetSymbolAddress((void**)&s.fwh, g_fwh);   cudaGetSymbolAddress((void**)&s.fwl, g_fwl);
    cudaGetSymbolAddress((void**)&s.kpbh, g_kpbh); cudaGetSymbolAddress((void**)&s.kpbl, g_kpbl);
    cudaGetSymbolAddress((void**)&s.qpbh, g_qpbh); cudaGetSymbolAddress((void**)&s.qpbl, g_qpbl);
    cudaGetSymbolAddress((void**)&s.shi, g_shi);   cudaGetSymbolAddress((void**)&s.slo, g_slo);
    cudaGetSymbolAddress((void**)&s.vhi, g_vhi);   cudaGetSymbolAddress((void**)&s.vlo, g_vlo);
    cudaGetSymbolAddress((void**)&s.cmh, g_cmh);   cudaGetSymbolAddress((void**)&s.cml, g_cml);
    cudaGetSymbolAddress((void**)&s.sim, g_sim);   cudaGetSymbolAddress((void**)&s.value, g_value);
    cudaGetSymbolAddress((void**)&s.kmax, g_kmax); cudaGetSymbolAddress((void**)&s.kinv, g_kinv);
    cudaGetSymbolAddress((void**)&s.qmax, g_qmax); cudaGetSymbolAddress((void**)&s.qinvs, g_qinvs);
    cudaGetSymbolAddress((void**)&s.qcol, g_qcol);
    cudaGetSymbolAddress((void**)&s.mean, g_mean); cudaGetSymbolAddress((void**)&s.istd, g_istd);
    cudaFuncSetAttribute(bgemm<false, true,  false, 1>, cudaFuncAttributeMaxDynamicSharedMemorySize, TG_SMEM);
    cudaFuncSetAttribute(bgemm<true,  false, false, 1>, cudaFuncAttributeMaxDynamicSharedMemorySize, TG_SMEM);
    cudaFuncSetAttribute(bgemm<true,  false, false, 0>, cudaFuncAttributeMaxDynamicSharedMemorySize, TG_SMEM);
    cudaFuncSetAttribute(bgemm<false, false, false, 0>, cudaFuncAttributeMaxDynamicSharedMemorySize, TG_SMEM);
    cudaFuncSetAttribute(bgemm<false, false, false, 2>, cudaFuncAttributeMaxDynamicSharedMemorySize, TG_SMEM);
    cudaFuncSetAttribute(bgemm<false, true,  true,  0>, cudaFuncAttributeMaxDynamicSharedMemorySize, TG_SMEM);
    return s;
}

extern "C" void kernel_launch(void* const* d_in, const int* in_sizes, int n_in,
                              void* d_out, int out_size)
{
    (void)in_sizes; (void)n_in; (void)out_size;
    static Scratch s = fetch_scratch();

    const float* x     = (const float*)d_in[0];
    const float* query = (const float*)d_in[1];
    const float* refs  = (const float*)d_in[2];
    const float* K_w   = (const float*)d_in[3];
    const float* K_b   = (const float*)d_in[4];
    // d_in[5], d_in[6] = V_w, V_b : dead code in the reference.
    const float* f_w   = (const float*)d_in[7];
    const float* f_b   = (const float*)d_in[8];
    const float* bn_g  = (const float*)d_in[9];
    const float* bn_b  = (const float*)d_in[10];
    float* out = (float*)d_out;

    // 0) pre-split inputs to bf16 hi/lo
    split_pass<<<98304, 256>>>((const float4*)refs,  (uint2*)s.rhi, (uint2*)s.rlo, 25165824L);
    split_pass<<<32768, 256>>>((const float4*)x,     (uint2*)s.xhi, (uint2*)s.xlo, 8388608L);
    split_pass<<<16384, 256>>>((const float4*)query, (uint2*)s.qhi, (uint2*)s.qlo, 4194304L);
    split_pass<<<128,   256>>>((const float4*)K_w,   (uint2*)s.kwh, (uint2*)s.kwl, 32768L);
    split_pass<<<384,   256>>>((const float4*)f_w,   (uint2*)s.fwh, (uint2*)s.fwl, 98304L);

    // 1) kf = K_w @ refs + K_b  -> split bf16 khi/klo (fp32 kf never materialized)
    bgemm<false, true, false, 1><<<dim3(64, 2, 48), 256, TG_SMEM>>>(
        s.kwh, s.kwl, s.rhi, s.rlo, nullptr, s.khi, s.klo,
        256, 4096, 512, 0, 512L * 4096,
        48, 256L * 4096, 0, 4096,
        K_b, nullptr, nullptr, 0, 0, nullptr, 1.f);

    // 2) softmax row stats + exp transforms
    row_stats_split<<<48 * 256, 256>>>((const uint2*)s.khi, (const uint2*)s.klo, s.kmax, s.kinv);
    row_stats_split<<<16 * 256, 256>>>((const uint2*)s.qhi, (const uint2*)s.qlo, s.qmax, s.qinvs);
    exp_split<<<48 * 256, 256>>>((const uint2*)s.khi, (const uint2*)s.klo, s.kmax, s.kinv,
                                 (uint2*)s.ehi, (uint2*)s.elo);
    exp_split<<<16 * 256, 256>>>((const uint2*)s.qhi, (const uint2*)s.qlo, s.qmax, s.qinvs,
                                 (uint2*)s.eqh, (uint2*)s.eql);

    // 3) k_pb = softmax(kf) @ kf^T  (TB) -> kpbs split
    bgemm<true, false, false, 1><<<dim3(4, 2, 48), 256, TG_SMEM>>>(
        s.ehi, s.elo, s.khi, s.klo, nullptr, s.kpbh, s.kpbl,
        256, 256, 4096, 256L * 4096, 256L * 4096,
        16, 768L * 256, 256L * 256, 256,
        nullptr, nullptr, nullptr, 0, 0, nullptr, 1.f);

    // 4) q_pb -> split
    bgemm<true, false, false, 1><<<dim3(4, 2, 16), 256, TG_SMEM>>>(
        s.eqh, s.eql, s.qhi, s.qlo, nullptr, s.qpbh, s.qpbl,
        256, 256, 4096, 256L * 4096, 256L * 4096,
        16, 256L * 256, 0, 256,
        nullptr, nullptr, nullptr, 0, 0, nullptr, 1.f);

    // 5) sim = (q_pb @ k_pbs^T) / 16  -> fp32
    bgemm<true, false, false, 0><<<dim3(12, 2, 16), 256, TG_SMEM>>>(
        s.qpbh, s.qpbl, s.kpbh, s.kpbl, s.sim, nullptr, nullptr,
        256, 768, 256, 256L * 256, 768L * 256,
        16, 256L * 768, 0, 768,
        nullptr, nullptr, nullptr, 0, 0, nullptr, 0.0625f);

    // 6) softmax(sim) -> split bf16
    softmax_split<<<16 * 256, 256>>>(s.sim, s.shi, s.slo, 768);

    // 7) value = softmax(sim) @ k_pbs (NN) -> fp32
    bgemm<false, false, false, 0><<<dim3(4, 2, 16), 256, TG_SMEM>>>(
        s.shi, s.slo, s.kpbh, s.kpbl, s.value, nullptr, nullptr,
        256, 256, 768, 256L * 768, 768L * 256,
        16, 256L * 256, 0, 256,
        nullptr, nullptr, nullptr, 0, 0, nullptr, 1.f);

    // 8) normalize prototypes -> split; query column norms
    norm_split<<<16 * 256, 256>>>(s.value, s.vhi, s.vlo);
    qcol_norm<<<dim3(16, 16), 256>>>(query, s.qcol);

    // 9) cm = proto_n @ query, scaled by qcol -> split bf16 (feeds stage 10 directly)
    bgemm<false, false, false, 2><<<dim3(64, 2, 16), 256, TG_SMEM>>>(
        s.vhi, s.vlo, s.qhi, s.qlo, nullptr, s.cmh, s.cml,
        256, 4096, 256, 256L * 256, 256L * 4096,
        16, 256L * 4096, 0, 4096,
        nullptr, nullptr, nullptr, 0, 0, s.qcol, 1.f);

    // 10) y = f_w @ concat(x, cm) + f_b -> fp32 out
    bgemm<false, true, true, 0><<<dim3(64, 4, 16), 256, TG_SMEM>>>(
        s.fwh, s.fwl, s.xhi, s.xlo, out, nullptr, nullptr,
        512, 4096, 768, 0, 512L * 4096,
        16, 512L * 4096, 0, 4096,
        f_b, s.cmh, s.cml, 1048576L, 512, nullptr, 1.f);

    // 11) BatchNorm (batch stats) + ReLU
    bn_stats<<<512, 256>>>(out, s.mean, s.istd);
    bn_apply<<<131072, 256>>>(out, s.mean, s.istd, bn_g, bn_b);
}

// round 9
// speedup vs baseline: 1.1840x; 1.1840x over previous
#include <cuda_runtime.h>
#include <cuda_bf16.h>
#include <cstdint>
#include <stdint.h>
#include <math.h>

typedef unsigned short ushort_t;

// ---------------------------------------------------------------------------
// Scratch (static __device__ arrays; no allocations anywhere)
// ---------------------------------------------------------------------------
__device__ float g_kf[48u * 256u * 4096u];   // 201 MB
__device__ float g_kmax[48 * 256];
__device__ float g_kinv[48 * 256];
__device__ float g_qmax[16 * 256];
__device__ float g_qinvs[16 * 256];
__device__ float g_kpbs[16 * 768 * 256];
__device__ float g_qpb[16 * 256 * 256];
__device__ float g_sim[16 * 256 * 768];
__device__ float g_value[16 * 256 * 256];
__device__ float g_qcol[16 * 4096];
__device__ float g_cm[16u * 256u * 4096u];   // 67 MB
__device__ float g_mean[512];
__device__ float g_istd[512];
// pre-split bf16 (hi/lo) for weight-class operands (A of NN stages)
__device__ ushort_t g_kwh[256 * 512],  g_kwl[256 * 512];    // K_w
__device__ ushort_t g_fwh[512 * 768],  g_fwl[512 * 768];    // f_w
__device__ ushort_t g_vhi[16 * 256 * 256], g_vlo[16 * 256 * 256]; // proto_n

// ---------------------------------------------------------------------------
// mma.sync helpers (plain sm_80+ PTX — valid under compute_103)
// ---------------------------------------------------------------------------
__device__ __forceinline__ uint32_t smem_u32(const void* p) {
    uint32_t a;
    asm("{ .reg .u64 t; cvta.to.shared.u64 t, %1; cvt.u32.u64 %0, t; }" : "=r"(a) : "l"(p));
    return a;
}
__device__ __forceinline__ void ldmat4(uint32_t& r0, uint32_t& r1, uint32_t& r2, uint32_t& r3,
                                       uint32_t addr) {
    asm volatile("ldmatrix.sync.aligned.m8n8.x4.shared.b16 {%0,%1,%2,%3}, [%4];"
                 : "=r"(r0), "=r"(r1), "=r"(r2), "=r"(r3) : "r"(addr));
}
__device__ __forceinline__ void mma16816(float* d, const uint32_t* a, const uint32_t* b) {
    asm volatile(
        "mma.sync.aligned.m16n8k16.row.col.f32.bf16.bf16.f32 "
        "{%0,%1,%2,%3}, {%4,%5,%6,%7}, {%8,%9}, {%0,%1,%2,%3};"
        : "+f"(d[0]), "+f"(d[1]), "+f"(d[2]), "+f"(d[3])
        : "r"(a[0]), "r"(a[1]), "r"(a[2]), "r"(a[3]), "r"(b[0]), "r"(b[1]));
}
__device__ __forceinline__ uint32_t pack_hi2(float a, float b) {
    uint32_t r;
    asm("prmt.b32 %0, %1, %2, 0x7632;" : "=r"(r)
        : "r"(__float_as_uint(a)), "r"(__float_as_uint(b)));
    return r;
}
__device__ __forceinline__ float fhi(float f) {
    return __uint_as_float(__float_as_uint(f) & 0xFFFF0000u);
}
__device__ __forceinline__ void split4(float4 f, uint2& hi, uint2& lo) {
    hi = make_uint2(pack_hi2(f.x, f.y), pack_hi2(f.z, f.w));
    lo = make_uint2(pack_hi2(f.x - fhi(f.x), f.y - fhi(f.y)),
                    pack_hi2(f.z - fhi(f.z), f.w - fhi(f.w)));
}

// smem geometry (per buffer): A parts 128 rows, B parts 64 rows, 80 B rows.
static constexpr int ROWB    = 80;             // 32 bf16 + 8 pad
static constexpr int A_PART  = 128 * ROWB;
static constexpr int B_PART  = 64 * ROWB;
static constexpr int OFF_A1  = 0;
static constexpr int OFF_A2  = A_PART;
static constexpr int OFF_B1  = 2 * A_PART;
static constexpr int OFF_B2  = 2 * A_PART + B_PART;
static constexpr int BUFB    = 2 * A_PART + 2 * B_PART;  // 30720
static constexpr int TG_SMEM = 2 * BUFB;                 // 61440

// ---------------------------------------------------------------------------
// mma.sync bf16-split2 GEMM: C = alpha*(A' @ B') (+bias[r])
//   ASPLIT: A pre-split bf16 hi/lo (K-major [M,K]); else fp32 A, in-loop split
//   EXPA (fp32 A only): fused exp(a - rmax)*rinv per row
//   TB:  B row-major [N,K] (C = A @ B^T);  !TB: B row-major [K,N]
//   CONCAT (!TB): k >= Ksplit reads B2 scaled by colscale[z*N+n]
// CTA 128x64, K chunks of 32; 8 warps 4(m)x2(n); 2 CTAs/SM.
// ---------------------------------------------------------------------------
template<bool TB, bool EXPA, bool HASBIAS, bool CONCAT, bool ASPLIT>
__global__ void __launch_bounds__(256, 2) mgemm(
    const float* __restrict__ A,
    const ushort_t* __restrict__ Ahi, const ushort_t* __restrict__ Alo,
    const float* __restrict__ B, float* __restrict__ C,
    int M, int N, int K, long sAz, long sBz,
    int modB, long sCb, long sCr, int ldc,
    const float* __restrict__ rmax, const float* __restrict__ rinv,
    const float* __restrict__ bias,
    const float* __restrict__ B2, long sB2z, int Ksplit,
    const float* __restrict__ colscale, float alpha)
{
    extern __shared__ char smem[];
    const uint32_t sb = smem_u32(smem);
    const int tid = threadIdx.x;
    const int wid = tid >> 5;
    const int lane = tid & 31;
    const int z = blockIdx.z;
    const int bm = blockIdx.y * 128;
    const int bn = blockIdx.x * 64;
    const float* Bb = B + (long)z * sBz;

    // ---- A loader geometry: row = ar+32j, 4 consecutive k per thread ----
    const int ar = tid >> 3;
    const int ac4 = tid & 7;
    const float* gA0 = nullptr;
    const ushort_t* gAh = nullptr;
    const ushort_t* gAl = nullptr;
    if (ASPLIT) {
        gAh = Ahi + (long)z * sAz + (long)(bm + ar) * K + ac4 * 4;
        gAl = Alo + (long)z * sAz + (long)(bm + ar) * K + ac4 * 4;
    } else {
        gA0 = A + (long)z * sAz + (long)(bm + ar) * K + ac4 * 4;
    }

    float smx[4], siv[4];
    if (EXPA) {
        #pragma unroll
        for (int j = 0; j < 4; j++) {
            const int r = bm + ar + 32 * j;
            smx[j] = rmax[(long)z * M + r];
            siv[j] = rinv[(long)z * M + r];
        }
    }

    // ---- B loader geometry ----
    const float* gB0 = nullptr;
    int bkp = 0, bn4 = 0;
    float4 csc = make_float4(1.f, 1.f, 1.f, 1.f);
    if (TB) {
        gB0 = Bb + (long)(bn + ar) * K + ac4 * 4;
    } else {
        bkp = tid & 15;
        bn4 = tid >> 4;
        if (CONCAT)
            csc = *reinterpret_cast<const float4*>(colscale + (long)z * N + bn + bn4 * 4);
    }

    const int nch = K >> 5;

    float4 fa[4], fb[2];
    uint2 uah[4], ual[4];

    auto loadA = [&](int ch) {
        if (ASPLIT) {
            #pragma unroll
            for (int j = 0; j < 4; j++) {
                uah[j] = *reinterpret_cast<const uint2*>(gAh + ch * 32 + (long)(32 * j) * K);
                ual[j] = *reinterpret_cast<const uint2*>(gAl + ch * 32 + (long)(32 * j) * K);
            }
        } else {
            const float* p = gA0 + ch * 32;
            #pragma unroll
            for (int j = 0; j < 4; j++)
                fa[j] = *reinterpret_cast<const float4*>(p + (long)(32 * j) * K);
        }
    };
    auto loadB = [&](int ch) {
        if (TB) {
            const float* p = gB0 + ch * 32;
            #pragma unroll
            for (int j = 0; j < 2; j++)
                fb[j] = *reinterpret_cast<const float4*>(p + (long)(32 * j) * K);
        } else {
            const int kg = ch * 32 + 2 * bkp;
            const float* src;
            if (CONCAT && kg >= Ksplit)
                src = B2 + (long)z * sB2z + (long)(kg - Ksplit) * N + bn + bn4 * 4;
            else
                src = Bb + (long)kg * N + bn + bn4 * 4;
            fb[0] = *reinterpret_cast<const float4*>(src);
            fb[1] = *reinterpret_cast<const float4*>(src + N);
            if (CONCAT && kg >= Ksplit) {
                fb[0].x *= csc.x; fb[0].y *= csc.y; fb[0].z *= csc.z; fb[0].w *= csc.w;
                fb[1].x *= csc.x; fb[1].y *= csc.y; fb[1].z *= csc.z; fb[1].w *= csc.w;
            }
        }
    };
    auto stashA = [&](int buf) {
        char* a1 = smem + buf * BUFB + OFF_A1;
        char* a2 = smem + buf * BUFB + OFF_A2;
        #pragma unroll
        for (int j = 0; j < 4; j++) {
            const int off = (ar + 32 * j) * ROWB + ac4 * 8;
            if (ASPLIT) {
                *reinterpret_cast<uint2*>(a1 + off) = uah[j];
                *reinterpret_cast<uint2*>(a2 + off) = ual[j];
            } else {
                float4 f = fa[j];
                if (EXPA) {
                    const float m = smx[j], v = siv[j];
                    f.x = __expf(f.x - m) * v; f.y = __expf(f.y - m) * v;
                    f.z = __expf(f.z - m) * v; f.w = __expf(f.w - m) * v;
                }
                uint2 hi, lo;
                split4(f, hi, lo);
                *reinterpret_cast<uint2*>(a1 + off) = hi;
                *reinterpret_cast<uint2*>(a2 + off) = lo;
            }
        }
    };
    auto stashB = [&](int buf) {
        char* b1 = smem + buf * BUFB + OFF_B1;
        char* b2 = smem + buf * BUFB + OFF_B2;
        if (TB) {
            #pragma unroll
            for (int j = 0; j < 2; j++) {
                uint2 hi, lo;
                split4(fb[j], hi, lo);
                const int off = (ar + 32 * j) * ROWB + ac4 * 8;
                *reinterpret_cast<uint2*>(b1 + off) = hi;
                *reinterpret_cast<uint2*>(b2 + off) = lo;
            }
        } else {
            const float r0[4] = {fb[0].x, fb[0].y, fb[0].z, fb[0].w};
            const float r1[4] = {fb[1].x, fb[1].y, fb[1].z, fb[1].w};
            #pragma unroll
            for (int u = 0; u < 4; u++) {
                const uint32_t hi = pack_hi2(r0[u], r1[u]);
                const uint32_t lo = pack_hi2(r0[u] - fhi(r0[u]), r1[u] - fhi(r1[u]));
                const int off = (bn4 * 4 + u) * ROWB + bkp * 4;
                *reinterpret_cast<uint32_t*>(b1 + off) = hi;
                *reinterpret_cast<uint32_t*>(b2 + off) = lo;
            }
        }
    };

    loadA(0); loadB(0);
    stashA(0); stashB(0);
    __syncthreads();

    float d[2][4][4];
    #pragma unroll
    for (int i = 0; i < 2; i++)
        #pragma unroll
        for (int j = 0; j < 4; j++)
            #pragma unroll
            for (int q = 0; q < 4; q++) d[i][j][q] = 0.f;

    const int wm = (wid >> 1) * 32;
    const int wn = (wid & 1) * 32;
    const int lr = lane & 15;
    const int lc = lane >> 4;

    for (int ch = 0; ch < nch; ch++) {
        const bool hasNext = (ch + 1 < nch);
        if (hasNext) { loadA(ch + 1); loadB(ch + 1); }

        const uint32_t base = sb + (ch & 1) * BUFB;
        #pragma unroll
        for (int ks = 0; ks < 2; ks++) {
            const uint32_t koff = ks * 32 + lc * 16;
            uint32_t ah[2][4], al[2][4], bh[4][2], bl[4][2];
            #pragma unroll
            for (int mt = 0; mt < 2; mt++)
                ldmat4(ah[mt][0], ah[mt][1], ah[mt][2], ah[mt][3],
                       base + OFF_A1 + (wm + mt * 16 + lr) * ROWB + koff);
            #pragma unroll
            for (int bt = 0; bt < 2; bt++) {
                uint32_t r0, r1, r2, r3;
                ldmat4(r0, r1, r2, r3, base + OFF_B1 + (wn + bt * 16 + lr) * ROWB + koff);
                bh[2 * bt][0] = r0; bh[2 * bt][1] = r2;
                bh[2 * bt + 1][0] = r1; bh[2 * bt + 1][1] = r3;
            }
            #pragma unroll
            for (int mt = 0; mt < 2; mt++)
                #pragma unroll
                for (int nt = 0; nt < 4; nt++) mma16816(d[mt][nt], ah[mt], bh[nt]);
            #pragma unroll
            for (int bt = 0; bt < 2; bt++) {
                uint32_t r0, r1, r2, r3;
                ldmat4(r0, r1, r2, r3, base + OFF_B2 + (wn + bt * 16 + lr) * ROWB + koff);
                bl[2 * bt][0] = r0; bl[2 * bt][1] = r2;
                bl[2 * bt + 1][0] = r1; bl[2 * bt + 1][1] = r3;
            }
            #pragma unroll
            for (int mt = 0; mt < 2; mt++)
                #pragma unroll
                for (int nt = 0; nt < 4; nt++) mma16816(d[mt][nt], ah[mt], bl[nt]);
            #pragma unroll
            for (int mt = 0; mt < 2; mt++)
                ldmat4(al[mt][0], al[mt][1], al[mt][2], al[mt][3],
                       base + OFF_A2 + (wm + mt * 16 + lr) * ROWB + koff);
            #pragma unroll
            for (int mt = 0; mt < 2; mt++)
                #pragma unroll
                for (int nt = 0; nt < 4; nt++) mma16816(d[mt][nt], al[mt], bh[nt]);
        }
        if (hasNext) { stashA((ch + 1) & 1); stashB((ch + 1) & 1); }
        __syncthreads();
    }

    // epilogue
    const long coff = (long)(z % modB) * sCb + (long)(z / modB) * sCr;
    #pragma unroll
    for (int mt = 0; mt < 2; mt++) {
        const int r0 = bm + wm + mt * 16 + (lane >> 2);
        const float bi0 = HASBIAS ? bias[r0] : 0.f;
        const float bi8 = HASBIAS ? bias[r0 + 8] : 0.f;
        #pragma unroll
        for (int nt = 0; nt < 4; nt++) {
            const int c0 = bn + wn + nt * 8 + (lane & 3) * 2;
            float* p0 = C + coff + (long)r0 * ldc + c0;
            float* p1 = C + coff + (long)(r0 + 8) * ldc + c0;
            *reinterpret_cast<float2*>(p0) =
                make_float2(d[mt][nt][0] * alpha + bi0, d[mt][nt][1] * alpha + bi0);
            *reinterpret_cast<float2*>(p1) =
                make_float2(d[mt][nt][2] * alpha + bi8, d[mt][nt][3] * alpha + bi8);
        }
    }
}

// ---------------------------------------------------------------------------
// convert / reduction / elementwise kernels
// ---------------------------------------------------------------------------
__global__ void split_pass(const float4* __restrict__ in, uint2* __restrict__ hi,
                           uint2* __restrict__ lo, long n)
{
    const long i = (long)blockIdx.x * blockDim.x + threadIdx.x;
    if (i >= n) return;
    uint2 h, l;
    split4(in[i], h, l);
    hi[i] = h; lo[i] = l;
}

__device__ __forceinline__ float blockReduce(float v, bool ismax) {
    __shared__ float sh[32];
    __syncthreads();
    int lane = threadIdx.x & 31, wid = threadIdx.x >> 5;
    #pragma unroll
    for (int o = 16; o; o >>= 1) {
        float t = __shfl_xor_sync(0xffffffffu, v, o);
        v = ismax ? fmaxf(v, t) : (v + t);
    }
    if (lane == 0) sh[wid] = v;
    __syncthreads();
    int nw = (blockDim.x + 31) >> 5;
    if (wid == 0) {
        v = (lane < nw) ? sh[lane] : (ismax ? -1e30f : 0.f);
        #pragma unroll
        for (int o = 16; o; o >>= 1) {
            float t = __shfl_xor_sync(0xffffffffu, v, o);
            v = ismax ? fmaxf(v, t) : (v + t);
        }
        if (lane == 0) sh[0] = v;
    }
    __syncthreads();
    return sh[0];
}

__global__ void row_stats(const float* __restrict__ X, float* __restrict__ omax,
                          float* __restrict__ oinv, int len)
{
    const long row = blockIdx.x;
    const float* x = X + row * len;
    float m = -1e30f;
    for (int i = threadIdx.x; i < len; i += blockDim.x) m = fmaxf(m, x[i]);
    m = blockReduce(m, true);
    float s = 0.f;
    for (int i = threadIdx.x; i < len; i += blockDim.x) s += __expf(x[i] - m);
    s = blockReduce(s, false);
    if (threadIdx.x == 0) { omax[row] = m; oinv[row] = 1.f / s; }
}

__global__ void softmax_inplace(float* __restrict__ X, int len)
{
    const long row = blockIdx.x;
    float* x = X + row * len;
    float m = -1e30f;
    for (int i = threadIdx.x; i < len; i += blockDim.x) m = fmaxf(m, x[i]);
    m = blockReduce(m, true);
    float s = 0.f;
    for (int i = threadIdx.x; i < len; i += blockDim.x) s += __expf(x[i] - m);
    s = blockReduce(s, false);
    const float inv = 1.f / s;
    for (int i = threadIdx.x; i < len; i += blockDim.x) x[i] = __expf(x[i] - m) * inv;
}

// L2-normalize fp32 rows of 256, output split bf16 (A operand of stage 9)
__global__ void norm_split(const float* __restrict__ V, ushort_t* __restrict__ hi,
                           ushort_t* __restrict__ lo)
{
    const long row = blockIdx.x;
    const float x = V[row * 256 + threadIdx.x];
    const float s = blockReduce(x * x, false);
    const float y = x * rsqrtf(s);
    const float r = y - fhi(y);
    hi[row * 256 + threadIdx.x] = (ushort_t)(__float_as_uint(y) >> 16);
    lo[row * 256 + threadIdx.x] = (ushort_t)(__float_as_uint(r) >> 16);
}

__global__ void qcol_norm(const float* __restrict__ q, float* __restrict__ out)
{
    const int b = blockIdx.y;
    const int n = blockIdx.x * 256 + threadIdx.x;
    const float* p = q + (long)b * 256 * 4096 + n;
    float s = 0.f;
    #pragma unroll 8
    for (int c = 0; c < 256; c++) { float v = p[(long)c * 4096]; s += v * v; }
    out[b * 4096 + n] = 1.f / sqrtf(s);
}

__global__ void bn_stats(const float* __restrict__ y, float* __restrict__ mean,
                         float* __restrict__ istd)
{
    const int o = blockIdx.x;
    float s = 0.f, s2 = 0.f;
    for (int b = 0; b < 16; b++) {
        const float* p = y + ((long)b * 512 + o) * 4096;
        for (int i = threadIdx.x; i < 4096; i += 256) {
            float v = p[i]; s += v; s2 += v * v;
        }
    }
    s = blockReduce(s, false);
    s2 = blockReduce(s2, false);
    if (threadIdx.x == 0) {
        float mu = s * (1.f / 65536.f);
        mean[o] = mu;
        istd[o] = 1.f / sqrtf(s2 * (1.f / 65536.f) - mu * mu + 1e-5f);
    }
}

__global__ void bn_apply(float* __restrict__ y, const float* __restrict__ mean,
                         const float* __restrict__ istd, const float* __restrict__ g,
                         const float* __restrict__ b)
{
    const long i = (long)blockIdx.x * 256 + threadIdx.x;
    const int o = (int)((i >> 12) & 511);
    float v = (y[i] - mean[o]) * istd[o] * g[o] + b[o];
    y[i] = v > 0.f ? v : 0.f;
}

// ---------------------------------------------------------------------------
// Host orchestration
// ---------------------------------------------------------------------------
struct Scratch {
    float *kf, *kmax, *kinv, *qmax, *qinvs, *kpbs, *qpb, *sim, *value, *qcol, *cm, *mean, *istd;
    ushort_t *kwh, *kwl, *fwh, *fwl, *vhi, *vlo;
};

static Scratch fetch_scratch() {
    Scratch s;
    cudaGetSymbolAddress((void**)&s.kf,    g_kf);
    cudaGetSymbolAddress((void**)&s.kmax,  g_kmax);
    cudaGetSymbolAddress((void**)&s.kinv,  g_kinv);
    cudaGetSymbolAddress((void**)&s.qmax,  g_qmax);
    cudaGetSymbolAddress((void**)&s.qinvs, g_qinvs);
    cudaGetSymbolAddress((void**)&s.kpbs,  g_kpbs);
    cudaGetSymbolAddress((void**)&s.qpb,   g_qpb);
    cudaGetSymbolAddress((void**)&s.sim,   g_sim);
    cudaGetSymbolAddress((void**)&s.value, g_value);
    cudaGetSymbolAddress((void**)&s.qcol,  g_qcol);
    cudaGetSymbolAddress((void**)&s.cm,    g_cm);
    cudaGetSymbolAddress((void**)&s.mean,  g_mean);
    cudaGetSymbolAddress((void**)&s.istd,  g_istd);
    cudaGetSymbolAddress((void**)&s.kwh,   g_kwh);
    cudaGetSymbolAddress((void**)&s.kwl,   g_kwl);
    cudaGetSymbolAddress((void**)&s.fwh,   g_fwh);
    cudaGetSymbolAddress((void**)&s.fwl,   g_fwl);
    cudaGetSymbolAddress((void**)&s.vhi,   g_vhi);
    cudaGetSymbolAddress((void**)&s.vlo,   g_vlo);
    cudaFuncSetAttribute(mgemm<false, false, true,  false, true >, cudaFuncAttributeMaxDynamicSharedMemorySize, TG_SMEM);
    cudaFuncSetAttribute(mgemm<true,  true,  false, false, false>, cudaFuncAttributeMaxDynamicSharedMemorySize, TG_SMEM);
    cudaFuncSetAttribute(mgemm<true,  false, false, false, false>, cudaFuncAttributeMaxDynamicSharedMemorySize, TG_SMEM);
    cudaFuncSetAttribute(mgemm<false, false, false, false, false>, cudaFuncAttributeMaxDynamicSharedMemorySize, TG_SMEM);
    cudaFuncSetAttribute(mgemm<false, false, false, false, true >, cudaFuncAttributeMaxDynamicSharedMemorySize, TG_SMEM);
    cudaFuncSetAttribute(mgemm<false, false, true,  true,  true >, cudaFuncAttributeMaxDynamicSharedMemorySize, TG_SMEM);
    return s;
}

extern "C" void kernel_launch(void* const* d_in, const int* in_sizes, int n_in,
                              void* d_out, int out_size)
{
    (void)in_sizes; (void)n_in; (void)out_size;
    static Scratch s = fetch_scratch();

    const float* x     = (const float*)d_in[0];
    const float* query = (const float*)d_in[1];
    const float* refs  = (const float*)d_in[2];
    const float* K_w   = (const float*)d_in[3];
    const float* K_b   = (const float*)d_in[4];
    // d_in[5], d_in[6] = V_w, V_b : dead code in the reference.
    const float* f_w   = (const float*)d_in[7];
    const float* f_b   = (const float*)d_in[8];
    const float* bn_g  = (const float*)d_in[9];
    const float* bn_b  = (const float*)d_in[10];
    float* out = (float*)d_out;

    // 0) pre-split WEIGHTS only (tiny)
    split_pass<<<128, 256>>>((const float4*)K_w, (uint2*)s.kwh, (uint2*)s.kwl, 32768L);
    split_pass<<<384, 256>>>((const float4*)f_w, (uint2*)s.fwh, (uint2*)s.fwl, 98304L);

    // 1) kf[z] = K_w @ refs[z] + K_b   (NN, bias, A pre-split)
    mgemm<false, false, true, false, true><<<dim3(64, 2, 48), 256, TG_SMEM>>>(
        nullptr, s.kwh, s.kwl, refs, s.kf, 256, 4096, 512, 0, 512L * 4096,
        48, 256L * 4096, 0, 4096,
        nullptr, nullptr, K_b, nullptr, 0, 0, nullptr, 1.f);

    // 2) softmax row stats
    row_stats<<<48 * 256, 256>>>(s.kf, s.kmax, s.kinv, 4096);
    row_stats<<<16 * 256, 256>>>(query, s.qmax, s.qinvs, 4096);

    // 3) k_pb[z] = softmax(kf[z]) @ kf[z]^T  (TB, EXPA)
    mgemm<true, true, false, false, false><<<dim3(4, 2, 48), 256, TG_SMEM>>>(
        s.kf, nullptr, nullptr, s.kf, s.kpbs, 256, 256, 4096, 256L * 4096, 256L * 4096,
        16, 768L * 256, 256L * 256, 256,
        s.kmax, s.kinv, nullptr, nullptr, 0, 0, nullptr, 1.f);

    // 4) q_pb[b] = softmax(query[b]) @ query[b]^T
    mgemm<true, true, false, false, false><<<dim3(4, 2, 16), 256, TG_SMEM>>>(
        query, nullptr, nullptr, query, s.qpb, 256, 256, 4096, 256L * 4096, 256L * 4096,
        16, 256L * 256, 0, 256,
        s.qmax, s.qinvs, nullptr, nullptr, 0, 0, nullptr, 1.f);

    // 5) sim = (q_pb @ k_pbs^T) / sqrt(256)
    mgemm<true, false, false, false, false><<<dim3(12, 2, 16), 256, TG_SMEM>>>(
        s.qpb, nullptr, nullptr, s.kpbs, s.sim, 256, 768, 256, 256L * 256, 768L * 256,
        16, 256L * 768, 0, 768,
        nullptr, nullptr, nullptr, nullptr, 0, 0, nullptr, 0.0625f);

    // 6) softmax over k
    softmax_inplace<<<16 * 256, 256>>>(s.sim, 768);

    // 7) value = sim @ k_pbs (NN)
    mgemm<false, false, false, false, false><<<dim3(4, 2, 16), 256, TG_SMEM>>>(
        s.sim, nullptr, nullptr, s.kpbs, s.value, 256, 256, 768, 256L * 768, 768L * 256,
        16, 256L * 256, 0, 256,
        nullptr, nullptr, nullptr, nullptr, 0, 0, nullptr, 1.f);

    // 8) normalize prototypes -> pre-split A for stage 9; query column norms
    norm_split<<<16 * 256, 256>>>(s.value, s.vhi, s.vlo);
    qcol_norm<<<dim3(16, 16), 256>>>(query, s.qcol);

    // 9) cm_raw = proto_n @ query  (NN, A pre-split; qcol folded into stage 10)
    mgemm<false, false, false, false, true><<<dim3(64, 2, 16), 256, TG_SMEM>>>(
        nullptr, s.vhi, s.vlo, query, s.cm, 256, 4096, 256, 256L * 256, 256L * 4096,
        16, 256L * 4096, 0, 4096,
        nullptr, nullptr, nullptr, nullptr, 0, 0, nullptr, 1.f);

    // 10) y = f_w @ concat(x, cm * qcol) + f_b  (NN, A pre-split, CONCAT)
    mgemm<false, false, true, true, true><<<dim3(64, 4, 16), 256, TG_SMEM>>>(
        nullptr, s.fwh, s.fwl, x, out, 512, 4096, 768, 0, 512L * 4096,
        16, 512L * 4096, 0, 4096,
        nullptr, nullptr, f_b, s.cm, 256L * 4096, 512, s.qcol, 1.f);

    // 11) BatchNorm (batch stats) + ReLU
    bn_stats<<<512, 256>>>(out, s.mean, s.istd);
    bn_apply<<<131072, 256>>>(out, s.mean, s.istd, bn_g, bn_b);
}

// round 10
// speedup vs baseline: 1.1863x; 1.0019x over previous
#include <cuda_runtime.h>
#include <cuda_bf16.h>
#include <cstdint>
#include <stdint.h>
#include <math.h>

typedef unsigned short ushort_t;

// ---------------------------------------------------------------------------
// Scratch (static __device__ arrays; no allocations anywhere)
// ---------------------------------------------------------------------------
__device__ float g_kf[48u * 256u * 4096u];   // 201 MB
__device__ float g_kmax[48 * 256];
__device__ float g_kinv[48 * 256];
__device__ float g_qmax[16 * 256];
__device__ float g_qinvs[16 * 256];
__device__ float g_kpbs[16 * 768 * 256];
__device__ float g_qpb[16 * 256 * 256];
__device__ float g_sim[16 * 256 * 768];
__device__ float g_value[16 * 256 * 256];
__device__ float g_qcol[16 * 4096];
__device__ float g_cm[16u * 256u * 4096u];   // 67 MB
__device__ float g_mean[512];
__device__ float g_istd[512];
// pre-split bf16 (hi/lo) for weight-class operands (A of NN stages)
__device__ ushort_t g_kwh[256 * 512],  g_kwl[256 * 512];    // K_w
__device__ ushort_t g_fwh[512 * 768],  g_fwl[512 * 768];    // f_w
__device__ ushort_t g_vhi[16 * 256 * 256], g_vlo[16 * 256 * 256]; // proto_n

// ---------------------------------------------------------------------------
// mma.sync helpers (plain sm_80+ PTX — valid under compute_103)
// ---------------------------------------------------------------------------
__device__ __forceinline__ uint32_t smem_u32(const void* p) {
    uint32_t a;
    asm("{ .reg .u64 t; cvta.to.shared.u64 t, %1; cvt.u32.u64 %0, t; }" : "=r"(a) : "l"(p));
    return a;
}
__device__ __forceinline__ void ldmat4(uint32_t& r0, uint32_t& r1, uint32_t& r2, uint32_t& r3,
                                       uint32_t addr) {
    asm volatile("ldmatrix.sync.aligned.m8n8.x4.shared.b16 {%0,%1,%2,%3}, [%4];"
                 : "=r"(r0), "=r"(r1), "=r"(r2), "=r"(r3) : "r"(addr));
}
__device__ __forceinline__ void mma16816(float* d, const uint32_t* a, const uint32_t* b) {
    asm volatile(
        "mma.sync.aligned.m16n8k16.row.col.f32.bf16.bf16.f32 "
        "{%0,%1,%2,%3}, {%4,%5,%6,%7}, {%8,%9}, {%0,%1,%2,%3};"
        : "+f"(d[0]), "+f"(d[1]), "+f"(d[2]), "+f"(d[3])
        : "r"(a[0]), "r"(a[1]), "r"(a[2]), "r"(a[3]), "r"(b[0]), "r"(b[1]));
}
__device__ __forceinline__ uint32_t pack_hi2(float a, float b) {
    uint32_t r;
    asm("prmt.b32 %0, %1, %2, 0x7632;" : "=r"(r)
        : "r"(__float_as_uint(a)), "r"(__float_as_uint(b)));
    return r;
}
__device__ __forceinline__ float fhi(float f) {
    return __uint_as_float(__float_as_uint(f) & 0xFFFF0000u);
}
__device__ __forceinline__ void split4(float4 f, uint2& hi, uint2& lo) {
    hi = make_uint2(pack_hi2(f.x, f.y), pack_hi2(f.z, f.w));
    lo = make_uint2(pack_hi2(f.x - fhi(f.x), f.y - fhi(f.y)),
                    pack_hi2(f.z - fhi(f.z), f.w - fhi(f.w)));
}

// smem geometry (per buffer): A parts 128 rows, B parts 64 rows, 80 B rows.
static constexpr int ROWB    = 80;             // 32 bf16 + 8 pad
static constexpr int A_PART  = 128 * ROWB;
static constexpr int B_PART  = 64 * ROWB;
static constexpr int OFF_A1  = 0;
static constexpr int OFF_A2  = A_PART;
static constexpr int OFF_B1  = 2 * A_PART;
static constexpr int OFF_B2  = 2 * A_PART + B_PART;
static constexpr int BUFB    = 2 * A_PART + 2 * B_PART;  // 30720
static constexpr int TG_SMEM = 2 * BUFB;                 // 61440

// ---------------------------------------------------------------------------
// mma.sync bf16-split2 GEMM: C = alpha*(A' @ B') (+bias[r])
//   ASPLIT: A pre-split bf16 hi/lo (K-major [M,K]); else fp32 A, in-loop split
//   EXPA (fp32 A only): fused exp(a - rmax)*rinv per row
//   TB:  B row-major [N,K] (C = A @ B^T);  !TB: B row-major [K,N]
//   CONCAT (!TB): k >= Ksplit reads B2 scaled by colscale[z*N+n]
// CTA 128x64, K chunks of 32; 8 warps 4(m)x2(n); 2 CTAs/SM.
// ---------------------------------------------------------------------------
template<bool TB, bool EXPA, bool HASBIAS, bool CONCAT, bool ASPLIT>
__global__ void __launch_bounds__(256, 2) mgemm(
    const float* __restrict__ A,
    const ushort_t* __restrict__ Ahi, const ushort_t* __restrict__ Alo,
    const float* __restrict__ B, float* __restrict__ C,
    int M, int N, int K, long sAz, long sBz,
    int modB, long sCb, long sCr, int ldc,
    const float* __restrict__ rmax, const float* __restrict__ rinv,
    const float* __restrict__ bias,
    const float* __restrict__ B2, long sB2z, int Ksplit,
    const float* __restrict__ colscale, float alpha)
{
    extern __shared__ char smem[];
    const uint32_t sb = smem_u32(smem);
    const int tid = threadIdx.x;
    const int wid = tid >> 5;
    const int lane = tid & 31;
    const int z = blockIdx.z;
    const int bm = blockIdx.y * 128;
    const int bn = blockIdx.x * 64;
    const float* Bb = B + (long)z * sBz;

    // ---- A loader geometry: row = ar+32j, 4 consecutive k per thread ----
    const int ar = tid >> 3;
    const int ac4 = tid & 7;
    const float* gA0 = nullptr;
    const ushort_t* gAh = nullptr;
    const ushort_t* gAl = nullptr;
    if (ASPLIT) {
        gAh = Ahi + (long)z * sAz + (long)(bm + ar) * K + ac4 * 4;
        gAl = Alo + (long)z * sAz + (long)(bm + ar) * K + ac4 * 4;
    } else {
        gA0 = A + (long)z * sAz + (long)(bm + ar) * K + ac4 * 4;
    }

    float smx[4], siv[4];
    if (EXPA) {
        #pragma unroll
        for (int j = 0; j < 4; j++) {
            const int r = bm + ar + 32 * j;
            smx[j] = rmax[(long)z * M + r];
            siv[j] = rinv[(long)z * M + r];
        }
    }

    // ---- B loader geometry ----
    const float* gB0 = nullptr;
    int bkp = 0, bn4 = 0;
    float4 csc = make_float4(1.f, 1.f, 1.f, 1.f);
    if (TB) {
        gB0 = Bb + (long)(bn + ar) * K + ac4 * 4;
    } else {
        bkp = tid & 15;
        bn4 = tid >> 4;
        if (CONCAT)
            csc = *reinterpret_cast<const float4*>(colscale + (long)z * N + bn + bn4 * 4);
    }

    const int nch = K >> 5;

    float4 fa[4], fb[2];
    uint2 uah[4], ual[4];

    auto loadA = [&](int ch) {
        if (ASPLIT) {
            #pragma unroll
            for (int j = 0; j < 4; j++) {
                uah[j] = *reinterpret_cast<const uint2*>(gAh + ch * 32 + (long)(32 * j) * K);
                ual[j] = *reinterpret_cast<const uint2*>(gAl + ch * 32 + (long)(32 * j) * K);
            }
        } else {
            const float* p = gA0 + ch * 32;
            #pragma unroll
            for (int j = 0; j < 4; j++)
                fa[j] = *reinterpret_cast<const float4*>(p + (long)(32 * j) * K);
        }
    };
    auto loadB = [&](int ch) {
        if (TB) {
            const float* p = gB0 + ch * 32;
            #pragma unroll
            for (int j = 0; j < 2; j++)
                fb[j] = *reinterpret_cast<const float4*>(p + (long)(32 * j) * K);
        } else {
            const int kg = ch * 32 + 2 * bkp;
            const float* src;
            if (CONCAT && kg >= Ksplit)
                src = B2 + (long)z * sB2z + (long)(kg - Ksplit) * N + bn + bn4 * 4;
            else
                src = Bb + (long)kg * N + bn + bn4 * 4;
            fb[0] = *reinterpret_cast<const float4*>(src);
            fb[1] = *reinterpret_cast<const float4*>(src + N);
            if (CONCAT && kg >= Ksplit) {
                fb[0].x *= csc.x; fb[0].y *= csc.y; fb[0].z *= csc.z; fb[0].w *= csc.w;
                fb[1].x *= csc.x; fb[1].y *= csc.y; fb[1].z *= csc.z; fb[1].w *= csc.w;
            }
        }
    };
    auto stashA = [&](int buf) {
        char* a1 = smem + buf * BUFB + OFF_A1;
        char* a2 = smem + buf * BUFB + OFF_A2;
        #pragma unroll
        for (int j = 0; j < 4; j++) {
            const int off = (ar + 32 * j) * ROWB + ac4 * 8;
            if (ASPLIT) {
                *reinterpret_cast<uint2*>(a1 + off) = uah[j];
                *reinterpret_cast<uint2*>(a2 + off) = ual[j];
            } else {
                float4 f = fa[j];
                if (EXPA) {
                    const float m = smx[j], v = siv[j];
                    f.x = __expf(f.x - m) * v; f.y = __expf(f.y - m) * v;
                    f.z = __expf(f.z - m) * v; f.w = __expf(f.w - m) * v;
                }
                uint2 hi, lo;
                split4(f, hi, lo);
                *reinterpret_cast<uint2*>(a1 + off) = hi;
                *reinterpret_cast<uint2*>(a2 + off) = lo;
            }
        }
    };
    auto stashB = [&](int buf) {
        char* b1 = smem + buf * BUFB + OFF_B1;
        char* b2 = smem + buf * BUFB + OFF_B2;
        if (TB) {
            #pragma unroll
            for (int j = 0; j < 2; j++) {
                uint2 hi, lo;
                split4(fb[j], hi, lo);
                const int off = (ar + 32 * j) * ROWB + ac4 * 8;
                *reinterpret_cast<uint2*>(b1 + off) = hi;
                *reinterpret_cast<uint2*>(b2 + off) = lo;
            }
        } else {
            const float r0[4] = {fb[0].x, fb[0].y, fb[0].z, fb[0].w};
            const float r1[4] = {fb[1].x, fb[1].y, fb[1].z, fb[1].w};
            #pragma unroll
            for (int u = 0; u < 4; u++) {
                const uint32_t hi = pack_hi2(r0[u], r1[u]);
                const uint32_t lo = pack_hi2(r0[u] - fhi(r0[u]), r1[u] - fhi(r1[u]));
                const int off = (bn4 * 4 + u) * ROWB + bkp * 4;
                *reinterpret_cast<uint32_t*>(b1 + off) = hi;
                *reinterpret_cast<uint32_t*>(b2 + off) = lo;
            }
        }
    };

    loadA(0); loadB(0);
    stashA(0); stashB(0);
    __syncthreads();

    float d[2][4][4];
    #pragma unroll
    for (int i = 0; i < 2; i++)
        #pragma unroll
        for (int j = 0; j < 4; j++)
            #pragma unroll
            for (int q = 0; q < 4; q++) d[i][j][q] = 0.f;

    const int wm = (wid >> 1) * 32;
    const int wn = (wid & 1) * 32;
    const int lr = lane & 15;
    const int lc = lane >> 4;

    for (int ch = 0; ch < nch; ch++) {
        const bool hasNext = (ch + 1 < nch);
        if (hasNext) { loadA(ch + 1); loadB(ch + 1); }

        const uint32_t base = sb + (ch & 1) * BUFB;
        #pragma unroll
        for (int ks = 0; ks < 2; ks++) {
            const uint32_t koff = ks * 32 + lc * 16;
            uint32_t ah[2][4], al[2][4], bh[4][2], bl[4][2];
            #pragma unroll
            for (int mt = 0; mt < 2; mt++)
                ldmat4(ah[mt][0], ah[mt][1], ah[mt][2], ah[mt][3],
                       base + OFF_A1 + (wm + mt * 16 + lr) * ROWB + koff);
            #pragma unroll
            for (int bt = 0; bt < 2; bt++) {
                uint32_t r0, r1, r2, r3;
                ldmat4(r0, r1, r2, r3, base + OFF_B1 + (wn + bt * 16 + lr) * ROWB + koff);
                bh[2 * bt][0] = r0; bh[2 * bt][1] = r2;
                bh[2 * bt + 1][0] = r1; bh[2 * bt + 1][1] = r3;
            }
            #pragma unroll
            for (int mt = 0; mt < 2; mt++)
                #pragma unroll
                for (int nt = 0; nt < 4; nt++) mma16816(d[mt][nt], ah[mt], bh[nt]);
            #pragma unroll
            for (int bt = 0; bt < 2; bt++) {
                uint32_t r0, r1, r2, r3;
                ldmat4(r0, r1, r2, r3, base + OFF_B2 + (wn + bt * 16 + lr) * ROWB + koff);
                bl[2 * bt][0] = r0; bl[2 * bt][1] = r2;
                bl[2 * bt + 1][0] = r1; bl[2 * bt + 1][1] = r3;
            }
            #pragma unroll
            for (int mt = 0; mt < 2; mt++)
                #pragma unroll
                for (int nt = 0; nt < 4; nt++) mma16816(d[mt][nt], ah[mt], bl[nt]);
            #pragma unroll
            for (int mt = 0; mt < 2; mt++)
                ldmat4(al[mt][0], al[mt][1], al[mt][2], al[mt][3],
                       base + OFF_A2 + (wm + mt * 16 + lr) * ROWB + koff);
            #pragma unroll
            for (int mt = 0; mt < 2; mt++)
                #pragma unroll
                for (int nt = 0; nt < 4; nt++) mma16816(d[mt][nt], al[mt], bh[nt]);
        }
        if (hasNext) { stashA((ch + 1) & 1); stashB((ch + 1) & 1); }
        __syncthreads();
    }

    // epilogue
    const long coff = (long)(z % modB) * sCb + (long)(z / modB) * sCr;
    #pragma unroll
    for (int mt = 0; mt < 2; mt++) {
        const int r0 = bm + wm + mt * 16 + (lane >> 2);
        const float bi0 = HASBIAS ? bias[r0] : 0.f;
        const float bi8 = HASBIAS ? bias[r0 + 8] : 0.f;
        #pragma unroll
        for (int nt = 0; nt < 4; nt++) {
            const int c0 = bn + wn + nt * 8 + (lane & 3) * 2;
            float* p0 = C + coff + (long)r0 * ldc + c0;
            float* p1 = C + coff + (long)(r0 + 8) * ldc + c0;
            *reinterpret_cast<float2*>(p0) =
                make_float2(d[mt][nt][0] * alpha + bi0, d[mt][nt][1] * alpha + bi0);
            *reinterpret_cast<float2*>(p1) =
                make_float2(d[mt][nt][2] * alpha + bi8, d[mt][nt][3] * alpha + bi8);
        }
    }
}

// ---------------------------------------------------------------------------
// convert / reduction / elementwise kernels
// ---------------------------------------------------------------------------
__global__ void split_pass(const float4* __restrict__ in, uint2* __restrict__ hi,
                           uint2* __restrict__ lo, long n)
{
    const long i = (long)blockIdx.x * blockDim.x + threadIdx.x;
    if (i >= n) return;
    uint2 h, l;
    split4(in[i], h, l);
    hi[i] = h; lo[i] = l;
}

__device__ __forceinline__ float blockReduce(float v, bool ismax) {
    __shared__ float sh[32];
    __syncthreads();
    int lane = threadIdx.x & 31, wid = threadIdx.x >> 5;
    #pragma unroll
    for (int o = 16; o; o >>= 1) {
        float t = __shfl_xor_sync(0xffffffffu, v, o);
        v = ismax ? fmaxf(v, t) : (v + t);
    }
    if (lane == 0) sh[wid] = v;
    __syncthreads();
    int nw = (blockDim.x + 31) >> 5;
    if (wid == 0) {
        v = (lane < nw) ? sh[lane] : (ismax ? -1e30f : 0.f);
        #pragma unroll
        for (int o = 16; o; o >>= 1) {
            float t = __shfl_xor_sync(0xffffffffu, v, o);
            v = ismax ? fmaxf(v, t) : (v + t);
        }
        if (lane == 0) sh[0] = v;
    }
    __syncthreads();
    return sh[0];
}

__global__ void row_stats(const float* __restrict__ X, float* __restrict__ omax,
                          float* __restrict__ oinv, int len)
{
    const long row = blockIdx.x;
    const float* x = X + row * len;
    float m = -1e30f;
    for (int i = threadIdx.x; i < len; i += blockDim.x) m = fmaxf(m, x[i]);
    m = blockReduce(m, true);
    float s = 0.f;
    for (int i = threadIdx.x; i < len; i += blockDim.x) s += __expf(x[i] - m);
    s = blockReduce(s, false);
    if (threadIdx.x == 0) { omax[row] = m; oinv[row] = 1.f / s; }
}

__global__ void softmax_inplace(float* __restrict__ X, int len)
{
    const long row = blockIdx.x;
    float* x = X + row * len;
    float m = -1e30f;
    for (int i = threadIdx.x; i < len; i += blockDim.x) m = fmaxf(m, x[i]);
    m = blockReduce(m, true);
    float s = 0.f;
    for (int i = threadIdx.x; i < len; i += blockDim.x) s += __expf(x[i] - m);
    s = blockReduce(s, false);
    const float inv = 1.f / s;
    for (int i = threadIdx.x; i < len; i += blockDim.x) x[i] = __expf(x[i] - m) * inv;
}

// L2-normalize fp32 rows of 256, output split bf16 (A operand of stage 9)
__global__ void norm_split(const float* __restrict__ V, ushort_t* __restrict__ hi,
                           ushort_t* __restrict__ lo)
{
    const long row = blockIdx.x;
    const float x = V[row * 256 + threadIdx.x];
    const float s = blockReduce(x * x, false);
    const float y = x * rsqrtf(s);
    const float r = y - fhi(y);
    hi[row * 256 + threadIdx.x] = (ushort_t)(__float_as_uint(y) >> 16);
    lo[row * 256 + threadIdx.x] = (ushort_t)(__float_as_uint(r) >> 16);
}

__global__ void qcol_norm(const float* __restrict__ q, float* __restrict__ out)
{
    const int b = blockIdx.y;
    const int n = blockIdx.x * 256 + threadIdx.x;
    const float* p = q + (long)b * 256 * 4096 + n;
    float s = 0.f;
    #pragma unroll 8
    for (int c = 0; c < 256; c++) { float v = p[(long)c * 4096]; s += v * v; }
    out[b * 4096 + n] = 1.f / sqrtf(s);
}

__global__ void bn_stats(const float* __restrict__ y, float* __restrict__ mean,
                         float* __restrict__ istd)
{
    const int o = blockIdx.x;
    float s = 0.f, s2 = 0.f;
    for (int b = 0; b < 16; b++) {
        const float* p = y + ((long)b * 512 + o) * 4096;
        for (int i = threadIdx.x; i < 4096; i += 256) {
            float v = p[i]; s += v; s2 += v * v;
        }
    }
    s = blockReduce(s, false);
    s2 = blockReduce(s2, false);
    if (threadIdx.x == 0) {
        float mu = s * (1.f / 65536.f);
        mean[o] = mu;
        istd[o] = 1.f / sqrtf(s2 * (1.f / 65536.f) - mu * mu + 1e-5f);
    }
}

__global__ void bn_apply(float* __restrict__ y, const float* __restrict__ mean,
                         const float* __restrict__ istd, const float* __restrict__ g,
                         const float* __restrict__ b)
{
    const long i = (long)blockIdx.x * 256 + threadIdx.x;
    const int o = (int)((i >> 12) & 511);
    float v = (y[i] - mean[o]) * istd[o] * g[o] + b[o];
    y[i] = v > 0.f ? v : 0.f;
}

// ---------------------------------------------------------------------------
// Host orchestration
// ---------------------------------------------------------------------------
struct Scratch {
    float *kf, *kmax, *kinv, *qmax, *qinvs, *kpbs, *qpb, *sim, *value, *qcol, *cm, *mean, *istd;
    ushort_t *kwh, *kwl, *fwh, *fwl, *vhi, *vlo;
};

static Scratch fetch_scratch() {
    Scratch s;
    cudaGetSymbolAddress((void**)&s.kf,    g_kf);
    cudaGetSymbolAddress((void**)&s.kmax,  g_kmax);
    cudaGetSymbolAddress((void**)&s.kinv,  g_kinv);
    cudaGetSymbolAddress((void**)&s.qmax,  g_qmax);
    cudaGetSymbolAddress((void**)&s.qinvs, g_qinvs);
    cudaGetSymbolAddress((void**)&s.kpbs,  g_kpbs);
    cudaGetSymbolAddress((void**)&s.qpb,   g_qpb);
    cudaGetSymbolAddress((void**)&s.sim,   g_sim);
    cudaGetSymbolAddress((void**)&s.value, g_value);
    cudaGetSymbolAddress((void**)&s.qcol,  g_qcol);
    cudaGetSymbolAddress((void**)&s.cm,    g_cm);
    cudaGetSymbolAddress((void**)&s.mean,  g_mean);
    cudaGetSymbolAddress((void**)&s.istd,  g_istd);
    cudaGetSymbolAddress((void**)&s.kwh,   g_kwh);
    cudaGetSymbolAddress((void**)&s.kwl,   g_kwl);
    cudaGetSymbolAddress((void**)&s.fwh,   g_fwh);
    cudaGetSymbolAddress((void**)&s.fwl,   g_fwl);
    cudaGetSymbolAddress((void**)&s.vhi,   g_vhi);
    cudaGetSymbolAddress((void**)&s.vlo,   g_vlo);
    cudaFuncSetAttribute(mgemm<false, false, true,  false, true >, cudaFuncAttributeMaxDynamicSharedMemorySize, TG_SMEM);
    cudaFuncSetAttribute(mgemm<true,  true,  false, false, false>, cudaFuncAttributeMaxDynamicSharedMemorySize, TG_SMEM);
    cudaFuncSetAttribute(mgemm<true,  false, false, false, false>, cudaFuncAttributeMaxDynamicSharedMemorySize, TG_SMEM);
    cudaFuncSetAttribute(mgemm<false, false, false, false, false>, cudaFuncAttributeMaxDynamicSharedMemorySize, TG_SMEM);
    cudaFuncSetAttribute(mgemm<false, false, false, false, true >, cudaFuncAttributeMaxDynamicSharedMemorySize, TG_SMEM);
    cudaFuncSetAttribute(mgemm<false, false, true,  true,  true >, cudaFuncAttributeMaxDynamicSharedMemorySize, TG_SMEM);
    return s;
}

extern "C" void kernel_launch(void* const* d_in, const int* in_sizes, int n_in,
                              void* d_out, int out_size)
{
    (void)in_sizes; (void)n_in; (void)out_size;
    static Scratch s = fetch_scratch();

    const float* x     = (const float*)d_in[0];
    const float* query = (const float*)d_in[1];
    const float* refs  = (const float*)d_in[2];
    const float* K_w   = (const float*)d_in[3];
    const float* K_b   = (const float*)d_in[4];
    // d_in[5], d_in[6] = V_w, V_b : dead code in the reference.
    const float* f_w   = (const float*)d_in[7];
    const float* f_b   = (const float*)d_in[8];
    const float* bn_g  = (const float*)d_in[9];
    const float* bn_b  = (const float*)d_in[10];
    float* out = (float*)d_out;

    // 0) pre-split WEIGHTS only (tiny)
    split_pass<<<128, 256>>>((const float4*)K_w, (uint2*)s.kwh, (uint2*)s.kwl, 32768L);
    split_pass<<<384, 256>>>((const float4*)f_w, (uint2*)s.fwh, (uint2*)s.fwl, 98304L);

    // 1) kf[z] = K_w @ refs[z] + K_b   (NN, bias, A pre-split)
    mgemm<false, false, true, false, true><<<dim3(64, 2, 48), 256, TG_SMEM>>>(
        nullptr, s.kwh, s.kwl, refs, s.kf, 256, 4096, 512, 0, 512L * 4096,
        48, 256L * 4096, 0, 4096,
        nullptr, nullptr, K_b, nullptr, 0, 0, nullptr, 1.f);

    // 2) softmax row stats
    row_stats<<<48 * 256, 256>>>(s.kf, s.kmax, s.kinv, 4096);
    row_stats<<<16 * 256, 256>>>(query, s.qmax, s.qinvs, 4096);

    // 3) k_pb[z] = softmax(kf[z]) @ kf[z]^T  (TB, EXPA)
    mgemm<true, true, false, false, false><<<dim3(4, 2, 48), 256, TG_SMEM>>>(
        s.kf, nullptr, nullptr, s.kf, s.kpbs, 256, 256, 4096, 256L * 4096, 256L * 4096,
        16, 768L * 256, 256L * 256, 256,
        s.kmax, s.kinv, nullptr, nullptr, 0, 0, nullptr, 1.f);

    // 4) q_pb[b] = softmax(query[b]) @ query[b]^T
    mgemm<true, true, false, false, false><<<dim3(4, 2, 16), 256, TG_SMEM>>>(
        query, nullptr, nullptr, query, s.qpb, 256, 256, 4096, 256L * 4096, 256L * 4096,
        16, 256L * 256, 0, 256,
        s.qmax, s.qinvs, nullptr, nullptr, 0, 0, nullptr, 1.f);

    // 5) sim = (q_pb @ k_pbs^T) / sqrt(256)
    mgemm<true, false, false, false, false><<<dim3(12, 2, 16), 256, TG_SMEM>>>(
        s.qpb, nullptr, nullptr, s.kpbs, s.sim, 256, 768, 256, 256L * 256, 768L * 256,
        16, 256L * 768, 0, 768,
        nullptr, nullptr, nullptr, nullptr, 0, 0, nullptr, 0.0625f);

    // 6) softmax over k
    softmax_inplace<<<16 * 256, 256>>>(s.sim, 768);

    // 7) value = sim @ k_pbs (NN)
    mgemm<false, false, false, false, false><<<dim3(4, 2, 16), 256, TG_SMEM>>>(
        s.sim, nullptr, nullptr, s.kpbs, s.value, 256, 256, 768, 256L * 768, 768L * 256,
        16, 256L * 256, 0, 256,
        nullptr, nullptr, nullptr, nullptr, 0, 0, nullptr, 1.f);

    // 8) normalize prototypes -> pre-split A for stage 9; query column norms
    norm_split<<<16 * 256, 256>>>(s.value, s.vhi, s.vlo);
    qcol_norm<<<dim3(16, 16), 256>>>(query, s.qcol);

    // 9) cm_raw = proto_n @ query  (NN, A pre-split; qcol folded into stage 10)
    mgemm<false, false, false, false, true><<<dim3(64, 2, 16), 256, TG_SMEM>>>(
        nullptr, s.vhi, s.vlo, query, s.cm, 256, 4096, 256, 256L * 256, 256L * 4096,
        16, 256L * 4096, 0, 4096,
        nullptr, nullptr, nullptr, nullptr, 0, 0, nullptr, 1.f);

    // 10) y = f_w @ concat(x, cm * qcol) + f_b  (NN, A pre-split, CONCAT)
    mgemm<false, false, true, true, true><<<dim3(64, 4, 16), 256, TG_SMEM>>>(
        nullptr, s.fwh, s.fwl, x, out, 512, 4096, 768, 0, 512L * 4096,
        16, 512L * 4096, 0, 4096,
        nullptr, nullptr, f_b, s.cm, 256L * 4096, 512, s.qcol, 1.f);

    // 11) BatchNorm (batch stats) + ReLU
    bn_stats<<<512, 256>>>(out, s.mean, s.istd);
    bn_apply<<<131072, 256>>>(out, s.mean, s.istd, bn_g, bn_b);
}

// round 11
// speedup vs baseline: 1.3629x; 1.1489x over previous
#include <cuda_runtime.h>
#include <cuda_bf16.h>
#include <cstdint>
#include <stdint.h>
#include <math.h>

// ---------------------------------------------------------------------------
// Scratch (static __device__ arrays; no allocations anywhere)
// ---------------------------------------------------------------------------
__device__ float g_kf[48u * 256u * 4096u];   // 201 MB
__device__ float g_kmax[48 * 256];
__device__ float g_kinv[48 * 256];
__device__ float g_qmax[16 * 256];
__device__ float g_qinvs[16 * 256];
__device__ float g_kpbs[16 * 768 * 256];
__device__ float g_qpb[16 * 256 * 256];
__device__ float g_sim[16 * 256 * 768];
__device__ float g_value[16 * 256 * 256];
__device__ float g_qcol[16 * 4096];
__device__ float g_cm[16u * 256u * 4096u];   // 67 MB
__device__ float g_mean[512];
__device__ float g_istd[512];

// ---------------------------------------------------------------------------
// mma.sync helpers (plain sm_80+ PTX — valid under compute_103)
// ---------------------------------------------------------------------------
__device__ __forceinline__ uint32_t smem_u32(const void* p) {
    uint32_t a;
    asm("{ .reg .u64 t; cvta.to.shared.u64 t, %1; cvt.u32.u64 %0, t; }" : "=r"(a) : "l"(p));
    return a;
}
__device__ __forceinline__ void ldmat4(uint32_t& r0, uint32_t& r1, uint32_t& r2, uint32_t& r3,
                                       uint32_t addr) {
    asm volatile("ldmatrix.sync.aligned.m8n8.x4.shared.b16 {%0,%1,%2,%3}, [%4];"
                 : "=r"(r0), "=r"(r1), "=r"(r2), "=r"(r3) : "r"(addr));
}
__device__ __forceinline__ void mma16816(float* d, const uint32_t* a, const uint32_t* b) {
    asm volatile(
        "mma.sync.aligned.m16n8k16.row.col.f32.bf16.bf16.f32 "
        "{%0,%1,%2,%3}, {%4,%5,%6,%7}, {%8,%9}, {%0,%1,%2,%3};"
        : "+f"(d[0]), "+f"(d[1]), "+f"(d[2]), "+f"(d[3])
        : "r"(a[0]), "r"(a[1]), "r"(a[2]), "r"(a[3]), "r"(b[0]), "r"(b[1]));
}

// Truncating fp32 -> bf16 split helpers (PRMT-based)
__device__ __forceinline__ uint32_t pack_hi2(float a, float b) {
    uint32_t r;
    asm("prmt.b32 %0, %1, %2, 0x7632;" : "=r"(r)
        : "r"(__float_as_uint(a)), "r"(__float_as_uint(b)));
    return r;
}
__device__ __forceinline__ float fhi(float f) {
    return __uint_as_float(__float_as_uint(f) & 0xFFFF0000u);
}
__device__ __forceinline__ void split4(float4 f, uint2& hi, uint2& lo) {
    hi = make_uint2(pack_hi2(f.x, f.y), pack_hi2(f.z, f.w));
    lo = make_uint2(pack_hi2(f.x - fhi(f.x), f.y - fhi(f.y)),
                    pack_hi2(f.z - fhi(f.z), f.w - fhi(f.w)));
}

// smem geometry (per buffer): A parts 128 rows, B parts 64 rows, 80 B rows.
static constexpr int ROWB    = 80;             // 32 bf16 + 8 pad
static constexpr int A_PART  = 128 * ROWB;
static constexpr int B_PART  = 64 * ROWB;
static constexpr int OFF_A1  = 0;
static constexpr int OFF_A2  = A_PART;
static constexpr int OFF_B1  = 2 * A_PART;
static constexpr int OFF_B2  = 2 * A_PART + B_PART;
static constexpr int BUFB    = 2 * A_PART + 2 * B_PART;  // 30720
static constexpr int TG_SMEM = 2 * BUFB;                 // 61440

// ---------------------------------------------------------------------------
// mma.sync bf16-split2 GEMM (R7-proven): C = alpha*(A' @ B') (+bias[r])
//   A: row-major [M,K]; EXPA: fused exp(a - rmax)*rinv per row
//   TB:  B row-major [N,K] (C = A @ B^T);  !TB: B row-major [K,N]
//   CONCAT (!TB): k >= Ksplit reads B2 scaled by colscale[z*N+n]
// CTA 128x64, K chunks of 32; 8 warps 4(m)x2(n); 2 CTAs/SM.
// ---------------------------------------------------------------------------
template<bool TB, bool EXPA, bool HASBIAS, bool CONCAT>
__global__ void __launch_bounds__(256, 2) mgemm(
    const float* __restrict__ A, const float* __restrict__ B, float* __restrict__ C,
    int M, int N, int K, long sAz, long sBz,
    int modB, long sCb, long sCr, int ldc,
    const float* __restrict__ rmax, const float* __restrict__ rinv,
    const float* __restrict__ bias,
    const float* __restrict__ B2, long sB2z, int Ksplit,
    const float* __restrict__ colscale, float alpha)
{
    extern __shared__ char smem[];
    const uint32_t sb = smem_u32(smem);
    const int tid = threadIdx.x;
    const int wid = tid >> 5;
    const int lane = tid & 31;
    const int z = blockIdx.z;
    const int bm = blockIdx.y * 128;
    const int bn = blockIdx.x * 64;
    const float* Ab = A + (long)z * sAz;
    const float* Bb = B + (long)z * sBz;

    const int ar = tid >> 3;
    const int ac4 = tid & 7;
    const float* gA0 = Ab + (long)(bm + ar) * K + ac4 * 4;

    float smx[4], siv[4];
    if (EXPA) {
        #pragma unroll
        for (int j = 0; j < 4; j++) {
            const int r = bm + ar + 32 * j;
            smx[j] = rmax[(long)z * M + r];
            siv[j] = rinv[(long)z * M + r];
        }
    }

    const float* gB0 = nullptr;
    int bkp = 0, bn4 = 0;
    float4 csc = make_float4(1.f, 1.f, 1.f, 1.f);
    if (TB) {
        gB0 = Bb + (long)(bn + ar) * K + ac4 * 4;
    } else {
        bkp = tid & 15;
        bn4 = tid >> 4;
        if (CONCAT)
            csc = *reinterpret_cast<const float4*>(colscale + (long)z * N + bn + bn4 * 4);
    }

    const int nch = K >> 5;

    float4 fa[4], fb[2];

    auto loadA = [&](int ch) {
        const float* p = gA0 + ch * 32;
        #pragma unroll
        for (int j = 0; j < 4; j++)
            fa[j] = *reinterpret_cast<const float4*>(p + (long)(32 * j) * K);
    };
    auto loadB = [&](int ch) {
        if (TB) {
            const float* p = gB0 + ch * 32;
            #pragma unroll
            for (int j = 0; j < 2; j++)
                fb[j] = *reinterpret_cast<const float4*>(p + (long)(32 * j) * K);
        } else {
            const int kg = ch * 32 + 2 * bkp;
            const float* src;
            if (CONCAT && kg >= Ksplit)
                src = B2 + (long)z * sB2z + (long)(kg - Ksplit) * N + bn + bn4 * 4;
            else
                src = Bb + (long)kg * N + bn + bn4 * 4;
            fb[0] = *reinterpret_cast<const float4*>(src);
            fb[1] = *reinterpret_cast<const float4*>(src + N);
            if (CONCAT && kg >= Ksplit) {
                fb[0].x *= csc.x; fb[0].y *= csc.y; fb[0].z *= csc.z; fb[0].w *= csc.w;
                fb[1].x *= csc.x; fb[1].y *= csc.y; fb[1].z *= csc.z; fb[1].w *= csc.w;
            }
        }
    };
    auto stashA = [&](int buf) {
        char* a1 = smem + buf * BUFB + OFF_A1;
        char* a2 = smem + buf * BUFB + OFF_A2;
        #pragma unroll
        for (int j = 0; j < 4; j++) {
            float4 f = fa[j];
            if (EXPA) {
                const float m = smx[j], v = siv[j];
                f.x = __expf(f.x - m) * v; f.y = __expf(f.y - m) * v;
                f.z = __expf(f.z - m) * v; f.w = __expf(f.w - m) * v;
            }
            uint2 hi, lo;
            split4(f, hi, lo);
            const int off = (ar + 32 * j) * ROWB + ac4 * 8;
            *reinterpret_cast<uint2*>(a1 + off) = hi;
            *reinterpret_cast<uint2*>(a2 + off) = lo;
        }
    };
    auto stashB = [&](int buf) {
        char* b1 = smem + buf * BUFB + OFF_B1;
        char* b2 = smem + buf * BUFB + OFF_B2;
        if (TB) {
            #pragma unroll
            for (int j = 0; j < 2; j++) {
                uint2 hi, lo;
                split4(fb[j], hi, lo);
                const int off = (ar + 32 * j) * ROWB + ac4 * 8;
                *reinterpret_cast<uint2*>(b1 + off) = hi;
                *reinterpret_cast<uint2*>(b2 + off) = lo;
            }
        } else {
            const float r0[4] = {fb[0].x, fb[0].y, fb[0].z, fb[0].w};
            const float r1[4] = {fb[1].x, fb[1].y, fb[1].z, fb[1].w};
            #pragma unroll
            for (int u = 0; u < 4; u++) {
                const uint32_t hi = pack_hi2(r0[u], r1[u]);
                const uint32_t lo = pack_hi2(r0[u] - fhi(r0[u]), r1[u] - fhi(r1[u]));
                const int off = (bn4 * 4 + u) * ROWB + bkp * 4;
                *reinterpret_cast<uint32_t*>(b1 + off) = hi;
                *reinterpret_cast<uint32_t*>(b2 + off) = lo;
            }
        }
    };

    loadA(0); loadB(0);
    stashA(0); stashB(0);
    __syncthreads();

    float d[2][4][4];
    #pragma unroll
    for (int i = 0; i < 2; i++)
        #pragma unroll
        for (int j = 0; j < 4; j++)
            #pragma unroll
            for (int q = 0; q < 4; q++) d[i][j][q] = 0.f;

    const int wm = (wid >> 1) * 32;
    const int wn = (wid & 1) * 32;
    const int lr = lane & 15;
    const int lc = lane >> 4;

    for (int ch = 0; ch < nch; ch++) {
        const bool hasNext = (ch + 1 < nch);
        if (hasNext) { loadA(ch + 1); loadB(ch + 1); }

        const uint32_t base = sb + (ch & 1) * BUFB;
        #pragma unroll
        for (int ks = 0; ks < 2; ks++) {
            const uint32_t koff = ks * 32 + lc * 16;
            uint32_t ah[2][4], al[2][4], bh[4][2], bl[4][2];
            #pragma unroll
            for (int mt = 0; mt < 2; mt++)
                ldmat4(ah[mt][0], ah[mt][1], ah[mt][2], ah[mt][3],
                       base + OFF_A1 + (wm + mt * 16 + lr) * ROWB + koff);
            #pragma unroll
            for (int bt = 0; bt < 2; bt++) {
                uint32_t r0, r1, r2, r3;
                ldmat4(r0, r1, r2, r3, base + OFF_B1 + (wn + bt * 16 + lr) * ROWB + koff);
                bh[2 * bt][0] = r0; bh[2 * bt][1] = r2;
                bh[2 * bt + 1][0] = r1; bh[2 * bt + 1][1] = r3;
            }
            #pragma unroll
            for (int mt = 0; mt < 2; mt++)
                #pragma unroll
                for (int nt = 0; nt < 4; nt++) mma16816(d[mt][nt], ah[mt], bh[nt]);
            #pragma unroll
            for (int bt = 0; bt < 2; bt++) {
                uint32_t r0, r1, r2, r3;
                ldmat4(r0, r1, r2, r3, base + OFF_B2 + (wn + bt * 16 + lr) * ROWB + koff);
                bl[2 * bt][0] = r0; bl[2 * bt][1] = r2;
                bl[2 * bt + 1][0] = r1; bl[2 * bt + 1][1] = r3;
            }
            #pragma unroll
            for (int mt = 0; mt < 2; mt++)
                #pragma unroll
                for (int nt = 0; nt < 4; nt++) mma16816(d[mt][nt], ah[mt], bl[nt]);
            #pragma unroll
            for (int mt = 0; mt < 2; mt++)
                ldmat4(al[mt][0], al[mt][1], al[mt][2], al[mt][3],
                       base + OFF_A2 + (wm + mt * 16 + lr) * ROWB + koff);
            #pragma unroll
            for (int mt = 0; mt < 2; mt++)
                #pragma unroll
                for (int nt = 0; nt < 4; nt++) mma16816(d[mt][nt], al[mt], bh[nt]);
        }
        if (hasNext) { stashA((ch + 1) & 1); stashB((ch + 1) & 1); }
        __syncthreads();
    }

    const long coff = (long)(z % modB) * sCb + (long)(z / modB) * sCr;
    #pragma unroll
    for (int mt = 0; mt < 2; mt++) {
        const int r0 = bm + wm + mt * 16 + (lane >> 2);
        const float bi0 = HASBIAS ? bias[r0] : 0.f;
        const float bi8 = HASBIAS ? bias[r0 + 8] : 0.f;
        #pragma unroll
        for (int nt = 0; nt < 4; nt++) {
            const int c0 = bn + wn + nt * 8 + (lane & 3) * 2;
            float* p0 = C + coff + (long)r0 * ldc + c0;
            float* p1 = C + coff + (long)(r0 + 8) * ldc + c0;
            *reinterpret_cast<float2*>(p0) =
                make_float2(d[mt][nt][0] * alpha + bi0, d[mt][nt][1] * alpha + bi0);
            *reinterpret_cast<float2*>(p1) =
                make_float2(d[mt][nt][2] * alpha + bi8, d[mt][nt][3] * alpha + bi8);
        }
    }
}

// ---------------------------------------------------------------------------
// Reductions / elementwise helpers
// ---------------------------------------------------------------------------
__device__ __forceinline__ float blockReduce(float v, bool ismax) {
    __shared__ float sh[32];
    __syncthreads();
    int lane = threadIdx.x & 31, wid = threadIdx.x >> 5;
    #pragma unroll
    for (int o = 16; o; o >>= 1) {
        float t = __shfl_xor_sync(0xffffffffu, v, o);
        v = ismax ? fmaxf(v, t) : (v + t);
    }
    if (lane == 0) sh[wid] = v;
    __syncthreads();
    int nw = (blockDim.x + 31) >> 5;
    if (wid == 0) {
        v = (lane < nw) ? sh[lane] : (ismax ? -1e30f : 0.f);
        #pragma unroll
        for (int o = 16; o; o >>= 1) {
            float t = __shfl_xor_sync(0xffffffffu, v, o);
            v = ismax ? fmaxf(v, t) : (v + t);
        }
        if (lane == 0) sh[0] = v;
    }
    __syncthreads();
    return sh[0];
}

// Row stats for rows of exactly 4096 floats: single DRAM pass, row cached in regs
__global__ void row_stats4k(const float* __restrict__ X, float* __restrict__ omax,
                            float* __restrict__ oinv)
{
    const long row = blockIdx.x;
    const float4* x = reinterpret_cast<const float4*>(X + row * 4096);
    float4 v[4];
    float m = -1e30f;
    #pragma unroll
    for (int j = 0; j < 4; j++) {
        v[j] = x[threadIdx.x + 256 * j];
        m = fmaxf(m, fmaxf(fmaxf(v[j].x, v[j].y), fmaxf(v[j].z, v[j].w)));
    }
    m = blockReduce(m, true);
    float s = 0.f;
    #pragma unroll
    for (int j = 0; j < 4; j++)
        s += __expf(v[j].x - m) + __expf(v[j].y - m) + __expf(v[j].z - m) + __expf(v[j].w - m);
    s = blockReduce(s, false);
    if (threadIdx.x == 0) { omax[row] = m; oinv[row] = 1.f / s; }
}

__global__ void softmax_inplace(float* __restrict__ X, int len)
{
    const long row = blockIdx.x;
    float* x = X + row * len;
    float m = -1e30f;
    for (int i = threadIdx.x; i < len; i += blockDim.x) m = fmaxf(m, x[i]);
    m = blockReduce(m, true);
    float s = 0.f;
    for (int i = threadIdx.x; i < len; i += blockDim.x) s += __expf(x[i] - m);
    s = blockReduce(s, false);
    const float inv = 1.f / s;
    for (int i = threadIdx.x; i < len; i += blockDim.x) x[i] = __expf(x[i] - m) * inv;
}

__global__ void norm_rows256(float* __restrict__ V)
{
    const long row = blockIdx.x;
    float* v = V + row * 256;
    const float x = v[threadIdx.x];
    const float s = blockReduce(x * x, false);
    v[threadIdx.x] = x * rsqrtf(s);
}

__global__ void qcol_norm(const float* __restrict__ q, float* __restrict__ out)
{
    const int b = blockIdx.y;
    const int n = blockIdx.x * 256 + threadIdx.x;
    const float* p = q + (long)b * 256 * 4096 + n;
    float s = 0.f;
    #pragma unroll 8
    for (int c = 0; c < 256; c++) { float v = p[(long)c * 4096]; s += v * v; }
    out[b * 4096 + n] = rsqrtf(s);
}

__global__ void bn_stats(const float* __restrict__ y, float* __restrict__ mean,
                         float* __restrict__ istd)
{
    const int o = blockIdx.x;
    float s = 0.f, s2 = 0.f;
    for (int b = 0; b < 16; b++) {
        const float* p = y + ((long)b * 512 + o) * 4096;
        for (int i = threadIdx.x; i < 4096; i += 256) {
            float v = p[i]; s += v; s2 += v * v;
        }
    }
    s = blockReduce(s, false);
    s2 = blockReduce(s2, false);
    if (threadIdx.x == 0) {
        float mu = s * (1.f / 65536.f);
        mean[o] = mu;
        istd[o] = 1.f / sqrtf(s2 * (1.f / 65536.f) - mu * mu + 1e-5f);
    }
}

__global__ void bn_apply(float* __restrict__ y, const float* __restrict__ mean,
                         const float* __restrict__ istd, const float* __restrict__ g,
                         const float* __restrict__ b)
{
    const long i = (long)blockIdx.x * 256 + threadIdx.x;
    const int o = (int)((i >> 12) & 511);
    float v = (y[i] - mean[o]) * istd[o] * g[o] + b[o];
    y[i] = v > 0.f ? v : 0.f;
}

// ---------------------------------------------------------------------------
// Host orchestration
// ---------------------------------------------------------------------------
struct Scratch {
    float *kf, *kmax, *kinv, *qmax, *qinvs, *kpbs, *qpb, *sim, *value, *qcol, *cm, *mean, *istd;
    cudaStream_t s2;
    cudaEvent_t evFork, evJoin;
};

static Scratch fetch_scratch() {
    Scratch s;
    cudaGetSymbolAddress((void**)&s.kf,    g_kf);
    cudaGetSymbolAddress((void**)&s.kmax,  g_kmax);
    cudaGetSymbolAddress((void**)&s.kinv,  g_kinv);
    cudaGetSymbolAddress((void**)&s.qmax,  g_qmax);
    cudaGetSymbolAddress((void**)&s.qinvs, g_qinvs);
    cudaGetSymbolAddress((void**)&s.kpbs,  g_kpbs);
    cudaGetSymbolAddress((void**)&s.qpb,   g_qpb);
    cudaGetSymbolAddress((void**)&s.sim,   g_sim);
    cudaGetSymbolAddress((void**)&s.value, g_value);
    cudaGetSymbolAddress((void**)&s.qcol,  g_qcol);
    cudaGetSymbolAddress((void**)&s.cm,    g_cm);
    cudaGetSymbolAddress((void**)&s.mean,  g_mean);
    cudaGetSymbolAddress((void**)&s.istd,  g_istd);
    cudaStreamCreateWithFlags(&s.s2, cudaStreamNonBlocking);
    cudaEventCreateWithFlags(&s.evFork, cudaEventDisableTiming);
    cudaEventCreateWithFlags(&s.evJoin, cudaEventDisableTiming);
    cudaFuncSetAttribute(mgemm<false, false, true,  false>, cudaFuncAttributeMaxDynamicSharedMemorySize, TG_SMEM);
    cudaFuncSetAttribute(mgemm<true,  true,  false, false>, cudaFuncAttributeMaxDynamicSharedMemorySize, TG_SMEM);
    cudaFuncSetAttribute(mgemm<true,  false, false, false>, cudaFuncAttributeMaxDynamicSharedMemorySize, TG_SMEM);
    cudaFuncSetAttribute(mgemm<false, false, false, false>, cudaFuncAttributeMaxDynamicSharedMemorySize, TG_SMEM);
    cudaFuncSetAttribute(mgemm<false, false, true,  true >, cudaFuncAttributeMaxDynamicSharedMemorySize, TG_SMEM);
    return s;
}

extern "C" void kernel_launch(void* const* d_in, const int* in_sizes, int n_in,
                              void* d_out, int out_size)
{
    (void)in_sizes; (void)n_in; (void)out_size;
    static Scratch s = fetch_scratch();  // first call is the non-captured correctness run

    const float* x     = (const float*)d_in[0];
    const float* query = (const float*)d_in[1];
    const float* refs  = (const float*)d_in[2];
    const float* K_w   = (const float*)d_in[3];
    const float* K_b   = (const float*)d_in[4];
    // d_in[5], d_in[6] = V_w, V_b : dead code in the reference.
    const float* f_w   = (const float*)d_in[7];
    const float* f_b   = (const float*)d_in[8];
    const float* bn_g  = (const float*)d_in[9];
    const float* bn_b  = (const float*)d_in[10];
    float* out = (float*)d_out;

    // ---- fork: independent query branch on s2 ----
    cudaEventRecord(s.evFork, 0);
    cudaStreamWaitEvent(s.s2, s.evFork, 0);

    // s2 branch: query stats, q_pb GEMM (stage 4), qcol norms
    row_stats4k<<<16 * 256, 256, 0, s.s2>>>(query, s.qmax, s.qinvs);
    mgemm<true, true, false, false><<<dim3(4, 2, 16), 256, TG_SMEM, s.s2>>>(
        query, query, s.qpb, 256, 256, 4096, 256L * 4096, 256L * 4096,
        16, 256L * 256, 0, 256,
        s.qmax, s.qinvs, nullptr, nullptr, 0, 0, nullptr, 1.f);
    qcol_norm<<<dim3(16, 16), 256, 0, s.s2>>>(query, s.qcol);

    // main branch: kf chain
    // 1) kf[z] = K_w @ refs[z] + K_b   (NN, bias)
    mgemm<false, false, true, false><<<dim3(64, 2, 48), 256, TG_SMEM>>>(
        K_w, refs, s.kf, 256, 4096, 512, 0, 512L * 4096,
        48, 256L * 4096, 0, 4096,
        nullptr, nullptr, K_b, nullptr, 0, 0, nullptr, 1.f);

    // 2) kf softmax row stats (single-pass, register-cached)
    row_stats4k<<<48 * 256, 256>>>(s.kf, s.kmax, s.kinv);

    // 3) k_pb[z] = softmax(kf[z]) @ kf[z]^T  (TB, EXPA)
    mgemm<true, true, false, false><<<dim3(4, 2, 48), 256, TG_SMEM>>>(
        s.kf, s.kf, s.kpbs, 256, 256, 4096, 256L * 4096, 256L * 4096,
        16, 768L * 256, 256L * 256, 256,
        s.kmax, s.kinv, nullptr, nullptr, 0, 0, nullptr, 1.f);

    // ---- join s2 back into main before stage 5 ----
    cudaEventRecord(s.evJoin, s.s2);
    cudaStreamWaitEvent(0, s.evJoin, 0);

    // 5) sim = (q_pb @ k_pbs^T) / sqrt(256)
    mgemm<true, false, false, false><<<dim3(12, 2, 16), 256, TG_SMEM>>>(
        s.qpb, s.kpbs, s.sim, 256, 768, 256, 256L * 256, 768L * 256,
        16, 256L * 768, 0, 768,
        nullptr, nullptr, nullptr, nullptr, 0, 0, nullptr, 0.0625f);

    // 6) softmax over k
    softmax_inplace<<<16 * 256, 256>>>(s.sim, 768);

    // 7) value = sim @ k_pbs (NN)
    mgemm<false, false, false, false><<<dim3(4, 2, 16), 256, TG_SMEM>>>(
        s.sim, s.kpbs, s.value, 256, 256, 768, 256L * 768, 768L * 256,
        16, 256L * 256, 0, 256,
        nullptr, nullptr, nullptr, nullptr, 0, 0, nullptr, 1.f);

    // 8) normalize prototypes
    norm_rows256<<<16 * 256, 256>>>(s.value);

    // 9) cm_raw = proto_n @ query (qcol folded into stage 10 loader)
    mgemm<false, false, false, false><<<dim3(64, 2, 16), 256, TG_SMEM>>>(
        s.value, query, s.cm, 256, 4096, 256, 256L * 256, 256L * 4096,
        16, 256L * 4096, 0, 4096,
        nullptr, nullptr, nullptr, nullptr, 0, 0, nullptr, 1.f);

    // 10) y = f_w @ concat(x, cm * qcol) + f_b
    mgemm<false, false, true, true><<<dim3(64, 4, 16), 256, TG_SMEM>>>(
        f_w, x, out, 512, 4096, 768, 0, 512L * 4096,
        16, 512L * 4096, 0, 4096,
        nullptr, nullptr, f_b, s.cm, 256L * 4096, 512, s.qcol, 1.f);

    // 11) BatchNorm (batch stats) + ReLU
    bn_stats<<<512, 256>>>(out, s.mean, s.istd);
    bn_apply<<<131072, 256>>>(out, s.mean, s.istd, bn_g, bn_b);
}

// round 12
// speedup vs baseline: 1.3721x; 1.0068x over previous
#include <cuda_runtime.h>
#include <cuda_bf16.h>
#include <cstdint>
#include <stdint.h>
#include <math.h>

// ---------------------------------------------------------------------------
// Scratch (static __device__ arrays; no allocations anywhere)
// ---------------------------------------------------------------------------
__device__ float g_kf[48u * 256u * 4096u];   // 201 MB
__device__ float g_kmax[48 * 256];
__device__ float g_kinv[48 * 256];
__device__ float g_qmax[16 * 256];
__device__ float g_qinvs[16 * 256];
__device__ float g_kpbs[16 * 768 * 256];
__device__ float g_qpb[16 * 256 * 256];
__device__ float g_sim[16 * 256 * 768];
__device__ float g_value[16 * 256 * 256];
__device__ float g_qcol[16 * 4096];
__device__ float g_cm[16u * 256u * 4096u];   // 67 MB
__device__ float g_mean[512];
__device__ float g_istd[512];

// ---------------------------------------------------------------------------
// mma.sync helpers (plain sm_80+ PTX — valid under compute_103)
// ---------------------------------------------------------------------------
__device__ __forceinline__ uint32_t smem_u32(const void* p) {
    uint32_t a;
    asm("{ .reg .u64 t; cvta.to.shared.u64 t, %1; cvt.u32.u64 %0, t; }" : "=r"(a) : "l"(p));
    return a;
}
__device__ __forceinline__ void ldmat4(uint32_t& r0, uint32_t& r1, uint32_t& r2, uint32_t& r3,
                                       uint32_t addr) {
    asm volatile("ldmatrix.sync.aligned.m8n8.x4.shared.b16 {%0,%1,%2,%3}, [%4];"
                 : "=r"(r0), "=r"(r1), "=r"(r2), "=r"(r3) : "r"(addr));
}
__device__ __forceinline__ void mma16816(float* d, const uint32_t* a, const uint32_t* b) {
    asm volatile(
        "mma.sync.aligned.m16n8k16.row.col.f32.bf16.bf16.f32 "
        "{%0,%1,%2,%3}, {%4,%5,%6,%7}, {%8,%9}, {%0,%1,%2,%3};"
        : "+f"(d[0]), "+f"(d[1]), "+f"(d[2]), "+f"(d[3])
        : "r"(a[0]), "r"(a[1]), "r"(a[2]), "r"(a[3]), "r"(b[0]), "r"(b[1]));
}

// Truncating fp32 -> bf16 split helpers (PRMT-based)
__device__ __forceinline__ uint32_t pack_hi2(float a, float b) {
    uint32_t r;
    asm("prmt.b32 %0, %1, %2, 0x7632;" : "=r"(r)
        : "r"(__float_as_uint(a)), "r"(__float_as_uint(b)));
    return r;
}
__device__ __forceinline__ float fhi(float f) {
    return __uint_as_float(__float_as_uint(f) & 0xFFFF0000u);
}
__device__ __forceinline__ void split4(float4 f, uint2& hi, uint2& lo) {
    hi = make_uint2(pack_hi2(f.x, f.y), pack_hi2(f.z, f.w));
    lo = make_uint2(pack_hi2(f.x - fhi(f.x), f.y - fhi(f.y)),
                    pack_hi2(f.z - fhi(f.z), f.w - fhi(f.w)));
}

// smem geometry (per buffer): A parts 128 rows, B parts 64 rows, 80 B rows.
static constexpr int ROWB    = 80;             // 32 bf16 + 8 pad
static constexpr int A_PART  = 128 * ROWB;
static constexpr int B_PART  = 64 * ROWB;
static constexpr int OFF_A1  = 0;
static constexpr int OFF_A2  = A_PART;
static constexpr int OFF_B1  = 2 * A_PART;
static constexpr int OFF_B2  = 2 * A_PART + B_PART;
static constexpr int BUFB    = 2 * A_PART + 2 * B_PART;  // 30720
static constexpr int TG_SMEM = 2 * BUFB;                 // 61440

// ---------------------------------------------------------------------------
// mma.sync bf16-split2 GEMM: C = alpha*(A' @ B') (+bias[r])
//   A: row-major [M,K]; EXPA: fused exp(a - rmax)*rinv per row
//   TB:  B row-major [N,K] (C = A @ B^T);  !TB: B row-major [K,N]
//   CONCAT (!TB): k >= Ksplit reads B2 scaled by colscale[z*N+n]
// CTA tile 128x64, K chunks of 32; 4 warps (128 thr), warp tile 64x32 (2m x 2n).
// 3 CTAs/SM (12 warps).
// ---------------------------------------------------------------------------
template<bool TB, bool EXPA, bool HASBIAS, bool CONCAT>
__global__ void __launch_bounds__(128, 3) mgemm(
    const float* __restrict__ A, const float* __restrict__ B, float* __restrict__ C,
    int M, int N, int K, long sAz, long sBz,
    int modB, long sCb, long sCr, int ldc,
    const float* __restrict__ rmax, const float* __restrict__ rinv,
    const float* __restrict__ bias,
    const float* __restrict__ B2, long sB2z, int Ksplit,
    const float* __restrict__ colscale, float alpha)
{
    extern __shared__ char smem[];
    const uint32_t sb = smem_u32(smem);
    const int tid = threadIdx.x;
    const int wid = tid >> 5;
    const int lane = tid & 31;
    const int z = blockIdx.z;
    const int bm = blockIdx.y * 128;
    const int bn = blockIdx.x * 64;
    const float* Ab = A + (long)z * sAz;
    const float* Bb = B + (long)z * sBz;

    // ---- A loader: row = ar+32j (j<4), 8 consecutive k per thread ----
    const int ar = tid >> 2;
    const int ak8 = (tid & 3) * 8;
    const float* gA0 = Ab + (long)(bm + ar) * K + ak8;

    float smx[4], siv[4];
    if (EXPA) {
        #pragma unroll
        for (int j = 0; j < 4; j++) {
            const int r = bm + ar + 32 * j;
            smx[j] = rmax[(long)z * M + r];
            siv[j] = rinv[(long)z * M + r];
        }
    }

    // ---- B loader geometry ----
    const float* gB0 = nullptr;      // TB: row = ar+32j (j<2)
    int bkp = 0, bng = 0;            // NN: k-pair, n-group (8 cols)
    float4 csc0 = make_float4(1.f, 1.f, 1.f, 1.f);
    float4 csc1 = make_float4(1.f, 1.f, 1.f, 1.f);
    if (TB) {
        gB0 = Bb + (long)(bn + ar) * K + ak8;
    } else {
        bkp = tid & 15;
        bng = tid >> 4;
        if (CONCAT) {
            csc0 = *reinterpret_cast<const float4*>(colscale + (long)z * N + bn + bng * 8);
            csc1 = *reinterpret_cast<const float4*>(colscale + (long)z * N + bn + bng * 8 + 4);
        }
    }

    const int nch = K >> 5;

    float4 fa[4][2], fb[2][2];

    auto loadA = [&](int ch) {
        const float* p = gA0 + ch * 32;
        #pragma unroll
        for (int j = 0; j < 4; j++) {
            fa[j][0] = *reinterpret_cast<const float4*>(p + (long)(32 * j) * K);
            fa[j][1] = *reinterpret_cast<const float4*>(p + (long)(32 * j) * K + 4);
        }
    };
    auto loadB = [&](int ch) {
        if (TB) {
            const float* p = gB0 + ch * 32;
            #pragma unroll
            for (int j = 0; j < 2; j++) {
                fb[j][0] = *reinterpret_cast<const float4*>(p + (long)(32 * j) * K);
                fb[j][1] = *reinterpret_cast<const float4*>(p + (long)(32 * j) * K + 4);
            }
        } else {
            const int kg = ch * 32 + 2 * bkp;
            const float* src;
            if (CONCAT && kg >= Ksplit)
                src = B2 + (long)z * sB2z + (long)(kg - Ksplit) * N + bn + bng * 8;
            else
                src = Bb + (long)kg * N + bn + bng * 8;
            fb[0][0] = *reinterpret_cast<const float4*>(src);
            fb[0][1] = *reinterpret_cast<const float4*>(src + 4);
            fb[1][0] = *reinterpret_cast<const float4*>(src + N);
            fb[1][1] = *reinterpret_cast<const float4*>(src + N + 4);
            if (CONCAT && kg >= Ksplit) {
                #pragma unroll
                for (int r = 0; r < 2; r++) {
                    fb[r][0].x *= csc0.x; fb[r][0].y *= csc0.y;
                    fb[r][0].z *= csc0.z; fb[r][0].w *= csc0.w;
                    fb[r][1].x *= csc1.x; fb[r][1].y *= csc1.y;
                    fb[r][1].z *= csc1.z; fb[r][1].w *= csc1.w;
                }
            }
        }
    };
    auto stashA = [&](int buf) {
        char* a1 = smem + buf * BUFB + OFF_A1;
        char* a2 = smem + buf * BUFB + OFF_A2;
        #pragma unroll
        for (int j = 0; j < 4; j++) {
            float4 f0 = fa[j][0], f1 = fa[j][1];
            if (EXPA) {
                const float m = smx[j], v = siv[j];
                f0.x = __expf(f0.x - m) * v; f0.y = __expf(f0.y - m) * v;
                f0.z = __expf(f0.z - m) * v; f0.w = __expf(f0.w - m) * v;
                f1.x = __expf(f1.x - m) * v; f1.y = __expf(f1.y - m) * v;
                f1.z = __expf(f1.z - m) * v; f1.w = __expf(f1.w - m) * v;
            }
            uint2 h0, l0, h1, l1;
            split4(f0, h0, l0); split4(f1, h1, l1);
            const int off = (ar + 32 * j) * ROWB + (tid & 3) * 16;
            *reinterpret_cast<uint4*>(a1 + off) = make_uint4(h0.x, h0.y, h1.x, h1.y);
            *reinterpret_cast<uint4*>(a2 + off) = make_uint4(l0.x, l0.y, l1.x, l1.y);
        }
    };
    auto stashB = [&](int buf) {
        char* b1 = smem + buf * BUFB + OFF_B1;
        char* b2 = smem + buf * BUFB + OFF_B2;
        if (TB) {
            #pragma unroll
            for (int j = 0; j < 2; j++) {
                uint2 h0, l0, h1, l1;
                split4(fb[j][0], h0, l0); split4(fb[j][1], h1, l1);
                const int off = (ar + 32 * j) * ROWB + (tid & 3) * 16;
                *reinterpret_cast<uint4*>(b1 + off) = make_uint4(h0.x, h0.y, h1.x, h1.y);
                *reinterpret_cast<uint4*>(b2 + off) = make_uint4(l0.x, l0.y, l1.x, l1.y);
            }
        } else {
            const float* r0 = reinterpret_cast<const float*>(&fb[0][0]);
            const float* r1 = reinterpret_cast<const float*>(&fb[1][0]);
            #pragma unroll
            for (int u = 0; u < 8; u++) {
                const uint32_t hi = pack_hi2(r0[u], r1[u]);
                const uint32_t lo = pack_hi2(r0[u] - fhi(r0[u]), r1[u] - fhi(r1[u]));
                const int off = (bng * 8 + u) * ROWB + bkp * 4;
                *reinterpret_cast<uint32_t*>(b1 + off) = hi;
                *reinterpret_cast<uint32_t*>(b2 + off) = lo;
            }
        }
    };

    loadA(0); loadB(0);
    stashA(0); stashB(0);
    __syncthreads();

    float d[4][4][4];
    #pragma unroll
    for (int i = 0; i < 4; i++)
        #pragma unroll
        for (int j = 0; j < 4; j++)
            #pragma unroll
            for (int q = 0; q < 4; q++) d[i][j][q] = 0.f;

    const int wm = (wid >> 1) * 64;   // 2 m-warps
    const int wn = (wid & 1) * 32;    // 2 n-warps
    const int lr = lane & 15;
    const int lc = lane >> 4;

    for (int ch = 0; ch < nch; ch++) {
        const bool hasNext = (ch + 1 < nch);
        if (hasNext) { loadA(ch + 1); loadB(ch + 1); }

        const uint32_t base = sb + (ch & 1) * BUFB;
        #pragma unroll
        for (int ks = 0; ks < 2; ks++) {
            const uint32_t koff = ks * 32 + lc * 16;
            uint32_t ah[4][4], bh[4][2];
            #pragma unroll
            for (int mt = 0; mt < 4; mt++)
                ldmat4(ah[mt][0], ah[mt][1], ah[mt][2], ah[mt][3],
                       base + OFF_A1 + (wm + mt * 16 + lr) * ROWB + koff);
            #pragma unroll
            for (int bt = 0; bt < 2; bt++) {
                uint32_t r0, r1, r2, r3;
                ldmat4(r0, r1, r2, r3, base + OFF_B1 + (wn + bt * 16 + lr) * ROWB + koff);
                bh[2 * bt][0] = r0; bh[2 * bt][1] = r2;
                bh[2 * bt + 1][0] = r1; bh[2 * bt + 1][1] = r3;
            }
            // pass 1: hi*hi
            #pragma unroll
            for (int mt = 0; mt < 4; mt++)
                #pragma unroll
                for (int nt = 0; nt < 4; nt++) mma16816(d[mt][nt], ah[mt], bh[nt]);
            // pass 2: hi(A)*lo(B)
            {
                uint32_t bl[4][2];
                #pragma unroll
                for (int bt = 0; bt < 2; bt++) {
                    uint32_t r0, r1, r2, r3;
                    ldmat4(r0, r1, r2, r3, base + OFF_B2 + (wn + bt * 16 + lr) * ROWB + koff);
                    bl[2 * bt][0] = r0; bl[2 * bt][1] = r2;
                    bl[2 * bt + 1][0] = r1; bl[2 * bt + 1][1] = r3;
                }
                #pragma unroll
                for (int mt = 0; mt < 4; mt++)
                    #pragma unroll
                    for (int nt = 0; nt < 4; nt++) mma16816(d[mt][nt], ah[mt], bl[nt]);
            }
            // pass 3: lo(A)*hi(B), per-mt to cap register liveness
            #pragma unroll
            for (int mt = 0; mt < 4; mt++) {
                uint32_t al[4];
                ldmat4(al[0], al[1], al[2], al[3],
                       base + OFF_A2 + (wm + mt * 16 + lr) * ROWB + koff);
                #pragma unroll
                for (int nt = 0; nt < 4; nt++) mma16816(d[mt][nt], al, bh[nt]);
            }
        }
        if (hasNext) { stashA((ch + 1) & 1); stashB((ch + 1) & 1); }
        __syncthreads();
    }

    // epilogue
    const long coff = (long)(z % modB) * sCb + (long)(z / modB) * sCr;
    #pragma unroll
    for (int mt = 0; mt < 4; mt++) {
        const int r0 = bm + wm + mt * 16 + (lane >> 2);
        const float bi0 = HASBIAS ? bias[r0] : 0.f;
        const float bi8 = HASBIAS ? bias[r0 + 8] : 0.f;
        #pragma unroll
        for (int nt = 0; nt < 4; nt++) {
            const int c0 = bn + wn + nt * 8 + (lane & 3) * 2;
            float* p0 = C + coff + (long)r0 * ldc + c0;
            float* p1 = C + coff + (long)(r0 + 8) * ldc + c0;
            *reinterpret_cast<float2*>(p0) =
                make_float2(d[mt][nt][0] * alpha + bi0, d[mt][nt][1] * alpha + bi0);
            *reinterpret_cast<float2*>(p1) =
                make_float2(d[mt][nt][2] * alpha + bi8, d[mt][nt][3] * alpha + bi8);
        }
    }
}

// ---------------------------------------------------------------------------
// Reductions / elementwise helpers
// ---------------------------------------------------------------------------
__device__ __forceinline__ float blockReduce(float v, bool ismax) {
    __shared__ float sh[32];
    __syncthreads();
    int lane = threadIdx.x & 31, wid = threadIdx.x >> 5;
    #pragma unroll
    for (int o = 16; o; o >>= 1) {
        float t = __shfl_xor_sync(0xffffffffu, v, o);
        v = ismax ? fmaxf(v, t) : (v + t);
    }
    if (lane == 0) sh[wid] = v;
    __syncthreads();
    int nw = (blockDim.x + 31) >> 5;
    if (wid == 0) {
        v = (lane < nw) ? sh[lane] : (ismax ? -1e30f : 0.f);
        #pragma unroll
        for (int o = 16; o; o >>= 1) {
            float t = __shfl_xor_sync(0xffffffffu, v, o);
            v = ismax ? fmaxf(v, t) : (v + t);
        }
        if (lane == 0) sh[0] = v;
    }
    __syncthreads();
    return sh[0];
}

// Row stats for rows of exactly 4096 floats: single DRAM pass, row cached in regs
__global__ void row_stats4k(const float* __restrict__ X, float* __restrict__ omax,
                            float* __restrict__ oinv)
{
    const long row = blockIdx.x;
    const float4* x = reinterpret_cast<const float4*>(X + row * 4096);
    float4 v[4];
    float m = -1e30f;
    #pragma unroll
    for (int j = 0; j < 4; j++) {
        v[j] = x[threadIdx.x + 256 * j];
        m = fmaxf(m, fmaxf(fmaxf(v[j].x, v[j].y), fmaxf(v[j].z, v[j].w)));
    }
    m = blockReduce(m, true);
    float s = 0.f;
    #pragma unroll
    for (int j = 0; j < 4; j++)
        s += __expf(v[j].x - m) + __expf(v[j].y - m) + __expf(v[j].z - m) + __expf(v[j].w - m);
    s = blockReduce(s, false);
    if (threadIdx.x == 0) { omax[row] = m; oinv[row] = 1.f / s; }
}

__global__ void softmax_inplace(float* __restrict__ X, int len)
{
    const long row = blockIdx.x;
    float* x = X + row * len;
    float m = -1e30f;
    for (int i = threadIdx.x; i < len; i += blockDim.x) m = fmaxf(m, x[i]);
    m = blockReduce(m, true);
    float s = 0.f;
    for (int i = threadIdx.x; i < len; i += blockDim.x) s += __expf(x[i] - m);
    s = blockReduce(s, false);
    const float inv = 1.f / s;
    for (int i = threadIdx.x; i < len; i += blockDim.x) x[i] = __expf(x[i] - m) * inv;
}

__global__ void norm_rows256(float* __restrict__ V)
{
    const long row = blockIdx.x;
    float* v = V + row * 256;
    const float x = v[threadIdx.x];
    const float s = blockReduce(x * x, false);
    v[threadIdx.x] = x * rsqrtf(s);
}

__global__ void qcol_norm(const float* __restrict__ q, float* __restrict__ out)
{
    const int b = blockIdx.y;
    const int n = blockIdx.x * 256 + threadIdx.x;
    const float* p = q + (long)b * 256 * 4096 + n;
    float s = 0.f;
    #pragma unroll 8
    for (int c = 0; c < 256; c++) { float v = p[(long)c * 4096]; s += v * v; }
    out[b * 4096 + n] = rsqrtf(s);
}

__global__ void bn_stats(const float* __restrict__ y, float* __restrict__ mean,
                         float* __restrict__ istd)
{
    const int o = blockIdx.x;
    float s = 0.f, s2 = 0.f;
    for (int b = 0; b < 16; b++) {
        const float* p = y + ((long)b * 512 + o) * 4096;
        for (int i = threadIdx.x; i < 4096; i += 256) {
            float v = p[i]; s += v; s2 += v * v;
        }
    }
    s = blockReduce(s, false);
    s2 = blockReduce(s2, false);
    if (threadIdx.x == 0) {
        float mu = s * (1.f / 65536.f);
        mean[o] = mu;
        istd[o] = 1.f / sqrtf(s2 * (1.f / 65536.f) - mu * mu + 1e-5f);
    }
}

__global__ void bn_apply(float* __restrict__ y, const float* __restrict__ mean,
                         const float* __restrict__ istd, const float* __restrict__ g,
                         const float* __restrict__ b)
{
    const long i = (long)blockIdx.x * 256 + threadIdx.x;
    const int o = (int)((i >> 12) & 511);
    float v = (y[i] - mean[o]) * istd[o] * g[o] + b[o];
    y[i] = v > 0.f ? v : 0.f;
}

// ---------------------------------------------------------------------------
// Host orchestration
// ---------------------------------------------------------------------------
struct Scratch {
    float *kf, *kmax, *kinv, *qmax, *qinvs, *kpbs, *qpb, *sim, *value, *qcol, *cm, *mean, *istd;
    cudaStream_t s2;
    cudaEvent_t evFork, evJoin;
};

static Scratch fetch_scratch() {
    Scratch s;
    cudaGetSymbolAddress((void**)&s.kf,    g_kf);
    cudaGetSymbolAddress((void**)&s.kmax,  g_kmax);
    cudaGetSymbolAddress((void**)&s.kinv,  g_kinv);
    cudaGetSymbolAddress((void**)&s.qmax,  g_qmax);
    cudaGetSymbolAddress((void**)&s.qinvs, g_qinvs);
    cudaGetSymbolAddress((void**)&s.kpbs,  g_kpbs);
    cudaGetSymbolAddress((void**)&s.qpb,   g_qpb);
    cudaGetSymbolAddress((void**)&s.sim,   g_sim);
    cudaGetSymbolAddress((void**)&s.value, g_value);
    cudaGetSymbolAddress((void**)&s.qcol,  g_qcol);
    cudaGetSymbolAddress((void**)&s.cm,    g_cm);
    cudaGetSymbolAddress((void**)&s.mean,  g_mean);
    cudaGetSymbolAddress((void**)&s.istd,  g_istd);
    cudaStreamCreateWithFlags(&s.s2, cudaStreamNonBlocking);
    cudaEventCreateWithFlags(&s.evFork, cudaEventDisableTiming);
    cudaEventCreateWithFlags(&s.evJoin, cudaEventDisableTiming);
    cudaFuncSetAttribute(mgemm<false, false, true,  false>, cudaFuncAttributeMaxDynamicSharedMemorySize, TG_SMEM);
    cudaFuncSetAttribute(mgemm<true,  true,  false, false>, cudaFuncAttributeMaxDynamicSharedMemorySize, TG_SMEM);
    cudaFuncSetAttribute(mgemm<true,  false, false, false>, cudaFuncAttributeMaxDynamicSharedMemorySize, TG_SMEM);
    cudaFuncSetAttribute(mgemm<false, false, false, false>, cudaFuncAttributeMaxDynamicSharedMemorySize, TG_SMEM);
    cudaFuncSetAttribute(mgemm<false, false, true,  true >, cudaFuncAttributeMaxDynamicSharedMemorySize, TG_SMEM);
    return s;
}

extern "C" void kernel_launch(void* const* d_in, const int* in_sizes, int n_in,
                              void* d_out, int out_size)
{
    (void)in_sizes; (void)n_in; (void)out_size;
    static Scratch s = fetch_scratch();  // first call is the non-captured correctness run

    const float* x     = (const float*)d_in[0];
    const float* query = (const float*)d_in[1];
    const float* refs  = (const float*)d_in[2];
    const float* K_w   = (const float*)d_in[3];
    const float* K_b   = (const float*)d_in[4];
    // d_in[5], d_in[6] = V_w, V_b : dead code in the reference.
    const float* f_w   = (const float*)d_in[7];
    const float* f_b   = (const float*)d_in[8];
    const float* bn_g  = (const float*)d_in[9];
    const float* bn_b  = (const float*)d_in[10];
    float* out = (float*)d_out;

    // ---- fork: independent query branch on s2 ----
    cudaEventRecord(s.evFork, 0);
    cudaStreamWaitEvent(s.s2, s.evFork, 0);

    row_stats4k<<<16 * 256, 256, 0, s.s2>>>(query, s.qmax, s.qinvs);
    mgemm<true, true, false, false><<<dim3(4, 2, 16), 128, TG_SMEM, s.s2>>>(
        query, query, s.qpb, 256, 256, 4096, 256L * 4096, 256L * 4096,
        16, 256L * 256, 0, 256,
        s.qmax, s.qinvs, nullptr, nullptr, 0, 0, nullptr, 1.f);
    qcol_norm<<<dim3(16, 16), 256, 0, s.s2>>>(query, s.qcol);

    // main branch: kf chain
    // 1) kf[z] = K_w @ refs[z] + K_b   (NN, bias)
    mgemm<false, false, true, false><<<dim3(64, 2, 48), 128, TG_SMEM>>>(
        K_w, refs, s.kf, 256, 4096, 512, 0, 512L * 4096,
        48, 256L * 4096, 0, 4096,
        nullptr, nullptr, K_b, nullptr, 0, 0, nullptr, 1.f);

    // 2) kf softmax row stats (single-pass, register-cached)
    row_stats4k<<<48 * 256, 256>>>(s.kf, s.kmax, s.kinv);

    // 3) k_pb[z] = softmax(kf[z]) @ kf[z]^T  (TB, EXPA)
    mgemm<true, true, false, false><<<dim3(4, 2, 48), 128, TG_SMEM>>>(
        s.kf, s.kf, s.kpbs, 256, 256, 4096, 256L * 4096, 256L * 4096,
        16, 768L * 256, 256L * 256, 256,
        s.kmax, s.kinv, nullptr, nullptr, 0, 0, nullptr, 1.f);

    // ---- join s2 back into main before stage 5 ----
    cudaEventRecord(s.evJoin, s.s2);
    cudaStreamWaitEvent(0, s.evJoin, 0);

    // 5) sim = (q_pb @ k_pbs^T) / sqrt(256)
    mgemm<true, false, false, false><<<dim3(12, 2, 16), 128, TG_SMEM>>>(
        s.qpb, s.kpbs, s.sim, 256, 768, 256, 256L * 256, 768L * 256,
        16, 256L * 768, 0, 768,
        nullptr, nullptr, nullptr, nullptr, 0, 0, nullptr, 0.0625f);

    // 6) softmax over k
    softmax_inplace<<<16 * 256, 256>>>(s.sim, 768);

    // 7) value = sim @ k_pbs (NN)
    mgemm<false, false, false, false><<<dim3(4, 2, 16), 128, TG_SMEM>>>(
        s.sim, s.kpbs, s.value, 256, 256, 768, 256L * 768, 768L * 256,
        16, 256L * 256, 0, 256,
        nullptr, nullptr, nullptr, nullptr, 0, 0, nullptr, 1.f);

    // 8) normalize prototypes
    norm_rows256<<<16 * 256, 256>>>(s.value);

    // 9) cm_raw = proto_n @ query (qcol folded into stage 10 loader)
    mgemm<false, false, false, false><<<dim3(64, 2, 16), 128, TG_SMEM>>>(
        s.value, query, s.cm, 256, 4096, 256, 256L * 256, 256L * 4096,
        16, 256L * 4096, 0, 4096,
        nullptr, nullptr, nullptr, nullptr, 0, 0, nullptr, 1.f);

    // 10) y = f_w @ concat(x, cm * qcol) + f_b
    mgemm<false, false, true, true><<<dim3(64, 4, 16), 128, TG_SMEM>>>(
        f_w, x, out, 512, 4096, 768, 0, 512L * 4096,
        16, 512L * 4096, 0, 4096,
        nullptr, nullptr, f_b, s.cm, 256L * 4096, 512, s.qcol, 1.f);

    // 11) BatchNorm (batch stats) + ReLU
    bn_stats<<<512, 256>>>(out, s.mean, s.istd);
    bn_apply<<<131072, 256>>>(out, s.mean, s.istd, bn_g, bn_b);
}

// round 13
// speedup vs baseline: 1.4264x; 1.0396x over previous
#include <cuda_runtime.h>
#include <cuda_bf16.h>
#include <cstdint>
#include <stdint.h>
#include <math.h>

// ---------------------------------------------------------------------------
// Scratch (static __device__ arrays; no allocations anywhere)
// ---------------------------------------------------------------------------
__device__ float g_kf[48u * 256u * 4096u];   // 201 MB
__device__ float g_kmax[48 * 256];
__device__ float g_kinv[48 * 256];
__device__ float g_qmax[16 * 256];
__device__ float g_qinvs[16 * 256];
__device__ float g_kpbs[16 * 768 * 256];
__device__ float g_qpb[16 * 256 * 256];
__device__ float g_sim[16 * 256 * 768];
__device__ float g_value[16 * 256 * 256];
__device__ float g_qcol[16 * 4096];
__device__ float g_cm[16u * 256u * 4096u];   // 67 MB
__device__ float g_mean[512];
__device__ float g_istd[512];

// ---------------------------------------------------------------------------
// mma.sync helpers (plain sm_80+ PTX — valid under compute_103)
// ---------------------------------------------------------------------------
__device__ __forceinline__ uint32_t smem_u32(const void* p) {
    uint32_t a;
    asm("{ .reg .u64 t; cvta.to.shared.u64 t, %1; cvt.u32.u64 %0, t; }" : "=r"(a) : "l"(p));
    return a;
}
__device__ __forceinline__ void ldmat4(uint32_t& r0, uint32_t& r1, uint32_t& r2, uint32_t& r3,
                                       uint32_t addr) {
    asm volatile("ldmatrix.sync.aligned.m8n8.x4.shared.b16 {%0,%1,%2,%3}, [%4];"
                 : "=r"(r0), "=r"(r1), "=r"(r2), "=r"(r3) : "r"(addr));
}
__device__ __forceinline__ void mma16816(float* d, const uint32_t* a, const uint32_t* b) {
    asm volatile(
        "mma.sync.aligned.m16n8k16.row.col.f32.bf16.bf16.f32 "
        "{%0,%1,%2,%3}, {%4,%5,%6,%7}, {%8,%9}, {%0,%1,%2,%3};"
        : "+f"(d[0]), "+f"(d[1]), "+f"(d[2]), "+f"(d[3])
        : "r"(a[0]), "r"(a[1]), "r"(a[2]), "r"(a[3]), "r"(b[0]), "r"(b[1]));
}

// Truncating fp32 -> bf16 split helpers (PRMT-based)
__device__ __forceinline__ uint32_t pack_hi2(float a, float b) {
    uint32_t r;
    asm("prmt.b32 %0, %1, %2, 0x7632;" : "=r"(r)
        : "r"(__float_as_uint(a)), "r"(__float_as_uint(b)));
    return r;
}
__device__ __forceinline__ float fhi(float f) {
    return __uint_as_float(__float_as_uint(f) & 0xFFFF0000u);
}
__device__ __forceinline__ void split4(float4 f, uint2& hi, uint2& lo) {
    hi = make_uint2(pack_hi2(f.x, f.y), pack_hi2(f.z, f.w));
    lo = make_uint2(pack_hi2(f.x - fhi(f.x), f.y - fhi(f.y)),
                    pack_hi2(f.z - fhi(f.z), f.w - fhi(f.w)));
}

// smem geometry (per buffer): A parts 128 rows, B parts 64 rows, 80 B rows.
static constexpr int ROWB    = 80;             // 32 bf16 + 8 pad
static constexpr int A_PART  = 128 * ROWB;
static constexpr int B_PART  = 64 * ROWB;
static constexpr int OFF_A1  = 0;
static constexpr int OFF_A2  = A_PART;
static constexpr int OFF_B1  = 2 * A_PART;
static constexpr int OFF_B2  = 2 * A_PART + B_PART;
static constexpr int BUFB    = 2 * A_PART + 2 * B_PART;  // 30720
static constexpr int TG_SMEM = 2 * BUFB;                 // 61440

// ---------------------------------------------------------------------------
// mma.sync bf16-split2 GEMM: C = alpha*(A' @ B') (+bias[r]) (+=C if ACCUM)
//   A: row-major [M, lda], first K cols used; EXPA: fused exp(a-rmax)*rinv
//   TB:  B row-major [N,K] (C = A @ B^T);  !TB: B row-major [K,N]
//   CONCAT (!TB): k >= Ksplit reads B2 scaled by colscale[z*N+n]
// CTA tile 128x64, K chunks of 32; 4 warps (128 thr), warp tile 64x32.
// ---------------------------------------------------------------------------
template<bool TB, bool EXPA, bool HASBIAS, bool CONCAT, bool ACCUM>
__global__ void __launch_bounds__(128, 3) mgemm(
    const float* __restrict__ A, const float* __restrict__ B, float* __restrict__ C,
    int M, int N, int K, int lda, long sAz, long sBz,
    int modB, long sCb, long sCr, int ldc,
    const float* __restrict__ rmax, const float* __restrict__ rinv,
    const float* __restrict__ bias,
    const float* __restrict__ B2, long sB2z, int Ksplit,
    const float* __restrict__ colscale, float alpha)
{
    extern __shared__ char smem[];
    const uint32_t sb = smem_u32(smem);
    const int tid = threadIdx.x;
    const int wid = tid >> 5;
    const int lane = tid & 31;
    const int z = blockIdx.z;
    const int bm = blockIdx.y * 128;
    const int bn = blockIdx.x * 64;
    const float* Ab = A + (long)z * sAz;
    const float* Bb = B + (long)z * sBz;

    // ---- A loader: row = ar+32j (j<4), 8 consecutive k per thread ----
    const int ar = tid >> 2;
    const int ak8 = (tid & 3) * 8;
    const float* gA0 = Ab + (long)(bm + ar) * lda + ak8;

    float smx[4], siv[4];
    if (EXPA) {
        #pragma unroll
        for (int j = 0; j < 4; j++) {
            const int r = bm + ar + 32 * j;
            smx[j] = rmax[(long)z * M + r];
            siv[j] = rinv[(long)z * M + r];
        }
    }

    // ---- B loader geometry ----
    const float* gB0 = nullptr;      // TB: row = ar+32j (j<2)
    int bkp = 0, bng = 0;            // NN: k-pair, n-group (8 cols)
    float4 csc0 = make_float4(1.f, 1.f, 1.f, 1.f);
    float4 csc1 = make_float4(1.f, 1.f, 1.f, 1.f);
    if (TB) {
        gB0 = Bb + (long)(bn + ar) * K + ak8;
    } else {
        bkp = tid & 15;
        bng = tid >> 4;
        if (CONCAT) {
            csc0 = *reinterpret_cast<const float4*>(colscale + (long)z * N + bn + bng * 8);
            csc1 = *reinterpret_cast<const float4*>(colscale + (long)z * N + bn + bng * 8 + 4);
        }
    }

    const int nch = K >> 5;

    float4 fa[4][2], fb[2][2];

    auto loadA = [&](int ch) {
        const float* p = gA0 + ch * 32;
        #pragma unroll
        for (int j = 0; j < 4; j++) {
            fa[j][0] = *reinterpret_cast<const float4*>(p + (long)(32 * j) * lda);
            fa[j][1] = *reinterpret_cast<const float4*>(p + (long)(32 * j) * lda + 4);
        }
    };
    auto loadB = [&](int ch) {
        if (TB) {
            const float* p = gB0 + ch * 32;
            #pragma unroll
            for (int j = 0; j < 2; j++) {
                fb[j][0] = *reinterpret_cast<const float4*>(p + (long)(32 * j) * K);
                fb[j][1] = *reinterpret_cast<const float4*>(p + (long)(32 * j) * K + 4);
            }
        } else {
            const int kg = ch * 32 + 2 * bkp;
            const float* src;
            if (CONCAT && kg >= Ksplit)
                src = B2 + (long)z * sB2z + (long)(kg - Ksplit) * N + bn + bng * 8;
            else
                src = Bb + (long)kg * N + bn + bng * 8;
            fb[0][0] = *reinterpret_cast<const float4*>(src);
            fb[0][1] = *reinterpret_cast<const float4*>(src + 4);
            fb[1][0] = *reinterpret_cast<const float4*>(src + N);
            fb[1][1] = *reinterpret_cast<const float4*>(src + N + 4);
            if (CONCAT && kg >= Ksplit) {
                #pragma unroll
                for (int r = 0; r < 2; r++) {
                    fb[r][0].x *= csc0.x; fb[r][0].y *= csc0.y;
                    fb[r][0].z *= csc0.z; fb[r][0].w *= csc0.w;
                    fb[r][1].x *= csc1.x; fb[r][1].y *= csc1.y;
                    fb[r][1].z *= csc1.z; fb[r][1].w *= csc1.w;
                }
            }
        }
    };
    auto stashA = [&](int buf) {
        char* a1 = smem + buf * BUFB + OFF_A1;
        char* a2 = smem + buf * BUFB + OFF_A2;
        #pragma unroll
        for (int j = 0; j < 4; j++) {
            float4 f0 = fa[j][0], f1 = fa[j][1];
            if (EXPA) {
                const float m = smx[j], v = siv[j];
                f0.x = __expf(f0.x - m) * v; f0.y = __expf(f0.y - m) * v;
                f0.z = __expf(f0.z - m) * v; f0.w = __expf(f0.w - m) * v;
                f1.x = __expf(f1.x - m) * v; f1.y = __expf(f1.y - m) * v;
                f1.z = __expf(f1.z - m) * v; f1.w = __expf(f1.w - m) * v;
            }
            uint2 h0, l0, h1, l1;
            split4(f0, h0, l0); split4(f1, h1, l1);
            const int off = (ar + 32 * j) * ROWB + (tid & 3) * 16;
            *reinterpret_cast<uint4*>(a1 + off) = make_uint4(h0.x, h0.y, h1.x, h1.y);
            *reinterpret_cast<uint4*>(a2 + off) = make_uint4(l0.x, l0.y, l1.x, l1.y);
        }
    };
    auto stashB = [&](int buf) {
        char* b1 = smem + buf * BUFB + OFF_B1;
        char* b2 = smem + buf * BUFB + OFF_B2;
        if (TB) {
            #pragma unroll
            for (int j = 0; j < 2; j++) {
                uint2 h0, l0, h1, l1;
                split4(fb[j][0], h0, l0); split4(fb[j][1], h1, l1);
                const int off = (ar + 32 * j) * ROWB + (tid & 3) * 16;
                *reinterpret_cast<uint4*>(b1 + off) = make_uint4(h0.x, h0.y, h1.x, h1.y);
                *reinterpret_cast<uint4*>(b2 + off) = make_uint4(l0.x, l0.y, l1.x, l1.y);
            }
        } else {
            const float* r0 = reinterpret_cast<const float*>(&fb[0][0]);
            const float* r1 = reinterpret_cast<const float*>(&fb[1][0]);
            #pragma unroll
            for (int u = 0; u < 8; u++) {
                const uint32_t hi = pack_hi2(r0[u], r1[u]);
                const uint32_t lo = pack_hi2(r0[u] - fhi(r0[u]), r1[u] - fhi(r1[u]));
                const int off = (bng * 8 + u) * ROWB + bkp * 4;
                *reinterpret_cast<uint32_t*>(b1 + off) = hi;
                *reinterpret_cast<uint32_t*>(b2 + off) = lo;
            }
        }
    };

    loadA(0); loadB(0);
    stashA(0); stashB(0);
    __syncthreads();

    float d[4][4][4];
    #pragma unroll
    for (int i = 0; i < 4; i++)
        #pragma unroll
        for (int j = 0; j < 4; j++)
            #pragma unroll
            for (int q = 0; q < 4; q++) d[i][j][q] = 0.f;

    const int wm = (wid >> 1) * 64;   // 2 m-warps
    const int wn = (wid & 1) * 32;    // 2 n-warps
    const int lr = lane & 15;
    const int lc = lane >> 4;

    for (int ch = 0; ch < nch; ch++) {
        const bool hasNext = (ch + 1 < nch);
        if (hasNext) { loadA(ch + 1); loadB(ch + 1); }

        const uint32_t base = sb + (ch & 1) * BUFB;
        #pragma unroll
        for (int ks = 0; ks < 2; ks++) {
            const uint32_t koff = ks * 32 + lc * 16;
            uint32_t ah[4][4], bh[4][2];
            #pragma unroll
            for (int mt = 0; mt < 4; mt++)
                ldmat4(ah[mt][0], ah[mt][1], ah[mt][2], ah[mt][3],
                       base + OFF_A1 + (wm + mt * 16 + lr) * ROWB + koff);
            #pragma unroll
            for (int bt = 0; bt < 2; bt++) {
                uint32_t r0, r1, r2, r3;
                ldmat4(r0, r1, r2, r3, base + OFF_B1 + (wn + bt * 16 + lr) * ROWB + koff);
                bh[2 * bt][0] = r0; bh[2 * bt][1] = r2;
                bh[2 * bt + 1][0] = r1; bh[2 * bt + 1][1] = r3;
            }
            #pragma unroll
            for (int mt = 0; mt < 4; mt++)
                #pragma unroll
                for (int nt = 0; nt < 4; nt++) mma16816(d[mt][nt], ah[mt], bh[nt]);
            {
                uint32_t bl[4][2];
                #pragma unroll
                for (int bt = 0; bt < 2; bt++) {
                    uint32_t r0, r1, r2, r3;
                    ldmat4(r0, r1, r2, r3, base + OFF_B2 + (wn + bt * 16 + lr) * ROWB + koff);
                    bl[2 * bt][0] = r0; bl[2 * bt][1] = r2;
                    bl[2 * bt + 1][0] = r1; bl[2 * bt + 1][1] = r3;
                }
                #pragma unroll
                for (int mt = 0; mt < 4; mt++)
                    #pragma unroll
                    for (int nt = 0; nt < 4; nt++) mma16816(d[mt][nt], ah[mt], bl[nt]);
            }
            #pragma unroll
            for (int mt = 0; mt < 4; mt++) {
                uint32_t al[4];
                ldmat4(al[0], al[1], al[2], al[3],
                       base + OFF_A2 + (wm + mt * 16 + lr) * ROWB + koff);
                #pragma unroll
                for (int nt = 0; nt < 4; nt++) mma16816(d[mt][nt], al, bh[nt]);
            }
        }
        if (hasNext) { stashA((ch + 1) & 1); stashB((ch + 1) & 1); }
        __syncthreads();
    }

    // epilogue
    const long coff = (long)(z % modB) * sCb + (long)(z / modB) * sCr;
    #pragma unroll
    for (int mt = 0; mt < 4; mt++) {
        const int r0 = bm + wm + mt * 16 + (lane >> 2);
        const float bi0 = HASBIAS ? bias[r0] : 0.f;
        const float bi8 = HASBIAS ? bias[r0 + 8] : 0.f;
        #pragma unroll
        for (int nt = 0; nt < 4; nt++) {
            const int c0 = bn + wn + nt * 8 + (lane & 3) * 2;
            float* p0 = C + coff + (long)r0 * ldc + c0;
            float* p1 = C + coff + (long)(r0 + 8) * ldc + c0;
            float v0 = d[mt][nt][0] * alpha + bi0;
            float v1 = d[mt][nt][1] * alpha + bi0;
            float v2 = d[mt][nt][2] * alpha + bi8;
            float v3 = d[mt][nt][3] * alpha + bi8;
            if (ACCUM) {
                const float2 o0 = *reinterpret_cast<float2*>(p0);
                const float2 o1 = *reinterpret_cast<float2*>(p1);
                v0 += o0.x; v1 += o0.y; v2 += o1.x; v3 += o1.y;
            }
            *reinterpret_cast<float2*>(p0) = make_float2(v0, v1);
            *reinterpret_cast<float2*>(p1) = make_float2(v2, v3);
        }
    }
}

// ---------------------------------------------------------------------------
// Reductions / elementwise helpers
// ---------------------------------------------------------------------------
__device__ __forceinline__ float blockReduce(float v, bool ismax) {
    __shared__ float sh[32];
    __syncthreads();
    int lane = threadIdx.x & 31, wid = threadIdx.x >> 5;
    #pragma unroll
    for (int o = 16; o; o >>= 1) {
        float t = __shfl_xor_sync(0xffffffffu, v, o);
        v = ismax ? fmaxf(v, t) : (v + t);
    }
    if (lane == 0) sh[wid] = v;
    __syncthreads();
    int nw = (blockDim.x + 31) >> 5;
    if (wid == 0) {
        v = (lane < nw) ? sh[lane] : (ismax ? -1e30f : 0.f);
        #pragma unroll
        for (int o = 16; o; o >>= 1) {
            float t = __shfl_xor_sync(0xffffffffu, v, o);
            v = ismax ? fmaxf(v, t) : (v + t);
        }
        if (lane == 0) sh[0] = v;
    }
    __syncthreads();
    return sh[0];
}

// Row stats for rows of exactly 4096 floats: single DRAM pass, row cached in regs
__global__ void row_stats4k(const float* __restrict__ X, float* __restrict__ omax,
                            float* __restrict__ oinv)
{
    const long row = blockIdx.x;
    const float4* x = reinterpret_cast<const float4*>(X + row * 4096);
    float4 v[4];
    float m = -1e30f;
    #pragma unroll
    for (int j = 0; j < 4; j++) {
        v[j] = x[threadIdx.x + 256 * j];
        m = fmaxf(m, fmaxf(fmaxf(v[j].x, v[j].y), fmaxf(v[j].z, v[j].w)));
    }
    m = blockReduce(m, true);
    float s = 0.f;
    #pragma unroll
    for (int j = 0; j < 4; j++)
        s += __expf(v[j].x - m) + __expf(v[j].y - m) + __expf(v[j].z - m) + __expf(v[j].w - m);
    s = blockReduce(s, false);
    if (threadIdx.x == 0) { omax[row] = m; oinv[row] = 1.f / s; }
}

__global__ void softmax_inplace(float* __restrict__ X, int len)
{
    const long row = blockIdx.x;
    float* x = X + row * len;
    float m = -1e30f;
    for (int i = threadIdx.x; i < len; i += blockDim.x) m = fmaxf(m, x[i]);
    m = blockReduce(m, true);
    float s = 0.f;
    for (int i = threadIdx.x; i < len; i += blockDim.x) s += __expf(x[i] - m);
    s = blockReduce(s, false);
    const float inv = 1.f / s;
    for (int i = threadIdx.x; i < len; i += blockDim.x) x[i] = __expf(x[i] - m) * inv;
}

__global__ void norm_rows256(float* __restrict__ V)
{
    const long row = blockIdx.x;
    float* v = V + row * 256;
    const float x = v[threadIdx.x];
    const float s = blockReduce(x * x, false);
    v[threadIdx.x] = x * rsqrtf(s);
}

__global__ void qcol_norm(const float* __restrict__ q, float* __restrict__ out)
{
    const int b = blockIdx.y;
    const int n = blockIdx.x * 256 + threadIdx.x;
    const float* p = q + (long)b * 256 * 4096 + n;
    float s = 0.f;
    #pragma unroll 8
    for (int c = 0; c < 256; c++) { float v = p[(long)c * 4096]; s += v * v; }
    out[b * 4096 + n] = rsqrtf(s);
}

__global__ void bn_stats(const float* __restrict__ y, float* __restrict__ mean,
                         float* __restrict__ istd)
{
    const int o = blockIdx.x;
    float s = 0.f, s2 = 0.f;
    for (int b = 0; b < 16; b++) {
        const float* p = y + ((long)b * 512 + o) * 4096;
        for (int i = threadIdx.x; i < 4096; i += 256) {
            float v = p[i]; s += v; s2 += v * v;
        }
    }
    s = blockReduce(s, false);
    s2 = blockReduce(s2, false);
    if (threadIdx.x == 0) {
        float mu = s * (1.f / 65536.f);
        mean[o] = mu;
        istd[o] = 1.f / sqrtf(s2 * (1.f / 65536.f) - mu * mu + 1e-5f);
    }
}

__global__ void bn_apply(float* __restrict__ y, const float* __restrict__ mean,
                         const float* __restrict__ istd, const float* __restrict__ g,
                         const float* __restrict__ b)
{
    const long i = (long)blockIdx.x * 256 + threadIdx.x;
    const int o = (int)((i >> 12) & 511);
    float v = (y[i] - mean[o]) * istd[o] * g[o] + b[o];
    y[i] = v > 0.f ? v : 0.f;
}

// ---------------------------------------------------------------------------
// Host orchestration
// ---------------------------------------------------------------------------
struct Scratch {
    float *kf, *kmax, *kinv, *qmax, *qinvs, *kpbs, *qpb, *sim, *value, *qcol, *cm, *mean, *istd;
    cudaStream_t s2;
    cudaEvent_t evFork, evJoin;
};

static Scratch fetch_scratch() {
    Scratch s;
    cudaGetSymbolAddress((void**)&s.kf,    g_kf);
    cudaGetSymbolAddress((void**)&s.kmax,  g_kmax);
    cudaGetSymbolAddress((void**)&s.kinv,  g_kinv);
    cudaGetSymbolAddress((void**)&s.qmax,  g_qmax);
    cudaGetSymbolAddress((void**)&s.qinvs, g_qinvs);
    cudaGetSymbolAddress((void**)&s.kpbs,  g_kpbs);
    cudaGetSymbolAddress((void**)&s.qpb,   g_qpb);
    cudaGetSymbolAddress((void**)&s.sim,   g_sim);
    cudaGetSymbolAddress((void**)&s.value, g_value);
    cudaGetSymbolAddress((void**)&s.qcol,  g_qcol);
    cudaGetSymbolAddress((void**)&s.cm,    g_cm);
    cudaGetSymbolAddress((void**)&s.mean,  g_mean);
    cudaGetSymbolAddress((void**)&s.istd,  g_istd);
    cudaStreamCreateWithFlags(&s.s2, cudaStreamNonBlocking);
    cudaEventCreateWithFlags(&s.evFork, cudaEventDisableTiming);
    cudaEventCreateWithFlags(&s.evJoin, cudaEventDisableTiming);
    cudaFuncSetAttribute(mgemm<false, false, true,  false, false>, cudaFuncAttributeMaxDynamicSharedMemorySize, TG_SMEM);
    cudaFuncSetAttribute(mgemm<true,  true,  false, false, false>, cudaFuncAttributeMaxDynamicSharedMemorySize, TG_SMEM);
    cudaFuncSetAttribute(mgemm<true,  false, false, false, false>, cudaFuncAttributeMaxDynamicSharedMemorySize, TG_SMEM);
    cudaFuncSetAttribute(mgemm<false, false, false, false, false>, cudaFuncAttributeMaxDynamicSharedMemorySize, TG_SMEM);
    cudaFuncSetAttribute(mgemm<false, false, false, true,  true >, cudaFuncAttributeMaxDynamicSharedMemorySize, TG_SMEM);
    return s;
}

extern "C" void kernel_launch(void* const* d_in, const int* in_sizes, int n_in,
                              void* d_out, int out_size)
{
    (void)in_sizes; (void)n_in; (void)out_size;
    static Scratch s = fetch_scratch();  // first call is the non-captured correctness run

    const float* x     = (const float*)d_in[0];
    const float* query = (const float*)d_in[1];
    const float* refs  = (const float*)d_in[2];
    const float* K_w   = (const float*)d_in[3];
    const float* K_b   = (const float*)d_in[4];
    // d_in[5], d_in[6] = V_w, V_b : dead code in the reference.
    const float* f_w   = (const float*)d_in[7];
    const float* f_b   = (const float*)d_in[8];
    const float* bn_g  = (const float*)d_in[9];
    const float* bn_b  = (const float*)d_in[10];
    float* out = (float*)d_out;

    // ---- fork: independent work on s2 ----
    cudaEventRecord(s.evFork, 0);
    cudaStreamWaitEvent(s.s2, s.evFork, 0);

    // s2: query branch (stats, q_pb, qcol), then stage 10a (x-part of final conv)
    row_stats4k<<<16 * 256, 256, 0, s.s2>>>(query, s.qmax, s.qinvs);
    mgemm<true, true, false, false, false><<<dim3(4, 2, 16), 128, TG_SMEM, s.s2>>>(
        query, query, s.qpb, 256, 256, 4096, 4096, 256L * 4096, 256L * 4096,
        16, 256L * 256, 0, 256,
        s.qmax, s.qinvs, nullptr, nullptr, 0, 0, nullptr, 1.f);
    qcol_norm<<<dim3(16, 16), 256, 0, s.s2>>>(query, s.qcol);
    // 10a) out = f_w[:, :512] @ x + f_b   (no deps; overlaps kf chain)
    mgemm<false, false, true, false, false><<<dim3(64, 4, 16), 128, TG_SMEM, s.s2>>>(
        f_w, x, out, 512, 4096, 512, 768, 0, 512L * 4096,
        16, 512L * 4096, 0, 4096,
        nullptr, nullptr, f_b, nullptr, 0, 0, nullptr, 1.f);

    // main: kf chain
    // 1) kf[z] = K_w @ refs[z] + K_b
    mgemm<false, false, true, false, false><<<dim3(64, 2, 48), 128, TG_SMEM>>>(
        K_w, refs, s.kf, 256, 4096, 512, 512, 0, 512L * 4096,
        48, 256L * 4096, 0, 4096,
        nullptr, nullptr, K_b, nullptr, 0, 0, nullptr, 1.f);

    // 2) kf softmax row stats
    row_stats4k<<<48 * 256, 256>>>(s.kf, s.kmax, s.kinv);

    // 3) k_pb[z] = softmax(kf[z]) @ kf[z]^T
    mgemm<true, true, false, false, false><<<dim3(4, 2, 48), 128, TG_SMEM>>>(
        s.kf, s.kf, s.kpbs, 256, 256, 4096, 4096, 256L * 4096, 256L * 4096,
        16, 768L * 256, 256L * 256, 256,
        s.kmax, s.kinv, nullptr, nullptr, 0, 0, nullptr, 1.f);

    // ---- join s2 (q_pb + out ready) before stage 5 ----
    cudaEventRecord(s.evJoin, s.s2);
    cudaStreamWaitEvent(0, s.evJoin, 0);

    // 5) sim = (q_pb @ k_pbs^T) / sqrt(256)
    mgemm<true, false, false, false, false><<<dim3(12, 2, 16), 128, TG_SMEM>>>(
        s.qpb, s.kpbs, s.sim, 256, 768, 256, 256, 256L * 256, 768L * 256,
        16, 256L * 768, 0, 768,
        nullptr, nullptr, nullptr, nullptr, 0, 0, nullptr, 0.0625f);

    // 6) softmax over k
    softmax_inplace<<<16 * 256, 256>>>(s.sim, 768);

    // 7) value = sim @ k_pbs (NN)
    mgemm<false, false, false, false, false><<<dim3(4, 2, 16), 128, TG_SMEM>>>(
        s.sim, s.kpbs, s.value, 256, 256, 768, 768, 256L * 768, 768L * 256,
        16, 256L * 256, 0, 256,
        nullptr, nullptr, nullptr, nullptr, 0, 0, nullptr, 1.f);

    // 8) normalize prototypes
    norm_rows256<<<16 * 256, 256>>>(s.value);

    // 9) cm_raw = proto_n @ query
    mgemm<false, false, false, false, false><<<dim3(64, 2, 16), 128, TG_SMEM>>>(
        s.value, query, s.cm, 256, 4096, 256, 256, 256L * 256, 256L * 4096,
        16, 256L * 4096, 0, 4096,
        nullptr, nullptr, nullptr, nullptr, 0, 0, nullptr, 1.f);

    // 10b) out += f_w[:, 512:] @ (cm * qcol)   (ACCUM, CONCAT path with Ksplit=0)
    mgemm<false, false, false, true, true><<<dim3(64, 4, 16), 128, TG_SMEM>>>(
        f_w + 512, s.cm, out, 512, 4096, 256, 768, 0, 256L * 4096,
        16, 512L * 4096, 0, 4096,
        nullptr, nullptr, nullptr, s.cm, 256L * 4096, 0, s.qcol, 1.f);

    // 11) BatchNorm (batch stats) + ReLU
    bn_stats<<<512, 256>>>(out, s.mean, s.istd);
    bn_apply<<<131072, 256>>>(out, s.mean, s.istd, bn_g, bn_b);
}

// round 14
// speedup vs baseline: 1.5972x; 1.1197x over previous
#include <cuda_runtime.h>
#include <cuda_bf16.h>
#include <cuda_fp16.h>
#include <cstdint>
#include <stdint.h>
#include <math.h>

// ---------------------------------------------------------------------------
// Scratch (static __device__ arrays; no allocations anywhere)
// ---------------------------------------------------------------------------
__device__ float g_kf[48u * 256u * 4096u];   // 201 MB
__device__ float g_kmax[48 * 256];
__device__ float g_kinv[48 * 256];
__device__ float g_qmax[16 * 256];
__device__ float g_qinvs[16 * 256];
__device__ float g_kpbs[16 * 768 * 256];
__device__ float g_qpb[16 * 256 * 256];
__device__ float g_sim[16 * 256 * 768];
__device__ float g_value[16 * 256 * 256];
__device__ float g_qcol[16 * 4096];
__device__ float g_cm[16u * 256u * 4096u];   // 67 MB
__device__ float g_mean[512];
__device__ float g_istd[512];

// ---------------------------------------------------------------------------
// mma.sync helpers (plain sm_80+ PTX — valid under compute_103)
// ---------------------------------------------------------------------------
__device__ __forceinline__ uint32_t smem_u32(const void* p) {
    uint32_t a;
    asm("{ .reg .u64 t; cvta.to.shared.u64 t, %1; cvt.u32.u64 %0, t; }" : "=r"(a) : "l"(p));
    return a;
}
__device__ __forceinline__ void ldmat4(uint32_t& r0, uint32_t& r1, uint32_t& r2, uint32_t& r3,
                                       uint32_t addr) {
    asm volatile("ldmatrix.sync.aligned.m8n8.x4.shared.b16 {%0,%1,%2,%3}, [%4];"
                 : "=r"(r0), "=r"(r1), "=r"(r2), "=r"(r3) : "r"(addr));
}
// fp16 MMA, fp32 accumulate
__device__ __forceinline__ void mma16816(float* d, const uint32_t* a, const uint32_t* b) {
    asm volatile(
        "mma.sync.aligned.m16n8k16.row.col.f32.f16.f16.f32 "
        "{%0,%1,%2,%3}, {%4,%5,%6,%7}, {%8,%9}, {%0,%1,%2,%3};"
        : "+f"(d[0]), "+f"(d[1]), "+f"(d[2]), "+f"(d[3])
        : "r"(a[0]), "r"(a[1]), "r"(a[2]), "r"(a[3]), "r"(b[0]), "r"(b[1]));
}

// pack two f32 into f16x2 (x -> low half, y -> high half), round-to-nearest
__device__ __forceinline__ uint32_t cvt2(float x, float y) {
    uint32_t r;
    asm("cvt.rn.f16x2.f32 %0, %1, %2;" : "=r"(r) : "f"(y), "f"(x));
    return r;
}
// residuals of a packed f16x2 vs original floats
__device__ __forceinline__ float2 resid2(uint32_t h, float x, float y) {
    __half2 hh = *reinterpret_cast<__half2*>(&h);
    float2 f = __half22float2(hh);
    return make_float2(x - f.x, y - f.y);
}
// split 8 floats (f0,f1) into hi f16x2 quad + residual f16x2 quad
__device__ __forceinline__ void split8(float4 f0, float4 f1, uint4& hi, uint4& lo) {
    hi.x = cvt2(f0.x, f0.y); hi.y = cvt2(f0.z, f0.w);
    hi.z = cvt2(f1.x, f1.y); hi.w = cvt2(f1.z, f1.w);
    float2 r0 = resid2(hi.x, f0.x, f0.y);
    float2 r1 = resid2(hi.y, f0.z, f0.w);
    float2 r2 = resid2(hi.z, f1.x, f1.y);
    float2 r3 = resid2(hi.w, f1.z, f1.w);
    lo.x = cvt2(r0.x, r0.y); lo.y = cvt2(r1.x, r1.y);
    lo.z = cvt2(r2.x, r2.y); lo.w = cvt2(r3.x, r3.y);
}

// smem geometry (per buffer): A hi/lo 128 rows, B hi 64 rows, 80 B rows.
static constexpr int ROWB    = 80;             // 32 f16 + 8 pad
static constexpr int A_PART  = 128 * ROWB;     // 10240
static constexpr int B_PART  = 64 * ROWB;      // 5120
static constexpr int OFF_A1  = 0;
static constexpr int OFF_A2  = A_PART;
static constexpr int OFF_B1  = 2 * A_PART;
static constexpr int BUFB    = 2 * A_PART + B_PART;  // 25600
static constexpr int TG_SMEM = 2 * BUFB;             // 51200

// ---------------------------------------------------------------------------
// mma.sync fp16 2-term split GEMM: C ~= alpha*(A @ B') (+bias) (+=C if ACCUM)
//   A = A1 + A2 (fp16 hi + fp16 residual); B ~= B1 (fp16 RN)
//   computes A1*B1 + A2*B1 = A*B1  (error ~2^-11, passes 1e-3 gate)
//   A: row-major [M, lda]; EXPA: fused exp(a-rmax)*rinv per row
//   TB:  B row-major [N,K] (C = A @ B^T);  !TB: B row-major [K,N]
//   CONCAT (!TB): k >= Ksplit reads B2 scaled by colscale[z*N+n]
// CTA tile 128x64, K chunks of 32; 4 warps (128 thr), warp tile 64x32.
// ---------------------------------------------------------------------------
template<bool TB, bool EXPA, bool HASBIAS, bool CONCAT, bool ACCUM>
__global__ void __launch_bounds__(128, 3) mgemm(
    const float* __restrict__ A, const float* __restrict__ B, float* __restrict__ C,
    int M, int N, int K, int lda, long sAz, long sBz,
    int modB, long sCb, long sCr, int ldc,
    const float* __restrict__ rmax, const float* __restrict__ rinv,
    const float* __restrict__ bias,
    const float* __restrict__ B2, long sB2z, int Ksplit,
    const float* __restrict__ colscale, float alpha)
{
    extern __shared__ char smem[];
    const uint32_t sb = smem_u32(smem);
    const int tid = threadIdx.x;
    const int wid = tid >> 5;
    const int lane = tid & 31;
    const int z = blockIdx.z;
    const int bm = blockIdx.y * 128;
    const int bn = blockIdx.x * 64;
    const float* Ab = A + (long)z * sAz;
    const float* Bb = B + (long)z * sBz;

    // ---- A loader: row = ar+32j (j<4), 8 consecutive k per thread ----
    const int ar = tid >> 2;
    const int ak8 = (tid & 3) * 8;
    const float* gA0 = Ab + (long)(bm + ar) * lda + ak8;

    float smx[4], siv[4];
    if (EXPA) {
        #pragma unroll
        for (int j = 0; j < 4; j++) {
            const int r = bm + ar + 32 * j;
            smx[j] = rmax[(long)z * M + r];
            siv[j] = rinv[(long)z * M + r];
        }
    }

    // ---- B loader geometry ----
    const float* gB0 = nullptr;      // TB: row = ar+32j (j<2)
    int bkp = 0, bng = 0;            // NN: k-pair, n-group (8 cols)
    float4 csc0 = make_float4(1.f, 1.f, 1.f, 1.f);
    float4 csc1 = make_float4(1.f, 1.f, 1.f, 1.f);
    if (TB) {
        gB0 = Bb + (long)(bn + ar) * K + ak8;
    } else {
        bkp = tid & 15;
        bng = tid >> 4;
        if (CONCAT) {
            csc0 = *reinterpret_cast<const float4*>(colscale + (long)z * N + bn + bng * 8);
            csc1 = *reinterpret_cast<const float4*>(colscale + (long)z * N + bn + bng * 8 + 4);
        }
    }

    const int nch = K >> 5;

    float4 fa[4][2], fb[2][2];

    auto loadA = [&](int ch) {
        const float* p = gA0 + ch * 32;
        #pragma unroll
        for (int j = 0; j < 4; j++) {
            fa[j][0] = *reinterpret_cast<const float4*>(p + (long)(32 * j) * lda);
            fa[j][1] = *reinterpret_cast<const float4*>(p + (long)(32 * j) * lda + 4);
        }
    };
    auto loadB = [&](int ch) {
        if (TB) {
            const float* p = gB0 + ch * 32;
            #pragma unroll
            for (int j = 0; j < 2; j++) {
                fb[j][0] = *reinterpret_cast<const float4*>(p + (long)(32 * j) * K);
                fb[j][1] = *reinterpret_cast<const float4*>(p + (long)(32 * j) * K + 4);
            }
        } else {
            const int kg = ch * 32 + 2 * bkp;
            const float* src;
            if (CONCAT && kg >= Ksplit)
                src = B2 + (long)z * sB2z + (long)(kg - Ksplit) * N + bn + bng * 8;
            else
                src = Bb + (long)kg * N + bn + bng * 8;
            fb[0][0] = *reinterpret_cast<const float4*>(src);
            fb[0][1] = *reinterpret_cast<const float4*>(src + 4);
            fb[1][0] = *reinterpret_cast<const float4*>(src + N);
            fb[1][1] = *reinterpret_cast<const float4*>(src + N + 4);
            if (CONCAT && kg >= Ksplit) {
                #pragma unroll
                for (int r = 0; r < 2; r++) {
                    fb[r][0].x *= csc0.x; fb[r][0].y *= csc0.y;
                    fb[r][0].z *= csc0.z; fb[r][0].w *= csc0.w;
                    fb[r][1].x *= csc1.x; fb[r][1].y *= csc1.y;
                    fb[r][1].z *= csc1.z; fb[r][1].w *= csc1.w;
                }
            }
        }
    };
    auto stashA = [&](int buf) {
        char* a1 = smem + buf * BUFB + OFF_A1;
        char* a2 = smem + buf * BUFB + OFF_A2;
        #pragma unroll
        for (int j = 0; j < 4; j++) {
            float4 f0 = fa[j][0], f1 = fa[j][1];
            if (EXPA) {
                const float m = smx[j], v = siv[j];
                f0.x = __expf(f0.x - m) * v; f0.y = __expf(f0.y - m) * v;
                f0.z = __expf(f0.z - m) * v; f0.w = __expf(f0.w - m) * v;
                f1.x = __expf(f1.x - m) * v; f1.y = __expf(f1.y - m) * v;
                f1.z = __expf(f1.z - m) * v; f1.w = __expf(f1.w - m) * v;
            }
            uint4 hi, lo;
            split8(f0, f1, hi, lo);
            const int off = (ar + 32 * j) * ROWB + (tid & 3) * 16;
            *reinterpret_cast<uint4*>(a1 + off) = hi;
            *reinterpret_cast<uint4*>(a2 + off) = lo;
        }
    };
    auto stashB = [&](int buf) {
        char* b1 = smem + buf * BUFB + OFF_B1;
        if (TB) {
            #pragma unroll
            for (int j = 0; j < 2; j++) {
                const float4 f0 = fb[j][0], f1 = fb[j][1];
                uint4 hi;
                hi.x = cvt2(f0.x, f0.y); hi.y = cvt2(f0.z, f0.w);
                hi.z = cvt2(f1.x, f1.y); hi.w = cvt2(f1.z, f1.w);
                const int off = (ar + 32 * j) * ROWB + (tid & 3) * 16;
                *reinterpret_cast<uint4*>(b1 + off) = hi;
            }
        } else {
            const float* r0 = reinterpret_cast<const float*>(&fb[0][0]);
            const float* r1 = reinterpret_cast<const float*>(&fb[1][0]);
            #pragma unroll
            for (int u = 0; u < 8; u++) {
                const uint32_t hi = cvt2(r0[u], r1[u]);   // k-pair in one word
                const int off = (bng * 8 + u) * ROWB + bkp * 4;
                *reinterpret_cast<uint32_t*>(b1 + off) = hi;
            }
        }
    };

    loadA(0); loadB(0);
    stashA(0); stashB(0);
    __syncthreads();

    float d[4][4][4];
    #pragma unroll
    for (int i = 0; i < 4; i++)
        #pragma unroll
        for (int j = 0; j < 4; j++)
            #pragma unroll
            for (int q = 0; q < 4; q++) d[i][j][q] = 0.f;

    const int wm = (wid >> 1) * 64;   // 2 m-warps
    const int wn = (wid & 1) * 32;    // 2 n-warps
    const int lr = lane & 15;
    const int lc = lane >> 4;

    for (int ch = 0; ch < nch; ch++) {
        const bool hasNext = (ch + 1 < nch);
        if (hasNext) { loadA(ch + 1); loadB(ch + 1); }

        const uint32_t base = sb + (ch & 1) * BUFB;
        #pragma unroll
        for (int ks = 0; ks < 2; ks++) {
            const uint32_t koff = ks * 32 + lc * 16;
            uint32_t ah[4][4], bh[4][2];
            #pragma unroll
            for (int mt = 0; mt < 4; mt++)
                ldmat4(ah[mt][0], ah[mt][1], ah[mt][2], ah[mt][3],
                       base + OFF_A1 + (wm + mt * 16 + lr) * ROWB + koff);
            #pragma unroll
            for (int bt = 0; bt < 2; bt++) {
                uint32_t r0, r1, r2, r3;
                ldmat4(r0, r1, r2, r3, base + OFF_B1 + (wn + bt * 16 + lr) * ROWB + koff);
                bh[2 * bt][0] = r0; bh[2 * bt][1] = r2;
                bh[2 * bt + 1][0] = r1; bh[2 * bt + 1][1] = r3;
            }
            // pass 1: A_hi * B
            #pragma unroll
            for (int mt = 0; mt < 4; mt++)
                #pragma unroll
                for (int nt = 0; nt < 4; nt++) mma16816(d[mt][nt], ah[mt], bh[nt]);
            // pass 2: A_residual * B (per-mt to cap register liveness)
            #pragma unroll
            for (int mt = 0; mt < 4; mt++) {
                uint32_t al[4];
                ldmat4(al[0], al[1], al[2], al[3],
                       base + OFF_A2 + (wm + mt * 16 + lr) * ROWB + koff);
                #pragma unroll
                for (int nt = 0; nt < 4; nt++) mma16816(d[mt][nt], al, bh[nt]);
            }
        }
        if (hasNext) { stashA((ch + 1) & 1); stashB((ch + 1) & 1); }
        __syncthreads();
    }

    // epilogue
    const long coff = (long)(z % modB) * sCb + (long)(z / modB) * sCr;
    #pragma unroll
    for (int mt = 0; mt < 4; mt++) {
        const int r0 = bm + wm + mt * 16 + (lane >> 2);
        const float bi0 = HASBIAS ? bias[r0] : 0.f;
        const float bi8 = HASBIAS ? bias[r0 + 8] : 0.f;
        #pragma unroll
        for (int nt = 0; nt < 4; nt++) {
            const int c0 = bn + wn + nt * 8 + (lane & 3) * 2;
            float* p0 = C + coff + (long)r0 * ldc + c0;
            float* p1 = C + coff + (long)(r0 + 8) * ldc + c0;
            float v0 = d[mt][nt][0] * alpha + bi0;
            float v1 = d[mt][nt][1] * alpha + bi0;
            float v2 = d[mt][nt][2] * alpha + bi8;
            float v3 = d[mt][nt][3] * alpha + bi8;
            if (ACCUM) {
                const float2 o0 = *reinterpret_cast<float2*>(p0);
                const float2 o1 = *reinterpret_cast<float2*>(p1);
                v0 += o0.x; v1 += o0.y; v2 += o1.x; v3 += o1.y;
            }
            *reinterpret_cast<float2*>(p0) = make_float2(v0, v1);
            *reinterpret_cast<float2*>(p1) = make_float2(v2, v3);
        }
    }
}

// ---------------------------------------------------------------------------
// Reductions / elementwise helpers
// ---------------------------------------------------------------------------
__device__ __forceinline__ float blockReduce(float v, bool ismax) {
    __shared__ float sh[32];
    __syncthreads();
    int lane = threadIdx.x & 31, wid = threadIdx.x >> 5;
    #pragma unroll
    for (int o = 16; o; o >>= 1) {
        float t = __shfl_xor_sync(0xffffffffu, v, o);
        v = ismax ? fmaxf(v, t) : (v + t);
    }
    if (lane == 0) sh[wid] = v;
    __syncthreads();
    int nw = (blockDim.x + 31) >> 5;
    if (wid == 0) {
        v = (lane < nw) ? sh[lane] : (ismax ? -1e30f : 0.f);
        #pragma unroll
        for (int o = 16; o; o >>= 1) {
            float t = __shfl_xor_sync(0xffffffffu, v, o);
            v = ismax ? fmaxf(v, t) : (v + t);
        }
        if (lane == 0) sh[0] = v;
    }
    __syncthreads();
    return sh[0];
}

// Row stats for rows of exactly 4096 floats: single DRAM pass, row cached in regs
__global__ void row_stats4k(const float* __restrict__ X, float* __restrict__ omax,
                            float* __restrict__ oinv)
{
    const long row = blockIdx.x;
    const float4* x = reinterpret_cast<const float4*>(X + row * 4096);
    float4 v[4];
    float m = -1e30f;
    #pragma unroll
    for (int j = 0; j < 4; j++) {
        v[j] = x[threadIdx.x + 256 * j];
        m = fmaxf(m, fmaxf(fmaxf(v[j].x, v[j].y), fmaxf(v[j].z, v[j].w)));
    }
    m = blockReduce(m, true);
    float s = 0.f;
    #pragma unroll
    for (int j = 0; j < 4; j++)
        s += __expf(v[j].x - m) + __expf(v[j].y - m) + __expf(v[j].z - m) + __expf(v[j].w - m);
    s = blockReduce(s, false);
    if (threadIdx.x == 0) { omax[row] = m; oinv[row] = 1.f / s; }
}

__global__ void softmax_inplace(float* __restrict__ X, int len)
{
    const long row = blockIdx.x;
    float* x = X + row * len;
    float m = -1e30f;
    for (int i = threadIdx.x; i < len; i += blockDim.x) m = fmaxf(m, x[i]);
    m = blockReduce(m, true);
    float s = 0.f;
    for (int i = threadIdx.x; i < len; i += blockDim.x) s += __expf(x[i] - m);
    s = blockReduce(s, false);
    const float inv = 1.f / s;
    for (int i = threadIdx.x; i < len; i += blockDim.x) x[i] = __expf(x[i] - m) * inv;
}

__global__ void norm_rows256(float* __restrict__ V)
{
    const long row = blockIdx.x;
    float* v = V + row * 256;
    const float x = v[threadIdx.x];
    const float s = blockReduce(x * x, false);
    v[threadIdx.x] = x * rsqrtf(s);
}

__global__ void qcol_norm(const float* __restrict__ q, float* __restrict__ out)
{
    const int b = blockIdx.y;
    const int n = blockIdx.x * 256 + threadIdx.x;
    const float* p = q + (long)b * 256 * 4096 + n;
    float s = 0.f;
    #pragma unroll 8
    for (int c = 0; c < 256; c++) { float v = p[(long)c * 4096]; s += v * v; }
    out[b * 4096 + n] = rsqrtf(s);
}

__global__ void bn_stats(const float* __restrict__ y, float* __restrict__ mean,
                         float* __restrict__ istd)
{
    const int o = blockIdx.x;
    float s = 0.f, s2 = 0.f;
    for (int b = 0; b < 16; b++) {
        const float* p = y + ((long)b * 512 + o) * 4096;
        for (int i = threadIdx.x; i < 4096; i += 256) {
            float v = p[i]; s += v; s2 += v * v;
        }
    }
    s = blockReduce(s, false);
    s2 = blockReduce(s2, false);
    if (threadIdx.x == 0) {
        float mu = s * (1.f / 65536.f);
        mean[o] = mu;
        istd[o] = 1.f / sqrtf(s2 * (1.f / 65536.f) - mu * mu + 1e-5f);
    }
}

__global__ void bn_apply(float* __restrict__ y, const float* __restrict__ mean,
                         const float* __restrict__ istd, const float* __restrict__ g,
                         const float* __restrict__ b)
{
    const long i = (long)blockIdx.x * 256 + threadIdx.x;
    const int o = (int)((i >> 12) & 511);
    float v = (y[i] - mean[o]) * istd[o] * g[o] + b[o];
    y[i] = v > 0.f ? v : 0.f;
}

// ---------------------------------------------------------------------------
// Host orchestration
// ---------------------------------------------------------------------------
struct Scratch {
    float *kf, *kmax, *kinv, *qmax, *qinvs, *kpbs, *qpb, *sim, *value, *qcol, *cm, *mean, *istd;
    cudaStream_t s2;
    cudaEvent_t evFork, evJoin;
};

static Scratch fetch_scratch() {
    Scratch s;
    cudaGetSymbolAddress((void**)&s.kf,    g_kf);
    cudaGetSymbolAddress((void**)&s.kmax,  g_kmax);
    cudaGetSymbolAddress((void**)&s.kinv,  g_kinv);
    cudaGetSymbolAddress((void**)&s.qmax,  g_qmax);
    cudaGetSymbolAddress((void**)&s.qinvs, g_qinvs);
    cudaGetSymbolAddress((void**)&s.kpbs,  g_kpbs);
    cudaGetSymbolAddress((void**)&s.qpb,   g_qpb);
    cudaGetSymbolAddress((void**)&s.sim,   g_sim);
    cudaGetSymbolAddress((void**)&s.value, g_value);
    cudaGetSymbolAddress((void**)&s.qcol,  g_qcol);
    cudaGetSymbolAddress((void**)&s.cm,    g_cm);
    cudaGetSymbolAddress((void**)&s.mean,  g_mean);
    cudaGetSymbolAddress((void**)&s.istd,  g_istd);
    cudaStreamCreateWithFlags(&s.s2, cudaStreamNonBlocking);
    cudaEventCreateWithFlags(&s.evFork, cudaEventDisableTiming);
    cudaEventCreateWithFlags(&s.evJoin, cudaEventDisableTiming);
    cudaFuncSetAttribute(mgemm<false, false, true,  false, false>, cudaFuncAttributeMaxDynamicSharedMemorySize, TG_SMEM);
    cudaFuncSetAttribute(mgemm<true,  true,  false, false, false>, cudaFuncAttributeMaxDynamicSharedMemorySize, TG_SMEM);
    cudaFuncSetAttribute(mgemm<true,  false, false, false, false>, cudaFuncAttributeMaxDynamicSharedMemorySize, TG_SMEM);
    cudaFuncSetAttribute(mgemm<false, false, false, false, false>, cudaFuncAttributeMaxDynamicSharedMemorySize, TG_SMEM);
    cudaFuncSetAttribute(mgemm<false, false, false, true,  true >, cudaFuncAttributeMaxDynamicSharedMemorySize, TG_SMEM);
    return s;
}

extern "C" void kernel_launch(void* const* d_in, const int* in_sizes, int n_in,
                              void* d_out, int out_size)
{
    (void)in_sizes; (void)n_in; (void)out_size;
    static Scratch s = fetch_scratch();  // first call is the non-captured correctness run

    const float* x     = (const float*)d_in[0];
    const float* query = (const float*)d_in[1];
    const float* refs  = (const float*)d_in[2];
    const float* K_w   = (const float*)d_in[3];
    const float* K_b   = (const float*)d_in[4];
    // d_in[5], d_in[6] = V_w, V_b : dead code in the reference.
    const float* f_w   = (const float*)d_in[7];
    const float* f_b   = (const float*)d_in[8];
    const float* bn_g  = (const float*)d_in[9];
    const float* bn_b  = (const float*)d_in[10];
    float* out = (float*)d_out;

    // ---- fork: independent work on s2 ----
    cudaEventRecord(s.evFork, 0);
    cudaStreamWaitEvent(s.s2, s.evFork, 0);

    // s2: query branch (stats, q_pb, qcol), then stage 10a (x-part of final conv)
    row_stats4k<<<16 * 256, 256, 0, s.s2>>>(query, s.qmax, s.qinvs);
    mgemm<true, true, false, false, false><<<dim3(4, 2, 16), 128, TG_SMEM, s.s2>>>(
        query, query, s.qpb, 256, 256, 4096, 4096, 256L * 4096, 256L * 4096,
        16, 256L * 256, 0, 256,
        s.qmax, s.qinvs, nullptr, nullptr, 0, 0, nullptr, 1.f);
    qcol_norm<<<dim3(16, 16), 256, 0, s.s2>>>(query, s.qcol);
    // 10a) out = f_w[:, :512] @ x + f_b   (no deps; overlaps kf chain)
    mgemm<false, false, true, false, false><<<dim3(64, 4, 16), 128, TG_SMEM, s.s2>>>(
        f_w, x, out, 512, 4096, 512, 768, 0, 512L * 4096,
        16, 512L * 4096, 0, 4096,
        nullptr, nullptr, f_b, nullptr, 0, 0, nullptr, 1.f);

    // main: kf chain
    // 1) kf[z] = K_w @ refs[z] + K_b
    mgemm<false, false, true, false, false><<<dim3(64, 2, 48), 128, TG_SMEM>>>(
        K_w, refs, s.kf, 256, 4096, 512, 512, 0, 512L * 4096,
        48, 256L * 4096, 0, 4096,
        nullptr, nullptr, K_b, nullptr, 0, 0, nullptr, 1.f);

    // 2) kf softmax row stats
    row_stats4k<<<48 * 256, 256>>>(s.kf, s.kmax, s.kinv);

    // 3) k_pb[z] = softmax(kf[z]) @ kf[z]^T
    mgemm<true, true, false, false, false><<<dim3(4, 2, 48), 128, TG_SMEM>>>(
        s.kf, s.kf, s.kpbs, 256, 256, 4096, 4096, 256L * 4096, 256L * 4096,
        16, 768L * 256, 256L * 256, 256,
        s.kmax, s.kinv, nullptr, nullptr, 0, 0, nullptr, 1.f);

    // ---- join s2 (q_pb + out ready) before stage 5 ----
    cudaEventRecord(s.evJoin, s.s2);
    cudaStreamWaitEvent(0, s.evJoin, 0);

    // 5) sim = (q_pb @ k_pbs^T) / sqrt(256)
    mgemm<true, false, false, false, false><<<dim3(12, 2, 16), 128, TG_SMEM>>>(
        s.qpb, s.kpbs, s.sim, 256, 768, 256, 256, 256L * 256, 768L * 256,
        16, 256L * 768, 0, 768,
        nullptr, nullptr, nullptr, nullptr, 0, 0, nullptr, 0.0625f);

    // 6) softmax over k
    softmax_inplace<<<16 * 256, 256>>>(s.sim, 768);

    // 7) value = sim @ k_pbs (NN)
    mgemm<false, false, false, false, false><<<dim3(4, 2, 16), 128, TG_SMEM>>>(
        s.sim, s.kpbs, s.value, 256, 256, 768, 768, 256L * 768, 768L * 256,
        16, 256L * 256, 0, 256,
        nullptr, nullptr, nullptr, nullptr, 0, 0, nullptr, 1.f);

    // 8) normalize prototypes
    norm_rows256<<<16 * 256, 256>>>(s.value);

    // 9) cm_raw = proto_n @ query
    mgemm<false, false, false, false, false><<<dim3(64, 2, 16), 128, TG_SMEM>>>(
        s.value, query, s.cm, 256, 4096, 256, 256, 256L * 256, 256L * 4096,
        16, 256L * 4096, 0, 4096,
        nullptr, nullptr, nullptr, nullptr, 0, 0, nullptr, 1.f);

    // 10b) out += f_w[:, 512:] @ (cm * qcol)   (ACCUM, CONCAT path with Ksplit=0)
    mgemm<false, false, false, true, true><<<dim3(64, 4, 16), 128, TG_SMEM>>>(
        f_w + 512, s.cm, out, 512, 4096, 256, 768, 0, 256L * 4096,
        16, 512L * 4096, 0, 4096,
        nullptr, nullptr, nullptr, s.cm, 256L * 4096, 0, s.qcol, 1.f);

    // 11) BatchNorm (batch stats) + ReLU
    bn_stats<<<512, 256>>>(out, s.mean, s.istd);
    bn_apply<<<131072, 256>>>(out, s.mean, s.istd, bn_g, bn_b);
}

// round 15
// speedup vs baseline: 1.9294x; 1.2080x over previous
#include <cuda_runtime.h>
#include <cuda_bf16.h>
#include <cuda_fp16.h>
#include <cstdint>
#include <stdint.h>
#include <math.h>

// ---------------------------------------------------------------------------
// Scratch (static __device__ arrays; no allocations anywhere)
// ---------------------------------------------------------------------------
__device__ float g_kf[48u * 256u * 4096u];   // 201 MB
__device__ float g_kmax[48 * 256];
__device__ float g_kinv[48 * 256];
__device__ float g_qmax[16 * 256];
__device__ float g_qinvs[16 * 256];
__device__ float g_kpbs[16 * 768 * 256];
__device__ float g_qpb[16 * 256 * 256];
__device__ float g_sim[16 * 256 * 768];
__device__ float g_value[16 * 256 * 256];
__device__ float g_qcol[16 * 4096];
__device__ float g_cm[16u * 256u * 4096u];   // 67 MB
__device__ float g_mean[512];
__device__ float g_istd[512];

// ---------------------------------------------------------------------------
// mma.sync helpers (plain sm_80+ PTX — valid under compute_103)
// ---------------------------------------------------------------------------
__device__ __forceinline__ uint32_t smem_u32(const void* p) {
    uint32_t a;
    asm("{ .reg .u64 t; cvta.to.shared.u64 t, %1; cvt.u32.u64 %0, t; }" : "=r"(a) : "l"(p));
    return a;
}
__device__ __forceinline__ void ldmat4(uint32_t& r0, uint32_t& r1, uint32_t& r2, uint32_t& r3,
                                       uint32_t addr) {
    asm volatile("ldmatrix.sync.aligned.m8n8.x4.shared.b16 {%0,%1,%2,%3}, [%4];"
                 : "=r"(r0), "=r"(r1), "=r"(r2), "=r"(r3) : "r"(addr));
}
// fp16 MMA, fp32 accumulate
__device__ __forceinline__ void mma16816(float* d, const uint32_t* a, const uint32_t* b) {
    asm volatile(
        "mma.sync.aligned.m16n8k16.row.col.f32.f16.f16.f32 "
        "{%0,%1,%2,%3}, {%4,%5,%6,%7}, {%8,%9}, {%0,%1,%2,%3};"
        : "+f"(d[0]), "+f"(d[1]), "+f"(d[2]), "+f"(d[3])
        : "r"(a[0]), "r"(a[1]), "r"(a[2]), "r"(a[3]), "r"(b[0]), "r"(b[1]));
}

// pack two f32 into f16x2 (x -> low half, y -> high half), round-to-nearest
__device__ __forceinline__ uint32_t cvt2(float x, float y) {
    uint32_t r;
    asm("cvt.rn.f16x2.f32 %0, %1, %2;" : "=r"(r) : "f"(y), "f"(x));
    return r;
}

// smem geometry (per buffer): A 128 rows, B 64 rows, 80 B rows.
static constexpr int ROWB    = 80;             // 32 f16 + 8 pad
static constexpr int A_PART  = 128 * ROWB;     // 10240
static constexpr int B_PART  = 64 * ROWB;      // 5120
static constexpr int OFF_A1  = 0;
static constexpr int OFF_B1  = A_PART;
static constexpr int BUFB    = A_PART + B_PART;   // 15360
static constexpr int TG_SMEM = 2 * BUFB;          // 30720

// ---------------------------------------------------------------------------
// Pure fp16 mma.sync GEMM: C ~= alpha*(A @ B') (+bias) (+=C if ACCUM)
//   A, B rounded RN to fp16 in the loader; fp32 accumulate.
//   (error ~2^-11 relative per operand; measured chain ~3e-4, gate is 1e-3)
//   A: row-major [M, lda]; EXPA: fused exp(a-rmax)*rinv per row
//   TB:  B row-major [N,K] (C = A @ B^T);  !TB: B row-major [K,N]
//   CONCAT (!TB): k >= Ksplit reads B2 scaled by colscale[z*N+n]
// CTA tile 128x64, K chunks of 32; 4 warps (128 thr), warp tile 64x32.
// ---------------------------------------------------------------------------
template<bool TB, bool EXPA, bool HASBIAS, bool CONCAT, bool ACCUM>
__global__ void __launch_bounds__(128, 3) mgemm(
    const float* __restrict__ A, const float* __restrict__ B, float* __restrict__ C,
    int M, int N, int K, int lda, long sAz, long sBz,
    int modB, long sCb, long sCr, int ldc,
    const float* __restrict__ rmax, const float* __restrict__ rinv,
    const float* __restrict__ bias,
    const float* __restrict__ B2, long sB2z, int Ksplit,
    const float* __restrict__ colscale, float alpha)
{
    extern __shared__ char smem[];
    const uint32_t sb = smem_u32(smem);
    const int tid = threadIdx.x;
    const int wid = tid >> 5;
    const int lane = tid & 31;
    const int z = blockIdx.z;
    const int bm = blockIdx.y * 128;
    const int bn = blockIdx.x * 64;
    const float* Ab = A + (long)z * sAz;
    const float* Bb = B + (long)z * sBz;

    // ---- A loader: row = ar+32j (j<4), 8 consecutive k per thread ----
    const int ar = tid >> 2;
    const int ak8 = (tid & 3) * 8;
    const float* gA0 = Ab + (long)(bm + ar) * lda + ak8;

    float smx[4], siv[4];
    if (EXPA) {
        #pragma unroll
        for (int j = 0; j < 4; j++) {
            const int r = bm + ar + 32 * j;
            smx[j] = rmax[(long)z * M + r];
            siv[j] = rinv[(long)z * M + r];
        }
    }

    // ---- B loader geometry ----
    const float* gB0 = nullptr;      // TB: row = ar+32j (j<2)
    int bkp = 0, bng = 0;            // NN: k-pair, n-group (8 cols)
    float4 csc0 = make_float4(1.f, 1.f, 1.f, 1.f);
    float4 csc1 = make_float4(1.f, 1.f, 1.f, 1.f);
    if (TB) {
        gB0 = Bb + (long)(bn + ar) * K + ak8;
    } else {
        bkp = tid & 15;
        bng = tid >> 4;
        if (CONCAT) {
            csc0 = *reinterpret_cast<const float4*>(colscale + (long)z * N + bn + bng * 8);
            csc1 = *reinterpret_cast<const float4*>(colscale + (long)z * N + bn + bng * 8 + 4);
        }
    }

    const int nch = K >> 5;

    float4 fa[4][2], fb[2][2];

    auto loadA = [&](int ch) {
        const float* p = gA0 + ch * 32;
        #pragma unroll
        for (int j = 0; j < 4; j++) {
            fa[j][0] = *reinterpret_cast<const float4*>(p + (long)(32 * j) * lda);
            fa[j][1] = *reinterpret_cast<const float4*>(p + (long)(32 * j) * lda + 4);
        }
    };
    auto loadB = [&](int ch) {
        if (TB) {
            const float* p = gB0 + ch * 32;
            #pragma unroll
            for (int j = 0; j < 2; j++) {
                fb[j][0] = *reinterpret_cast<const float4*>(p + (long)(32 * j) * K);
                fb[j][1] = *reinterpret_cast<const float4*>(p + (long)(32 * j) * K + 4);
            }
        } else {
            const int kg = ch * 32 + 2 * bkp;
            const float* src;
            if (CONCAT && kg >= Ksplit)
                src = B2 + (long)z * sB2z + (long)(kg - Ksplit) * N + bn + bng * 8;
            else
                src = Bb + (long)kg * N + bn + bng * 8;
            fb[0][0] = *reinterpret_cast<const float4*>(src);
            fb[0][1] = *reinterpret_cast<const float4*>(src + 4);
            fb[1][0] = *reinterpret_cast<const float4*>(src + N);
            fb[1][1] = *reinterpret_cast<const float4*>(src + N + 4);
            if (CONCAT && kg >= Ksplit) {
                #pragma unroll
                for (int r = 0; r < 2; r++) {
                    fb[r][0].x *= csc0.x; fb[r][0].y *= csc0.y;
                    fb[r][0].z *= csc0.z; fb[r][0].w *= csc0.w;
                    fb[r][1].x *= csc1.x; fb[r][1].y *= csc1.y;
                    fb[r][1].z *= csc1.z; fb[r][1].w *= csc1.w;
                }
            }
        }
    };
    auto stashA = [&](int buf) {
        char* a1 = smem + buf * BUFB + OFF_A1;
        #pragma unroll
        for (int j = 0; j < 4; j++) {
            float4 f0 = fa[j][0], f1 = fa[j][1];
            if (EXPA) {
                const float m = smx[j], v = siv[j];
                f0.x = __expf(f0.x - m) * v; f0.y = __expf(f0.y - m) * v;
                f0.z = __expf(f0.z - m) * v; f0.w = __expf(f0.w - m) * v;
                f1.x = __expf(f1.x - m) * v; f1.y = __expf(f1.y - m) * v;
                f1.z = __expf(f1.z - m) * v; f1.w = __expf(f1.w - m) * v;
            }
            uint4 hi;
            hi.x = cvt2(f0.x, f0.y); hi.y = cvt2(f0.z, f0.w);
            hi.z = cvt2(f1.x, f1.y); hi.w = cvt2(f1.z, f1.w);
            const int off = (ar + 32 * j) * ROWB + (tid & 3) * 16;
            *reinterpret_cast<uint4*>(a1 + off) = hi;
        }
    };
    auto stashB = [&](int buf) {
        char* b1 = smem + buf * BUFB + OFF_B1;
        if (TB) {
            #pragma unroll
            for (int j = 0; j < 2; j++) {
                const float4 f0 = fb[j][0], f1 = fb[j][1];
                uint4 hi;
                hi.x = cvt2(f0.x, f0.y); hi.y = cvt2(f0.z, f0.w);
                hi.z = cvt2(f1.x, f1.y); hi.w = cvt2(f1.z, f1.w);
                const int off = (ar + 32 * j) * ROWB + (tid & 3) * 16;
                *reinterpret_cast<uint4*>(b1 + off) = hi;
            }
        } else {
            const float* r0 = reinterpret_cast<const float*>(&fb[0][0]);
            const float* r1 = reinterpret_cast<const float*>(&fb[1][0]);
            #pragma unroll
            for (int u = 0; u < 8; u++) {
                const uint32_t hi = cvt2(r0[u], r1[u]);   // k-pair in one word
                const int off = (bng * 8 + u) * ROWB + bkp * 4;
                *reinterpret_cast<uint32_t*>(b1 + off) = hi;
            }
        }
    };

    loadA(0); loadB(0);
    stashA(0); stashB(0);
    __syncthreads();

    float d[4][4][4];
    #pragma unroll
    for (int i = 0; i < 4; i++)
        #pragma unroll
        for (int j = 0; j < 4; j++)
            #pragma unroll
            for (int q = 0; q < 4; q++) d[i][j][q] = 0.f;

    const int wm = (wid >> 1) * 64;   // 2 m-warps
    const int wn = (wid & 1) * 32;    // 2 n-warps
    const int lr = lane & 15;
    const int lc = lane >> 4;

    for (int ch = 0; ch < nch; ch++) {
        const bool hasNext = (ch + 1 < nch);
        if (hasNext) { loadA(ch + 1); loadB(ch + 1); }

        const uint32_t base = sb + (ch & 1) * BUFB;
        #pragma unroll
        for (int ks = 0; ks < 2; ks++) {
            const uint32_t koff = ks * 32 + lc * 16;
            uint32_t ah[4][4], bh[4][2];
            #pragma unroll
            for (int mt = 0; mt < 4; mt++)
                ldmat4(ah[mt][0], ah[mt][1], ah[mt][2], ah[mt][3],
                       base + OFF_A1 + (wm + mt * 16 + lr) * ROWB + koff);
            #pragma unroll
            for (int bt = 0; bt < 2; bt++) {
                uint32_t r0, r1, r2, r3;
                ldmat4(r0, r1, r2, r3, base + OFF_B1 + (wn + bt * 16 + lr) * ROWB + koff);
                bh[2 * bt][0] = r0; bh[2 * bt][1] = r2;
                bh[2 * bt + 1][0] = r1; bh[2 * bt + 1][1] = r3;
            }
            #pragma unroll
            for (int mt = 0; mt < 4; mt++)
                #pragma unroll
                for (int nt = 0; nt < 4; nt++) mma16816(d[mt][nt], ah[mt], bh[nt]);
        }
        if (hasNext) { stashA((ch + 1) & 1); stashB((ch + 1) & 1); }
        __syncthreads();
    }

    // epilogue
    const long coff = (long)(z % modB) * sCb + (long)(z / modB) * sCr;
    #pragma unroll
    for (int mt = 0; mt < 4; mt++) {
        const int r0 = bm + wm + mt * 16 + (lane >> 2);
        const float bi0 = HASBIAS ? bias[r0] : 0.f;
        const float bi8 = HASBIAS ? bias[r0 + 8] : 0.f;
        #pragma unroll
        for (int nt = 0; nt < 4; nt++) {
            const int c0 = bn + wn + nt * 8 + (lane & 3) * 2;
            float* p0 = C + coff + (long)r0 * ldc + c0;
            float* p1 = C + coff + (long)(r0 + 8) * ldc + c0;
            float v0 = d[mt][nt][0] * alpha + bi0;
            float v1 = d[mt][nt][1] * alpha + bi0;
            float v2 = d[mt][nt][2] * alpha + bi8;
            float v3 = d[mt][nt][3] * alpha + bi8;
            if (ACCUM) {
                const float2 o0 = *reinterpret_cast<float2*>(p0);
                const float2 o1 = *reinterpret_cast<float2*>(p1);
                v0 += o0.x; v1 += o0.y; v2 += o1.x; v3 += o1.y;
            }
            *reinterpret_cast<float2*>(p0) = make_float2(v0, v1);
            *reinterpret_cast<float2*>(p1) = make_float2(v2, v3);
        }
    }
}

// ---------------------------------------------------------------------------
// Reductions / elementwise helpers
// ---------------------------------------------------------------------------
__device__ __forceinline__ float blockReduce(float v, bool ismax) {
    __shared__ float sh[32];
    __syncthreads();
    int lane = threadIdx.x & 31, wid = threadIdx.x >> 5;
    #pragma unroll
    for (int o = 16; o; o >>= 1) {
        float t = __shfl_xor_sync(0xffffffffu, v, o);
        v = ismax ? fmaxf(v, t) : (v + t);
    }
    if (lane == 0) sh[wid] = v;
    __syncthreads();
    int nw = (blockDim.x + 31) >> 5;
    if (wid == 0) {
        v = (lane < nw) ? sh[lane] : (ismax ? -1e30f : 0.f);
        #pragma unroll
        for (int o = 16; o; o >>= 1) {
            float t = __shfl_xor_sync(0xffffffffu, v, o);
            v = ismax ? fmaxf(v, t) : (v + t);
        }
        if (lane == 0) sh[0] = v;
    }
    __syncthreads();
    return sh[0];
}

// Row stats for rows of exactly 4096 floats: single DRAM pass, row cached in regs
__global__ void row_stats4k(const float* __restrict__ X, float* __restrict__ omax,
                            float* __restrict__ oinv)
{
    const long row = blockIdx.x;
    const float4* x = reinterpret_cast<const float4*>(X + row * 4096);
    float4 v[4];
    float m = -1e30f;
    #pragma unroll
    for (int j = 0; j < 4; j++) {
        v[j] = x[threadIdx.x + 256 * j];
        m = fmaxf(m, fmaxf(fmaxf(v[j].x, v[j].y), fmaxf(v[j].z, v[j].w)));
    }
    m = blockReduce(m, true);
    float s = 0.f;
    #pragma unroll
    for (int j = 0; j < 4; j++)
        s += __expf(v[j].x - m) + __expf(v[j].y - m) + __expf(v[j].z - m) + __expf(v[j].w - m);
    s = blockReduce(s, false);
    if (threadIdx.x == 0) { omax[row] = m; oinv[row] = 1.f / s; }
}

__global__ void softmax_inplace(float* __restrict__ X, int len)
{
    const long row = blockIdx.x;
    float* x = X + row * len;
    float m = -1e30f;
    for (int i = threadIdx.x; i < len; i += blockDim.x) m = fmaxf(m, x[i]);
    m = blockReduce(m, true);
    float s = 0.f;
    for (int i = threadIdx.x; i < len; i += blockDim.x) s += __expf(x[i] - m);
    s = blockReduce(s, false);
    const float inv = 1.f / s;
    for (int i = threadIdx.x; i < len; i += blockDim.x) x[i] = __expf(x[i] - m) * inv;
}

__global__ void norm_rows256(float* __restrict__ V)
{
    const long row = blockIdx.x;
    float* v = V + row * 256;
    const float x = v[threadIdx.x];
    const float s = blockReduce(x * x, false);
    v[threadIdx.x] = x * rsqrtf(s);
}

__global__ void qcol_norm(const float* __restrict__ q, float* __restrict__ out)
{
    const int b = blockIdx.y;
    const int n = blockIdx.x * 256 + threadIdx.x;
    const float* p = q + (long)b * 256 * 4096 + n;
    float s = 0.f;
    #pragma unroll 8
    for (int c = 0; c < 256; c++) { float v = p[(long)c * 4096]; s += v * v; }
    out[b * 4096 + n] = rsqrtf(s);
}

__global__ void bn_stats(const float* __restrict__ y, float* __restrict__ mean,
                         float* __restrict__ istd)
{
    const int o = blockIdx.x;
    float s = 0.f, s2 = 0.f;
    for (int b = 0; b < 16; b++) {
        const float* p = y + ((long)b * 512 + o) * 4096;
        for (int i = threadIdx.x; i < 4096; i += 256) {
            float v = p[i]; s += v; s2 += v * v;
        }
    }
    s = blockReduce(s, false);
    s2 = blockReduce(s2, false);
    if (threadIdx.x == 0) {
        float mu = s * (1.f / 65536.f);
        mean[o] = mu;
        istd[o] = 1.f / sqrtf(s2 * (1.f / 65536.f) - mu * mu + 1e-5f);
    }
}

__global__ void bn_apply(float* __restrict__ y, const float* __restrict__ mean,
                         const float* __restrict__ istd, const float* __restrict__ g,
                         const float* __restrict__ b)
{
    const long i = (long)blockIdx.x * 256 + threadIdx.x;
    const int o = (int)((i >> 12) & 511);
    float v = (y[i] - mean[o]) * istd[o] * g[o] + b[o];
    y[i] = v > 0.f ? v : 0.f;
}

// ---------------------------------------------------------------------------
// Host orchestration
// ---------------------------------------------------------------------------
struct Scratch {
    float *kf, *kmax, *kinv, *qmax, *qinvs, *kpbs, *qpb, *sim, *value, *qcol, *cm, *mean, *istd;
    cudaStream_t s2;
    cudaEvent_t evFork, evJoin;
};

static Scratch fetch_scratch() {
    Scratch s;
    cudaGetSymbolAddress((void**)&s.kf,    g_kf);
    cudaGetSymbolAddress((void**)&s.kmax,  g_kmax);
    cudaGetSymbolAddress((void**)&s.kinv,  g_kinv);
    cudaGetSymbolAddress((void**)&s.qmax,  g_qmax);
    cudaGetSymbolAddress((void**)&s.qinvs, g_qinvs);
    cudaGetSymbolAddress((void**)&s.kpbs,  g_kpbs);
    cudaGetSymbolAddress((void**)&s.qpb,   g_qpb);
    cudaGetSymbolAddress((void**)&s.sim,   g_sim);
    cudaGetSymbolAddress((void**)&s.value, g_value);
    cudaGetSymbolAddress((void**)&s.qcol,  g_qcol);
    cudaGetSymbolAddress((void**)&s.cm,    g_cm);
    cudaGetSymbolAddress((void**)&s.mean,  g_mean);
    cudaGetSymbolAddress((void**)&s.istd,  g_istd);
    cudaStreamCreateWithFlags(&s.s2, cudaStreamNonBlocking);
    cudaEventCreateWithFlags(&s.evFork, cudaEventDisableTiming);
    cudaEventCreateWithFlags(&s.evJoin, cudaEventDisableTiming);
    cudaFuncSetAttribute(mgemm<false, false, true,  false, false>, cudaFuncAttributeMaxDynamicSharedMemorySize, TG_SMEM);
    cudaFuncSetAttribute(mgemm<true,  true,  false, false, false>, cudaFuncAttributeMaxDynamicSharedMemorySize, TG_SMEM);
    cudaFuncSetAttribute(mgemm<true,  false, false, false, false>, cudaFuncAttributeMaxDynamicSharedMemorySize, TG_SMEM);
    cudaFuncSetAttribute(mgemm<false, false, false, false, false>, cudaFuncAttributeMaxDynamicSharedMemorySize, TG_SMEM);
    cudaFuncSetAttribute(mgemm<false, false, false, true,  true >, cudaFuncAttributeMaxDynamicSharedMemorySize, TG_SMEM);
    return s;
}

extern "C" void kernel_launch(void* const* d_in, const int* in_sizes, int n_in,
                              void* d_out, int out_size)
{
    (void)in_sizes; (void)n_in; (void)out_size;
    static Scratch s = fetch_scratch();  // first call is the non-captured correctness run

    const float* x     = (const float*)d_in[0];
    const float* query = (const float*)d_in[1];
    const float* refs  = (const float*)d_in[2];
    const float* K_w   = (const float*)d_in[3];
    const float* K_b   = (const float*)d_in[4];
    // d_in[5], d_in[6] = V_w, V_b : dead code in the reference.
    const float* f_w   = (const float*)d_in[7];
    const float* f_b   = (const float*)d_in[8];
    const float* bn_g  = (const float*)d_in[9];
    const float* bn_b  = (const float*)d_in[10];
    float* out = (float*)d_out;

    // ---- fork: independent work on s2 ----
    cudaEventRecord(s.evFork, 0);
    cudaStreamWaitEvent(s.s2, s.evFork, 0);

    // s2: query branch (stats, q_pb, qcol), then stage 10a (x-part of final conv)
    row_stats4k<<<16 * 256, 256, 0, s.s2>>>(query, s.qmax, s.qinvs);
    mgemm<true, true, false, false, false><<<dim3(4, 2, 16), 128, TG_SMEM, s.s2>>>(
        query, query, s.qpb, 256, 256, 4096, 4096, 256L * 4096, 256L * 4096,
        16, 256L * 256, 0, 256,
        s.qmax, s.qinvs, nullptr, nullptr, 0, 0, nullptr, 1.f);
    qcol_norm<<<dim3(16, 16), 256, 0, s.s2>>>(query, s.qcol);
    // 10a) out = f_w[:, :512] @ x + f_b   (no deps; overlaps kf chain)
    mgemm<false, false, true, false, false><<<dim3(64, 4, 16), 128, TG_SMEM, s.s2>>>(
        f_w, x, out, 512, 4096, 512, 768, 0, 512L * 4096,
        16, 512L * 4096, 0, 4096,
        nullptr, nullptr, f_b, nullptr, 0, 0, nullptr, 1.f);

    // main: kf chain
    // 1) kf[z] = K_w @ refs[z] + K_b
    mgemm<false, false, true, false, false><<<dim3(64, 2, 48), 128, TG_SMEM>>>(
        K_w, refs, s.kf, 256, 4096, 512, 512, 0, 512L * 4096,
        48, 256L * 4096, 0, 4096,
        nullptr, nullptr, K_b, nullptr, 0, 0, nullptr, 1.f);

    // 2) kf softmax row stats
    row_stats4k<<<48 * 256, 256>>>(s.kf, s.kmax, s.kinv);

    // 3) k_pb[z] = softmax(kf[z]) @ kf[z]^T
    mgemm<true, true, false, false, false><<<dim3(4, 2, 48), 128, TG_SMEM>>>(
        s.kf, s.kf, s.kpbs, 256, 256, 4096, 4096, 256L * 4096, 256L * 4096,
        16, 768L * 256, 256L * 256, 256,
        s.kmax, s.kinv, nullptr, nullptr, 0, 0, nullptr, 1.f);

    // ---- join s2 (q_pb + out ready) before stage 5 ----
    cudaEventRecord(s.evJoin, s.s2);
    cudaStreamWaitEvent(0, s.evJoin, 0);

    // 5) sim = (q_pb @ k_pbs^T) / sqrt(256)
    mgemm<true, false, false, false, false><<<dim3(12, 2, 16), 128, TG_SMEM>>>(
        s.qpb, s.kpbs, s.sim, 256, 768, 256, 256, 256L * 256, 768L * 256,
        16, 256L * 768, 0, 768,
        nullptr, nullptr, nullptr, nullptr, 0, 0, nullptr, 0.0625f);

    // 6) softmax over k
    softmax_inplace<<<16 * 256, 256>>>(s.sim, 768);

    // 7) value = sim @ k_pbs (NN)
    mgemm<false, false, false, false, false><<<dim3(4, 2, 16), 128, TG_SMEM>>>(
        s.sim, s.kpbs, s.value, 256, 256, 768, 768, 256L * 768, 768L * 256,
        16, 256L * 256, 0, 256,
        nullptr, nullptr, nullptr, nullptr, 0, 0, nullptr, 1.f);

    // 8) normalize prototypes
    norm_rows256<<<16 * 256, 256>>>(s.value);

    // 9) cm_raw = proto_n @ query
    mgemm<false, false, false, false, false><<<dim3(64, 2, 16), 128, TG_SMEM>>>(
        s.value, query, s.cm, 256, 4096, 256, 256, 256L * 256, 256L * 4096,
        16, 256L * 4096, 0, 4096,
        nullptr, nullptr, nullptr, nullptr, 0, 0, nullptr, 1.f);

    // 10b) out += f_w[:, 512:] @ (cm * qcol)   (ACCUM, CONCAT path with Ksplit=0)
    mgemm<false, false, false, true, true><<<dim3(64, 4, 16), 128, TG_SMEM>>>(
        f_w + 512, s.cm, out, 512, 4096, 256, 768, 0, 256L * 4096,
        16, 512L * 4096, 0, 4096,
        nullptr, nullptr, nullptr, s.cm, 256L * 4096, 0, s.qcol, 1.f);

    // 11) BatchNorm (batch stats) + ReLU
    bn_stats<<<512, 256>>>(out, s.mean, s.istd);
    bn_apply<<<131072, 256>>>(out, s.mean, s.istd, bn_g, bn_b);
}

// round 16
// speedup vs baseline: 1.9983x; 1.0357x over previous
#include <cuda_runtime.h>
#include <cuda_bf16.h>
#include <cuda_fp16.h>
#include <cstdint>
#include <stdint.h>
#include <math.h>

// ---------------------------------------------------------------------------
// Scratch (static __device__ arrays; no allocations anywhere)
// ---------------------------------------------------------------------------
__device__ __half g_kf[48u * 256u * 4096u];   // fp16 kf, 100 MB
__device__ __half g_cm[16u * 256u * 4096u];   // fp16 cm*qcol, 34 MB
__device__ float g_kmax[48 * 256];
__device__ float g_kinv[48 * 256];
__device__ float g_qmax[16 * 256];
__device__ float g_qinvs[16 * 256];
__device__ float g_kpbs[16 * 768 * 256];
__device__ float g_qpb[16 * 256 * 256];
__device__ float g_sim[16 * 256 * 768];
__device__ float g_value[16 * 256 * 256];
__device__ float g_qcol[16 * 4096];
__device__ float g_mean[512];
__device__ float g_istd[512];

// ---------------------------------------------------------------------------
// mma.sync helpers (plain sm_80+ PTX — valid under compute_103)
// ---------------------------------------------------------------------------
__device__ __forceinline__ uint32_t smem_u32(const void* p) {
    uint32_t a;
    asm("{ .reg .u64 t; cvta.to.shared.u64 t, %1; cvt.u32.u64 %0, t; }" : "=r"(a) : "l"(p));
    return a;
}
__device__ __forceinline__ void ldmat4(uint32_t& r0, uint32_t& r1, uint32_t& r2, uint32_t& r3,
                                       uint32_t addr) {
    asm volatile("ldmatrix.sync.aligned.m8n8.x4.shared.b16 {%0,%1,%2,%3}, [%4];"
                 : "=r"(r0), "=r"(r1), "=r"(r2), "=r"(r3) : "r"(addr));
}
__device__ __forceinline__ void mma16816(float* d, const uint32_t* a, const uint32_t* b) {
    asm volatile(
        "mma.sync.aligned.m16n8k16.row.col.f32.f16.f16.f32 "
        "{%0,%1,%2,%3}, {%4,%5,%6,%7}, {%8,%9}, {%0,%1,%2,%3};"
        : "+f"(d[0]), "+f"(d[1]), "+f"(d[2]), "+f"(d[3])
        : "r"(a[0]), "r"(a[1]), "r"(a[2]), "r"(a[3]), "r"(b[0]), "r"(b[1]));
}
__device__ __forceinline__ uint32_t cvt2(float x, float y) {   // (x->lo, y->hi)
    uint32_t r;
    asm("cvt.rn.f16x2.f32 %0, %1, %2;" : "=r"(r) : "f"(y), "f"(x));
    return r;
}
__device__ __forceinline__ uint32_t prmt(uint32_t a, uint32_t b, uint32_t sel) {
    uint32_t r;
    asm("prmt.b32 %0, %1, %2, %3;" : "=r"(r) : "r"(a), "r"(b), "r"(sel));
    return r;
}
__device__ __forceinline__ float2 h2f(uint32_t w) {
    __half2 h = *reinterpret_cast<__half2*>(&w);
    return __half22float2(h);
}

// smem geometry (per buffer): A 128 rows, B 64 rows, 80 B rows.
static constexpr int ROWB    = 80;             // 32 f16 + 8 pad
static constexpr int A_PART  = 128 * ROWB;     // 10240
static constexpr int B_PART  = 64 * ROWB;      // 5120
static constexpr int OFF_A1  = 0;
static constexpr int OFF_B1  = A_PART;
static constexpr int BUFB    = A_PART + B_PART;   // 15360
static constexpr int TG_SMEM = 2 * BUFB;          // 30720

// ---------------------------------------------------------------------------
// Pure fp16 mma.sync GEMM: C ~= alpha*(A @ B') (+bias) (+=C if ACCUM)
//   AH/BH: A/B source already fp16;  OUT16: write C as fp16
//   COLSC: epilogue column scale colscale[z*N+c]
//   A: row-major [M, lda]; EXPA: fused exp(a-rmax)*rinv per row
//   TB:  B row-major [N,K] (C = A @ B^T);  !TB: B row-major [K,N]
// CTA tile 128x64, K chunks of 32; 4 warps (128 thr), warp tile 64x32.
// ---------------------------------------------------------------------------
template<bool TB, bool EXPA, bool HASBIAS, bool ACCUM, bool AH, bool BH, bool OUT16, bool COLSC>
__global__ void __launch_bounds__(128, 3) mgemm(
    const void* __restrict__ Ain, const void* __restrict__ Bin, void* __restrict__ Cout,
    int M, int N, int K, int lda, long sAz, long sBz,
    int modB, long sCb, long sCr, int ldc,
    const float* __restrict__ rmax, const float* __restrict__ rinv,
    const float* __restrict__ bias,
    const float* __restrict__ colscale, float alpha)
{
    extern __shared__ char smem[];
    const uint32_t sb = smem_u32(smem);
    const int tid = threadIdx.x;
    const int wid = tid >> 5;
    const int lane = tid & 31;
    const int z = blockIdx.z;
    const int bm = blockIdx.y * 128;
    const int bn = blockIdx.x * 64;

    // ---- A loader: row = ar+32j (j<4), 8 consecutive k per thread ----
    const int ar = tid >> 2;
    const int ak8 = (tid & 3) * 8;
    const float* gA0 = nullptr;
    const __half* gAh = nullptr;
    if (AH) gAh = (const __half*)Ain + (long)z * sAz + (long)(bm + ar) * lda + ak8;
    else    gA0 = (const float*)Ain + (long)z * sAz + (long)(bm + ar) * lda + ak8;

    float smx[4], siv[4];
    if (EXPA) {
        #pragma unroll
        for (int j = 0; j < 4; j++) {
            const int r = bm + ar + 32 * j;
            smx[j] = rmax[(long)z * M + r];
            siv[j] = rinv[(long)z * M + r];
        }
    }

    // ---- B loader geometry ----
    const float* gB0 = nullptr;
    const __half* gBh = nullptr;
    int bkp = 0, bng = 0;
    if (TB) {
        if (BH) gBh = (const __half*)Bin + (long)z * sBz + (long)(bn + ar) * K + ak8;
        else    gB0 = (const float*)Bin + (long)z * sBz + (long)(bn + ar) * K + ak8;
    } else {
        bkp = tid & 15;
        bng = tid >> 4;
        if (BH) gBh = (const __half*)Bin + (long)z * sBz;
        else    gB0 = (const float*)Bin + (long)z * sBz;
    }

    const int nch = K >> 5;

    float4 fa[4][2], fb[2][2];
    uint4 uaA[4], ubT[2], ubN[2];

    auto loadA = [&](int ch) {
        if (AH) {
            const __half* p = gAh + ch * 32;
            #pragma unroll
            for (int j = 0; j < 4; j++)
                uaA[j] = *reinterpret_cast<const uint4*>(p + (long)(32 * j) * lda);
        } else {
            const float* p = gA0 + ch * 32;
            #pragma unroll
            for (int j = 0; j < 4; j++) {
                fa[j][0] = *reinterpret_cast<const float4*>(p + (long)(32 * j) * lda);
                fa[j][1] = *reinterpret_cast<const float4*>(p + (long)(32 * j) * lda + 4);
            }
        }
    };
    auto loadB = [&](int ch) {
        if (TB) {
            if (BH) {
                const __half* p = gBh + ch * 32;
                #pragma unroll
                for (int j = 0; j < 2; j++)
                    ubT[j] = *reinterpret_cast<const uint4*>(p + (long)(32 * j) * K);
            } else {
                const float* p = gB0 + ch * 32;
                #pragma unroll
                for (int j = 0; j < 2; j++) {
                    fb[j][0] = *reinterpret_cast<const float4*>(p + (long)(32 * j) * K);
                    fb[j][1] = *reinterpret_cast<const float4*>(p + (long)(32 * j) * K + 4);
                }
            }
        } else {
            const int kg = ch * 32 + 2 * bkp;
            if (BH) {
                const __half* src = gBh + (long)kg * N + bn + bng * 8;
                ubN[0] = *reinterpret_cast<const uint4*>(src);
                ubN[1] = *reinterpret_cast<const uint4*>(src + N);
            } else {
                const float* src = gB0 + (long)kg * N + bn + bng * 8;
                fb[0][0] = *reinterpret_cast<const float4*>(src);
                fb[0][1] = *reinterpret_cast<const float4*>(src + 4);
                fb[1][0] = *reinterpret_cast<const float4*>(src + N);
                fb[1][1] = *reinterpret_cast<const float4*>(src + N + 4);
            }
        }
    };
    auto stashA = [&](int buf) {
        char* a1 = smem + buf * BUFB + OFF_A1;
        #pragma unroll
        for (int j = 0; j < 4; j++) {
            uint4 hi;
            if (AH) {
                if (EXPA) {
                    float2 p0 = h2f(uaA[j].x), p1 = h2f(uaA[j].y);
                    float2 p2 = h2f(uaA[j].z), p3 = h2f(uaA[j].w);
                    const float m = smx[j], v = siv[j];
                    p0.x = __expf(p0.x - m) * v; p0.y = __expf(p0.y - m) * v;
                    p1.x = __expf(p1.x - m) * v; p1.y = __expf(p1.y - m) * v;
                    p2.x = __expf(p2.x - m) * v; p2.y = __expf(p2.y - m) * v;
                    p3.x = __expf(p3.x - m) * v; p3.y = __expf(p3.y - m) * v;
                    hi.x = cvt2(p0.x, p0.y); hi.y = cvt2(p1.x, p1.y);
                    hi.z = cvt2(p2.x, p2.y); hi.w = cvt2(p3.x, p3.y);
                } else {
                    hi = uaA[j];
                }
            } else {
                float4 f0 = fa[j][0], f1 = fa[j][1];
                if (EXPA) {
                    const float m = smx[j], v = siv[j];
                    f0.x = __expf(f0.x - m) * v; f0.y = __expf(f0.y - m) * v;
                    f0.z = __expf(f0.z - m) * v; f0.w = __expf(f0.w - m) * v;
                    f1.x = __expf(f1.x - m) * v; f1.y = __expf(f1.y - m) * v;
                    f1.z = __expf(f1.z - m) * v; f1.w = __expf(f1.w - m) * v;
                }
                hi.x = cvt2(f0.x, f0.y); hi.y = cvt2(f0.z, f0.w);
                hi.z = cvt2(f1.x, f1.y); hi.w = cvt2(f1.z, f1.w);
            }
            const int off = (ar + 32 * j) * ROWB + (tid & 3) * 16;
            *reinterpret_cast<uint4*>(a1 + off) = hi;
        }
    };
    auto stashB = [&](int buf) {
        char* b1 = smem + buf * BUFB + OFF_B1;
        if (TB) {
            #pragma unroll
            for (int j = 0; j < 2; j++) {
                uint4 hi;
                if (BH) {
                    hi = ubT[j];
                } else {
                    const float4 f0 = fb[j][0], f1 = fb[j][1];
                    hi.x = cvt2(f0.x, f0.y); hi.y = cvt2(f0.z, f0.w);
                    hi.z = cvt2(f1.x, f1.y); hi.w = cvt2(f1.z, f1.w);
                }
                const int off = (ar + 32 * j) * ROWB + (tid & 3) * 16;
                *reinterpret_cast<uint4*>(b1 + off) = hi;
            }
        } else if (BH) {
            const uint32_t* w0 = reinterpret_cast<const uint32_t*>(&ubN[0]);
            const uint32_t* w1 = reinterpret_cast<const uint32_t*>(&ubN[1]);
            #pragma unroll
            for (int u = 0; u < 4; u++) {
                const uint32_t lo = prmt(w0[u], w1[u], 0x5410);  // n = 2u
                const uint32_t hi = prmt(w0[u], w1[u], 0x7632);  // n = 2u+1
                const int off0 = (bng * 8 + 2 * u) * ROWB + bkp * 4;
                *reinterpret_cast<uint32_t*>(b1 + off0) = lo;
                *reinterpret_cast<uint32_t*>(b1 + off0 + ROWB) = hi;
            }
        } else {
            const float* r0 = reinterpret_cast<const float*>(&fb[0][0]);
            const float* r1 = reinterpret_cast<const float*>(&fb[1][0]);
            #pragma unroll
            for (int u = 0; u < 8; u++) {
                const uint32_t hi = cvt2(r0[u], r1[u]);   // k-pair in one word
                const int off = (bng * 8 + u) * ROWB + bkp * 4;
                *reinterpret_cast<uint32_t*>(b1 + off) = hi;
            }
        }
    };

    loadA(0); loadB(0);
    stashA(0); stashB(0);
    __syncthreads();

    float d[4][4][4];
    #pragma unroll
    for (int i = 0; i < 4; i++)
        #pragma unroll
        for (int j = 0; j < 4; j++)
            #pragma unroll
            for (int q = 0; q < 4; q++) d[i][j][q] = 0.f;

    const int wm = (wid >> 1) * 64;   // 2 m-warps
    const int wn = (wid & 1) * 32;    // 2 n-warps
    const int lr = lane & 15;
    const int lc = lane >> 4;

    for (int ch = 0; ch < nch; ch++) {
        const bool hasNext = (ch + 1 < nch);
        if (hasNext) { loadA(ch + 1); loadB(ch + 1); }

        const uint32_t base = sb + (ch & 1) * BUFB;
        #pragma unroll
        for (int ks = 0; ks < 2; ks++) {
            const uint32_t koff = ks * 32 + lc * 16;
            uint32_t ah[4][4], bh[4][2];
            #pragma unroll
            for (int mt = 0; mt < 4; mt++)
                ldmat4(ah[mt][0], ah[mt][1], ah[mt][2], ah[mt][3],
                       base + OFF_A1 + (wm + mt * 16 + lr) * ROWB + koff);
            #pragma unroll
            for (int bt = 0; bt < 2; bt++) {
                uint32_t r0, r1, r2, r3;
                ldmat4(r0, r1, r2, r3, base + OFF_B1 + (wn + bt * 16 + lr) * ROWB + koff);
                bh[2 * bt][0] = r0; bh[2 * bt][1] = r2;
                bh[2 * bt + 1][0] = r1; bh[2 * bt + 1][1] = r3;
            }
            #pragma unroll
            for (int mt = 0; mt < 4; mt++)
                #pragma unroll
                for (int nt = 0; nt < 4; nt++) mma16816(d[mt][nt], ah[mt], bh[nt]);
        }
        if (hasNext) { stashA((ch + 1) & 1); stashB((ch + 1) & 1); }
        __syncthreads();
    }

    // epilogue
    const long coff = (long)(z % modB) * sCb + (long)(z / modB) * sCr;
    #pragma unroll
    for (int mt = 0; mt < 4; mt++) {
        const int r0 = bm + wm + mt * 16 + (lane >> 2);
        const float bi0 = HASBIAS ? bias[r0] : 0.f;
        const float bi8 = HASBIAS ? bias[r0 + 8] : 0.f;
        #pragma unroll
        for (int nt = 0; nt < 4; nt++) {
            const int c0 = bn + wn + nt * 8 + (lane & 3) * 2;
            float v0 = d[mt][nt][0] * alpha + bi0;
            float v1 = d[mt][nt][1] * alpha + bi0;
            float v2 = d[mt][nt][2] * alpha + bi8;
            float v3 = d[mt][nt][3] * alpha + bi8;
            if (COLSC) {
                const float2 cs = *reinterpret_cast<const float2*>(colscale + (long)z * N + c0);
                v0 *= cs.x; v1 *= cs.y; v2 *= cs.x; v3 *= cs.y;
            }
            if (OUT16) {
                __half* Ch = (__half*)Cout;
                *reinterpret_cast<uint32_t*>(Ch + coff + (long)r0 * ldc + c0) = cvt2(v0, v1);
                *reinterpret_cast<uint32_t*>(Ch + coff + (long)(r0 + 8) * ldc + c0) = cvt2(v2, v3);
            } else {
                float* Cf = (float*)Cout;
                float* p0 = Cf + coff + (long)r0 * ldc + c0;
                float* p1 = Cf + coff + (long)(r0 + 8) * ldc + c0;
                if (ACCUM) {
                    const float2 o0 = *reinterpret_cast<float2*>(p0);
                    const float2 o1 = *reinterpret_cast<float2*>(p1);
                    v0 += o0.x; v1 += o0.y; v2 += o1.x; v3 += o1.y;
                }
                *reinterpret_cast<float2*>(p0) = make_float2(v0, v1);
                *reinterpret_cast<float2*>(p1) = make_float2(v2, v3);
            }
        }
    }
}

// ---------------------------------------------------------------------------
// Reductions / elementwise helpers
// ---------------------------------------------------------------------------
__device__ __forceinline__ float blockReduce(float v, bool ismax) {
    __shared__ float sh[32];
    __syncthreads();
    int lane = threadIdx.x & 31, wid = threadIdx.x >> 5;
    #pragma unroll
    for (int o = 16; o; o >>= 1) {
        float t = __shfl_xor_sync(0xffffffffu, v, o);
        v = ismax ? fmaxf(v, t) : (v + t);
    }
    if (lane == 0) sh[wid] = v;
    __syncthreads();
    int nw = (blockDim.x + 31) >> 5;
    if (wid == 0) {
        v = (lane < nw) ? sh[lane] : (ismax ? -1e30f : 0.f);
        #pragma unroll
        for (int o = 16; o; o >>= 1) {
            float t = __shfl_xor_sync(0xffffffffu, v, o);
            v = ismax ? fmaxf(v, t) : (v + t);
        }
        if (lane == 0) sh[0] = v;
    }
    __syncthreads();
    return sh[0];
}

// Row stats, fp32 rows of 4096 (query)
__global__ void row_stats4k(const float* __restrict__ X, float* __restrict__ omax,
                            float* __restrict__ oinv)
{
    const long row = blockIdx.x;
    const float4* x = reinterpret_cast<const float4*>(X + row * 4096);
    float4 v[4];
    float m = -1e30f;
    #pragma unroll
    for (int j = 0; j < 4; j++) {
        v[j] = x[threadIdx.x + 256 * j];
        m = fmaxf(m, fmaxf(fmaxf(v[j].x, v[j].y), fmaxf(v[j].z, v[j].w)));
    }
    m = blockReduce(m, true);
    float s = 0.f;
    #pragma unroll
    for (int j = 0; j < 4; j++)
        s += __expf(v[j].x - m) + __expf(v[j].y - m) + __expf(v[j].z - m) + __expf(v[j].w - m);
    s = blockReduce(s, false);
    if (threadIdx.x == 0) { omax[row] = m; oinv[row] = 1.f / s; }
}

// Row stats, fp16 rows of 4096 (kf)
__global__ void row_stats4k_h(const __half* __restrict__ X, float* __restrict__ omax,
                              float* __restrict__ oinv)
{
    const long row = blockIdx.x;
    const uint4* x = reinterpret_cast<const uint4*>(X + row * 4096);  // 512 uint4/row
    uint4 v[2];
    v[0] = x[threadIdx.x];
    v[1] = x[threadIdx.x + 256];
    float f[16];
    #pragma unroll
    for (int j = 0; j < 2; j++) {
        const uint32_t* w = reinterpret_cast<const uint32_t*>(&v[j]);
        #pragma unroll
        for (int u = 0; u < 4; u++) {
            float2 p = h2f(w[u]);
            f[j * 8 + 2 * u] = p.x; f[j * 8 + 2 * u + 1] = p.y;
        }
    }
    float m = -1e30f;
    #pragma unroll
    for (int i = 0; i < 16; i++) m = fmaxf(m, f[i]);
    m = blockReduce(m, true);
    float s = 0.f;
    #pragma unroll
    for (int i = 0; i < 16; i++) s += __expf(f[i] - m);
    s = blockReduce(s, false);
    if (threadIdx.x == 0) { omax[row] = m; oinv[row] = 1.f / s; }
}

__global__ void softmax_inplace(float* __restrict__ X, int len)
{
    const long row = blockIdx.x;
    float* x = X + row * len;
    float m = -1e30f;
    for (int i = threadIdx.x; i < len; i += blockDim.x) m = fmaxf(m, x[i]);
    m = blockReduce(m, true);
    float s = 0.f;
    for (int i = threadIdx.x; i < len; i += blockDim.x) s += __expf(x[i] - m);
    s = blockReduce(s, false);
    const float inv = 1.f / s;
    for (int i = threadIdx.x; i < len; i += blockDim.x) x[i] = __expf(x[i] - m) * inv;
}

__global__ void norm_rows256(float* __restrict__ V)
{
    const long row = blockIdx.x;
    float* v = V + row * 256;
    const float x = v[threadIdx.x];
    const float s = blockReduce(x * x, false);
    v[threadIdx.x] = x * rsqrtf(s);
}

__global__ void qcol_norm(const float* __restrict__ q, float* __restrict__ out)
{
    const int b = blockIdx.y;
    const int n = blockIdx.x * 256 + threadIdx.x;
    const float* p = q + (long)b * 256 * 4096 + n;
    float s = 0.f;
    #pragma unroll 8
    for (int c = 0; c < 256; c++) { float v = p[(long)c * 4096]; s += v * v; }
    out[b * 4096 + n] = rsqrtf(s);
}

__global__ void bn_stats(const float* __restrict__ y, float* __restrict__ mean,
                         float* __restrict__ istd)
{
    const int o = blockIdx.x;
    float s = 0.f, s2 = 0.f;
    for (int b = 0; b < 16; b++) {
        const float* p = y + ((long)b * 512 + o) * 4096;
        for (int i = threadIdx.x; i < 4096; i += 256) {
            float v = p[i]; s += v; s2 += v * v;
        }
    }
    s = blockReduce(s, false);
    s2 = blockReduce(s2, false);
    if (threadIdx.x == 0) {
        float mu = s * (1.f / 65536.f);
        mean[o] = mu;
        istd[o] = 1.f / sqrtf(s2 * (1.f / 65536.f) - mu * mu + 1e-5f);
    }
}

__global__ void bn_apply(float* __restrict__ y, const float* __restrict__ mean,
                         const float* __restrict__ istd, const float* __restrict__ g,
                         const float* __restrict__ b)
{
    const long i = (long)blockIdx.x * 256 + threadIdx.x;
    const int o = (int)((i >> 12) & 511);
    float v = (y[i] - mean[o]) * istd[o] * g[o] + b[o];
    y[i] = v > 0.f ? v : 0.f;
}

// ---------------------------------------------------------------------------
// Host orchestration
// ---------------------------------------------------------------------------
struct Scratch {
    __half *kf, *cm;
    float *kmax, *kinv, *qmax, *qinvs, *kpbs, *qpb, *sim, *value, *qcol, *mean, *istd;
    cudaStream_t s2;
    cudaEvent_t evFork, evJoin;
};

static Scratch fetch_scratch() {
    Scratch s;
    cudaGetSymbolAddress((void**)&s.kf,    g_kf);
    cudaGetSymbolAddress((void**)&s.cm,    g_cm);
    cudaGetSymbolAddress((void**)&s.kmax,  g_kmax);
    cudaGetSymbolAddress((void**)&s.kinv,  g_kinv);
    cudaGetSymbolAddress((void**)&s.qmax,  g_qmax);
    cudaGetSymbolAddress((void**)&s.qinvs, g_qinvs);
    cudaGetSymbolAddress((void**)&s.kpbs,  g_kpbs);
    cudaGetSymbolAddress((void**)&s.qpb,   g_qpb);
    cudaGetSymbolAddress((void**)&s.sim,   g_sim);
    cudaGetSymbolAddress((void**)&s.value, g_value);
    cudaGetSymbolAddress((void**)&s.qcol,  g_qcol);
    cudaGetSymbolAddress((void**)&s.mean,  g_mean);
    cudaGetSymbolAddress((void**)&s.istd,  g_istd);
    cudaStreamCreateWithFlags(&s.s2, cudaStreamNonBlocking);
    cudaEventCreateWithFlags(&s.evFork, cudaEventDisableTiming);
    cudaEventCreateWithFlags(&s.evJoin, cudaEventDisableTiming);
    // raise smem limit for every instantiation used
    cudaFuncSetAttribute(mgemm<false, false, true,  false, false, false, true,  false>, cudaFuncAttributeMaxDynamicSharedMemorySize, TG_SMEM);
    cudaFuncSetAttribute(mgemm<true,  true,  false, false, true,  true,  false, false>, cudaFuncAttributeMaxDynamicSharedMemorySize, TG_SMEM);
    cudaFuncSetAttribute(mgemm<true,  true,  false, false, false, false, false, false>, cudaFuncAttributeMaxDynamicSharedMemorySize, TG_SMEM);
    cudaFuncSetAttribute(mgemm<true,  false, false, false, false, false, false, false>, cudaFuncAttributeMaxDynamicSharedMemorySize, TG_SMEM);
    cudaFuncSetAttribute(mgemm<false, false, false, false, false, false, false, false>, cudaFuncAttributeMaxDynamicSharedMemorySize, TG_SMEM);
    cudaFuncSetAttribute(mgemm<false, false, false, false, false, false, true,  true >, cudaFuncAttributeMaxDynamicSharedMemorySize, TG_SMEM);
    cudaFuncSetAttribute(mgemm<false, false, true,  false, false, false, false, false>, cudaFuncAttributeMaxDynamicSharedMemorySize, TG_SMEM);
    cudaFuncSetAttribute(mgemm<false, false, false, true,  false, true,  false, false>, cudaFuncAttributeMaxDynamicSharedMemorySize, TG_SMEM);
    return s;
}

extern "C" void kernel_launch(void* const* d_in, const int* in_sizes, int n_in,
                              void* d_out, int out_size)
{
    (void)in_sizes; (void)n_in; (void)out_size;
    static Scratch s = fetch_scratch();  // first call is the non-captured correctness run

    const float* x     = (const float*)d_in[0];
    const float* query = (const float*)d_in[1];
    const float* refs  = (const float*)d_in[2];
    const float* K_w   = (const float*)d_in[3];
    const float* K_b   = (const float*)d_in[4];
    // d_in[5], d_in[6] = V_w, V_b : dead code in the reference.
    const float* f_w   = (const float*)d_in[7];
    const float* f_b   = (const float*)d_in[8];
    const float* bn_g  = (const float*)d_in[9];
    const float* bn_b  = (const float*)d_in[10];
    float* out = (float*)d_out;

    // ---- fork: independent work on s2 ----
    cudaEventRecord(s.evFork, 0);
    cudaStreamWaitEvent(s.s2, s.evFork, 0);

    // s2: query branch (stats, q_pb, qcol), then stage 10a (x-part of final conv)
    row_stats4k<<<16 * 256, 256, 0, s.s2>>>(query, s.qmax, s.qinvs);
    mgemm<true, true, false, false, false, false, false, false><<<dim3(4, 2, 16), 128, TG_SMEM, s.s2>>>(
        query, query, s.qpb, 256, 256, 4096, 4096, 256L * 4096, 256L * 4096,
        16, 256L * 256, 0, 256,
        s.qmax, s.qinvs, nullptr, nullptr, 1.f);
    qcol_norm<<<dim3(16, 16), 256, 0, s.s2>>>(query, s.qcol);
    // 10a) out = f_w[:, :512] @ x + f_b
    mgemm<false, false, true, false, false, false, false, false><<<dim3(64, 4, 16), 128, TG_SMEM, s.s2>>>(
        f_w, x, out, 512, 4096, 512, 768, 0, 512L * 4096,
        16, 512L * 4096, 0, 4096,
        nullptr, nullptr, f_b, nullptr, 1.f);

    // main: kf chain
    // 1) kf[z] = K_w @ refs[z] + K_b  -> fp16 kf
    mgemm<false, false, true, false, false, false, true, false><<<dim3(64, 2, 48), 128, TG_SMEM>>>(
        K_w, refs, s.kf, 256, 4096, 512, 512, 0, 512L * 4096,
        48, 256L * 4096, 0, 4096,
        nullptr, nullptr, K_b, nullptr, 1.f);

    // 2) kf softmax row stats (fp16 input)
    row_stats4k_h<<<48 * 256, 256>>>(s.kf, s.kmax, s.kinv);

    // 3) k_pb[z] = softmax(kf[z]) @ kf[z]^T  (fp16 A with EXPA, fp16 B)
    mgemm<true, true, false, false, true, true, false, false><<<dim3(4, 2, 48), 128, TG_SMEM>>>(
        s.kf, s.kf, s.kpbs, 256, 256, 4096, 4096, 256L * 4096, 256L * 4096,
        16, 768L * 256, 256L * 256, 256,
        s.kmax, s.kinv, nullptr, nullptr, 1.f);

    // ---- join s2 (q_pb + out ready) before stage 5 ----
    cudaEventRecord(s.evJoin, s.s2);
    cudaStreamWaitEvent(0, s.evJoin, 0);

    // 5) sim = (q_pb @ k_pbs^T) / sqrt(256)
    mgemm<true, false, false, false, false, false, false, false><<<dim3(12, 2, 16), 128, TG_SMEM>>>(
        s.qpb, s.kpbs, s.sim, 256, 768, 256, 256, 256L * 256, 768L * 256,
        16, 256L * 768, 0, 768,
        nullptr, nullptr, nullptr, nullptr, 0.0625f);

    // 6) softmax over k
    softmax_inplace<<<16 * 256, 256>>>(s.sim, 768);

    // 7) value = sim @ k_pbs (NN)
    mgemm<false, false, false, false, false, false, false, false><<<dim3(4, 2, 16), 128, TG_SMEM>>>(
        s.sim, s.kpbs, s.value, 256, 256, 768, 768, 256L * 768, 768L * 256,
        16, 256L * 256, 0, 256,
        nullptr, nullptr, nullptr, nullptr, 1.f);

    // 8) normalize prototypes
    norm_rows256<<<16 * 256, 256>>>(s.value);

    // 9) cm = (proto_n @ query) * qcol  -> fp16 (COLSC epilogue)
    mgemm<false, false, false, false, false, false, true, true><<<dim3(64, 2, 16), 128, TG_SMEM>>>(
        s.value, query, s.cm, 256, 4096, 256, 256, 256L * 256, 256L * 4096,
        16, 256L * 4096, 0, 4096,
        nullptr, nullptr, nullptr, s.qcol, 1.f);

    // 10b) out += f_w[:, 512:] @ cm   (ACCUM, fp16 B)
    mgemm<false, false, false, true, false, true, false, false><<<dim3(64, 4, 16), 128, TG_SMEM>>>(
        f_w + 512, s.cm, out, 512, 4096, 256, 768, 0, 256L * 4096,
        16, 512L * 4096, 0, 4096,
        nullptr, nullptr, nullptr, nullptr, 1.f);

    // 11) BatchNorm (batch stats) + ReLU
    bn_stats<<<512, 256>>>(out, s.mean, s.istd);
    bn_apply<<<131072, 256>>>(out, s.mean, s.istd, bn_g, bn_b);
}

// round 17
// speedup vs baseline: 2.1549x; 1.0784x over previous
#include <cuda_runtime.h>
#include <cuda_bf16.h>
#include <cuda_fp16.h>
#include <cstdint>
#include <stdint.h>
#include <math.h>

// ---------------------------------------------------------------------------
// Scratch (static __device__ arrays; no allocations anywhere)
// ---------------------------------------------------------------------------
__device__ __half g_kf[48u * 256u * 4096u];   // fp16 kf, 100 MB
__device__ __half g_cm[16u * 256u * 4096u];   // fp16 cm*qcol, 34 MB
__device__ __half g_kwh[256 * 512];           // fp16 K_w
__device__ __half g_fwh[512 * 768];           // fp16 f_w
__device__ __half g_kpbs[16 * 768 * 256];     // fp16 kpbs
__device__ __half g_qpb[16 * 256 * 256];      // fp16 qpb
__device__ __half g_valh[16 * 256 * 256];     // fp16 normalized proto
__device__ float g_kmax[48 * 256];
__device__ float g_kinv[48 * 256];
__device__ float g_qmax[16 * 256];
__device__ float g_qinvs[16 * 256];
__device__ float g_sim[16 * 256 * 768];
__device__ float g_value[16 * 256 * 256];
__device__ float g_qcol[16 * 4096];
__device__ float g_mean[512];
__device__ float g_istd[512];

// ---------------------------------------------------------------------------
// mma.sync helpers (plain sm_80+ PTX — valid under compute_103)
// ---------------------------------------------------------------------------
__device__ __forceinline__ uint32_t smem_u32(const void* p) {
    uint32_t a;
    asm("{ .reg .u64 t; cvta.to.shared.u64 t, %1; cvt.u32.u64 %0, t; }" : "=r"(a) : "l"(p));
    return a;
}
__device__ __forceinline__ void ldmat4(uint32_t& r0, uint32_t& r1, uint32_t& r2, uint32_t& r3,
                                       uint32_t addr) {
    asm volatile("ldmatrix.sync.aligned.m8n8.x4.shared.b16 {%0,%1,%2,%3}, [%4];"
                 : "=r"(r0), "=r"(r1), "=r"(r2), "=r"(r3) : "r"(addr));
}
__device__ __forceinline__ void mma16816(float* d, const uint32_t* a, const uint32_t* b) {
    asm volatile(
        "mma.sync.aligned.m16n8k16.row.col.f32.f16.f16.f32 "
        "{%0,%1,%2,%3}, {%4,%5,%6,%7}, {%8,%9}, {%0,%1,%2,%3};"
        : "+f"(d[0]), "+f"(d[1]), "+f"(d[2]), "+f"(d[3])
        : "r"(a[0]), "r"(a[1]), "r"(a[2]), "r"(a[3]), "r"(b[0]), "r"(b[1]));
}
__device__ __forceinline__ uint32_t cvt2(float x, float y) {   // (x->lo, y->hi)
    uint32_t r;
    asm("cvt.rn.f16x2.f32 %0, %1, %2;" : "=r"(r) : "f"(y), "f"(x));
    return r;
}
__device__ __forceinline__ uint32_t prmt(uint32_t a, uint32_t b, uint32_t sel) {
    uint32_t r;
    asm("prmt.b32 %0, %1, %2, %3;" : "=r"(r) : "r"(a), "r"(b), "r"(sel));
    return r;
}
__device__ __forceinline__ float2 h2f(uint32_t w) {
    __half2 h = *reinterpret_cast<__half2*>(&w);
    return __half22float2(h);
}

// smem geometry (per buffer): A 128 rows, B 64 rows, 80 B rows.
static constexpr int ROWB    = 80;             // 32 f16 + 8 pad
static constexpr int A_PART  = 128 * ROWB;     // 10240
static constexpr int B_PART  = 64 * ROWB;      // 5120
static constexpr int OFF_A1  = 0;
static constexpr int OFF_B1  = A_PART;
static constexpr int BUFB    = A_PART + B_PART;   // 15360
static constexpr int TG_SMEM = 2 * BUFB;          // 30720

// ---------------------------------------------------------------------------
// Pure fp16 mma.sync GEMM: C ~= alpha*(A @ B') (+bias) (+=C if ACCUM)
//   AH/BH: A/B source already fp16;  OUT16: write C as fp16
//   COLSC: epilogue column scale colscale[z*N+c]
//   A: row-major [M, lda]; EXPA: fused exp(a-rmax)*rinv per row
//   TB:  B row-major [N,K] (C = A @ B^T);  !TB: B row-major [K,N]
// CTA tile 128x64, K chunks of 32; 4 warps (128 thr), warp tile 64x32.
// ---------------------------------------------------------------------------
template<bool TB, bool EXPA, bool HASBIAS, bool ACCUM, bool AH, bool BH, bool OUT16, bool COLSC>
__global__ void __launch_bounds__(128, 3) mgemm(
    const void* __restrict__ Ain, const void* __restrict__ Bin, void* __restrict__ Cout,
    int M, int N, int K, int lda, long sAz, long sBz,
    int modB, long sCb, long sCr, int ldc,
    const float* __restrict__ rmax, const float* __restrict__ rinv,
    const float* __restrict__ bias,
    const float* __restrict__ colscale, float alpha)
{
    extern __shared__ char smem[];
    const uint32_t sb = smem_u32(smem);
    const int tid = threadIdx.x;
    const int wid = tid >> 5;
    const int lane = tid & 31;
    const int z = blockIdx.z;
    const int bm = blockIdx.y * 128;
    const int bn = blockIdx.x * 64;

    // ---- A loader: row = ar+32j (j<4), 8 consecutive k per thread ----
    const int ar = tid >> 2;
    const int ak8 = (tid & 3) * 8;
    const float* gA0 = nullptr;
    const __half* gAh = nullptr;
    if (AH) gAh = (const __half*)Ain + (long)z * sAz + (long)(bm + ar) * lda + ak8;
    else    gA0 = (const float*)Ain + (long)z * sAz + (long)(bm + ar) * lda + ak8;

    float smx[4], siv[4];
    if (EXPA) {
        #pragma unroll
        for (int j = 0; j < 4; j++) {
            const int r = bm + ar + 32 * j;
            smx[j] = rmax[(long)z * M + r];
            siv[j] = rinv[(long)z * M + r];
        }
    }

    // ---- B loader geometry ----
    const float* gB0 = nullptr;
    const __half* gBh = nullptr;
    int bkp = 0, bng = 0;
    if (TB) {
        if (BH) gBh = (const __half*)Bin + (long)z * sBz + (long)(bn + ar) * K + ak8;
        else    gB0 = (const float*)Bin + (long)z * sBz + (long)(bn + ar) * K + ak8;
    } else {
        bkp = tid & 15;
        bng = tid >> 4;
        if (BH) gBh = (const __half*)Bin + (long)z * sBz;
        else    gB0 = (const float*)Bin + (long)z * sBz;
    }

    const int nch = K >> 5;

    float4 fa[4][2], fb[2][2];
    uint4 uaA[4], ubT[2], ubN[2];

    auto loadA = [&](int ch) {
        if (AH) {
            const __half* p = gAh + ch * 32;
            #pragma unroll
            for (int j = 0; j < 4; j++)
                uaA[j] = *reinterpret_cast<const uint4*>(p + (long)(32 * j) * lda);
        } else {
            const float* p = gA0 + ch * 32;
            #pragma unroll
            for (int j = 0; j < 4; j++) {
                fa[j][0] = *reinterpret_cast<const float4*>(p + (long)(32 * j) * lda);
                fa[j][1] = *reinterpret_cast<const float4*>(p + (long)(32 * j) * lda + 4);
            }
        }
    };
    auto loadB = [&](int ch) {
        if (TB) {
            if (BH) {
                const __half* p = gBh + ch * 32;
                #pragma unroll
                for (int j = 0; j < 2; j++)
                    ubT[j] = *reinterpret_cast<const uint4*>(p + (long)(32 * j) * K);
            } else {
                const float* p = gB0 + ch * 32;
                #pragma unroll
                for (int j = 0; j < 2; j++) {
                    fb[j][0] = *reinterpret_cast<const float4*>(p + (long)(32 * j) * K);
                    fb[j][1] = *reinterpret_cast<const float4*>(p + (long)(32 * j) * K + 4);
                }
            }
        } else {
            const int kg = ch * 32 + 2 * bkp;
            if (BH) {
                const __half* src = gBh + (long)kg * N + bn + bng * 8;
                ubN[0] = *reinterpret_cast<const uint4*>(src);
                ubN[1] = *reinterpret_cast<const uint4*>(src + N);
            } else {
                const float* src = gB0 + (long)kg * N + bn + bng * 8;
                fb[0][0] = *reinterpret_cast<const float4*>(src);
                fb[0][1] = *reinterpret_cast<const float4*>(src + 4);
                fb[1][0] = *reinterpret_cast<const float4*>(src + N);
                fb[1][1] = *reinterpret_cast<const float4*>(src + N + 4);
            }
        }
    };
    auto stashA = [&](int buf) {
        char* a1 = smem + buf * BUFB + OFF_A1;
        #pragma unroll
        for (int j = 0; j < 4; j++) {
            uint4 hi;
            if (AH) {
                if (EXPA) {
                    float2 p0 = h2f(uaA[j].x), p1 = h2f(uaA[j].y);
                    float2 p2 = h2f(uaA[j].z), p3 = h2f(uaA[j].w);
                    const float m = smx[j], v = siv[j];
                    p0.x = __expf(p0.x - m) * v; p0.y = __expf(p0.y - m) * v;
                    p1.x = __expf(p1.x - m) * v; p1.y = __expf(p1.y - m) * v;
                    p2.x = __expf(p2.x - m) * v; p2.y = __expf(p2.y - m) * v;
                    p3.x = __expf(p3.x - m) * v; p3.y = __expf(p3.y - m) * v;
                    hi.x = cvt2(p0.x, p0.y); hi.y = cvt2(p1.x, p1.y);
                    hi.z = cvt2(p2.x, p2.y); hi.w = cvt2(p3.x, p3.y);
                } else {
                    hi = uaA[j];
                }
            } else {
                float4 f0 = fa[j][0], f1 = fa[j][1];
                if (EXPA) {
                    const float m = smx[j], v = siv[j];
                    f0.x = __expf(f0.x - m) * v; f0.y = __expf(f0.y - m) * v;
                    f0.z = __expf(f0.z - m) * v; f0.w = __expf(f0.w - m) * v;
                    f1.x = __expf(f1.x - m) * v; f1.y = __expf(f1.y - m) * v;
                    f1.z = __expf(f1.z - m) * v; f1.w = __expf(f1.w - m) * v;
                }
                hi.x = cvt2(f0.x, f0.y); hi.y = cvt2(f0.z, f0.w);
                hi.z = cvt2(f1.x, f1.y); hi.w = cvt2(f1.z, f1.w);
            }
            const int off = (ar + 32 * j) * ROWB + (tid & 3) * 16;
            *reinterpret_cast<uint4*>(a1 + off) = hi;
        }
    };
    auto stashB = [&](int buf) {
        char* b1 = smem + buf * BUFB + OFF_B1;
        if (TB) {
            #pragma unroll
            for (int j = 0; j < 2; j++) {
                uint4 hi;
                if (BH) {
                    hi = ubT[j];
                } else {
                    const float4 f0 = fb[j][0], f1 = fb[j][1];
                    hi.x = cvt2(f0.x, f0.y); hi.y = cvt2(f0.z, f0.w);
                    hi.z = cvt2(f1.x, f1.y); hi.w = cvt2(f1.z, f1.w);
                }
                const int off = (ar + 32 * j) * ROWB + (tid & 3) * 16;
                *reinterpret_cast<uint4*>(b1 + off) = hi;
            }
        } else if (BH) {
            const uint32_t* w0 = reinterpret_cast<const uint32_t*>(&ubN[0]);
            const uint32_t* w1 = reinterpret_cast<const uint32_t*>(&ubN[1]);
            #pragma unroll
            for (int u = 0; u < 4; u++) {
                const uint32_t lo = prmt(w0[u], w1[u], 0x5410);  // n = 2u
                const uint32_t hi = prmt(w0[u], w1[u], 0x7632);  // n = 2u+1
                const int off0 = (bng * 8 + 2 * u) * ROWB + bkp * 4;
                *reinterpret_cast<uint32_t*>(b1 + off0) = lo;
                *reinterpret_cast<uint32_t*>(b1 + off0 + ROWB) = hi;
            }
        } else {
            const float* r0 = reinterpret_cast<const float*>(&fb[0][0]);
            const float* r1 = reinterpret_cast<const float*>(&fb[1][0]);
            #pragma unroll
            for (int u = 0; u < 8; u++) {
                const uint32_t hi = cvt2(r0[u], r1[u]);   // k-pair in one word
                const int off = (bng * 8 + u) * ROWB + bkp * 4;
                *reinterpret_cast<uint32_t*>(b1 + off) = hi;
            }
        }
    };

    loadA(0); loadB(0);
    stashA(0); stashB(0);
    __syncthreads();

    float d[4][4][4];
    #pragma unroll
    for (int i = 0; i < 4; i++)
        #pragma unroll
        for (int j = 0; j < 4; j++)
            #pragma unroll
            for (int q = 0; q < 4; q++) d[i][j][q] = 0.f;

    const int wm = (wid >> 1) * 64;   // 2 m-warps
    const int wn = (wid & 1) * 32;    // 2 n-warps
    const int lr = lane & 15;
    const int lc = lane >> 4;

    for (int ch = 0; ch < nch; ch++) {
        const bool hasNext = (ch + 1 < nch);
        if (hasNext) { loadA(ch + 1); loadB(ch + 1); }

        const uint32_t base = sb + (ch & 1) * BUFB;
        #pragma unroll
        for (int ks = 0; ks < 2; ks++) {
            const uint32_t koff = ks * 32 + lc * 16;
            uint32_t ah[4][4], bh[4][2];
            #pragma unroll
            for (int mt = 0; mt < 4; mt++)
                ldmat4(ah[mt][0], ah[mt][1], ah[mt][2], ah[mt][3],
                       base + OFF_A1 + (wm + mt * 16 + lr) * ROWB + koff);
            #pragma unroll
            for (int bt = 0; bt < 2; bt++) {
                uint32_t r0, r1, r2, r3;
                ldmat4(r0, r1, r2, r3, base + OFF_B1 + (wn + bt * 16 + lr) * ROWB + koff);
                bh[2 * bt][0] = r0; bh[2 * bt][1] = r2;
                bh[2 * bt + 1][0] = r1; bh[2 * bt + 1][1] = r3;
            }
            #pragma unroll
            for (int mt = 0; mt < 4; mt++)
                #pragma unroll
                for (int nt = 0; nt < 4; nt++) mma16816(d[mt][nt], ah[mt], bh[nt]);
        }
        if (hasNext) { stashA((ch + 1) & 1); stashB((ch + 1) & 1); }
        __syncthreads();
    }

    // epilogue
    const long coff = (long)(z % modB) * sCb + (long)(z / modB) * sCr;
    #pragma unroll
    for (int mt = 0; mt < 4; mt++) {
        const int r0 = bm + wm + mt * 16 + (lane >> 2);
        const float bi0 = HASBIAS ? bias[r0] : 0.f;
        const float bi8 = HASBIAS ? bias[r0 + 8] : 0.f;
        #pragma unroll
        for (int nt = 0; nt < 4; nt++) {
            const int c0 = bn + wn + nt * 8 + (lane & 3) * 2;
            float v0 = d[mt][nt][0] * alpha + bi0;
            float v1 = d[mt][nt][1] * alpha + bi0;
            float v2 = d[mt][nt][2] * alpha + bi8;
            float v3 = d[mt][nt][3] * alpha + bi8;
            if (COLSC) {
                const float2 cs = *reinterpret_cast<const float2*>(colscale + (long)z * N + c0);
                v0 *= cs.x; v1 *= cs.y; v2 *= cs.x; v3 *= cs.y;
            }
            if (OUT16) {
                __half* Ch = (__half*)Cout;
                *reinterpret_cast<uint32_t*>(Ch + coff + (long)r0 * ldc + c0) = cvt2(v0, v1);
                *reinterpret_cast<uint32_t*>(Ch + coff + (long)(r0 + 8) * ldc + c0) = cvt2(v2, v3);
            } else {
                float* Cf = (float*)Cout;
                float* p0 = Cf + coff + (long)r0 * ldc + c0;
                float* p1 = Cf + coff + (long)(r0 + 8) * ldc + c0;
                if (ACCUM) {
                    const float2 o0 = *reinterpret_cast<float2*>(p0);
                    const float2 o1 = *reinterpret_cast<float2*>(p1);
                    v0 += o0.x; v1 += o0.y; v2 += o1.x; v3 += o1.y;
                }
                *reinterpret_cast<float2*>(p0) = make_float2(v0, v1);
                *reinterpret_cast<float2*>(p1) = make_float2(v2, v3);
            }
        }
    }
}

// ---------------------------------------------------------------------------
// Reductions / elementwise helpers
// ---------------------------------------------------------------------------
__device__ __forceinline__ float blockReduce(float v, bool ismax) {
    __shared__ float sh[32];
    __syncthreads();
    int lane = threadIdx.x & 31, wid = threadIdx.x >> 5;
    #pragma unroll
    for (int o = 16; o; o >>= 1) {
        float t = __shfl_xor_sync(0xffffffffu, v, o);
        v = ismax ? fmaxf(v, t) : (v + t);
    }
    if (lane == 0) sh[wid] = v;
    __syncthreads();
    int nw = (blockDim.x + 31) >> 5;
    if (wid == 0) {
        v = (lane < nw) ? sh[lane] : (ismax ? -1e30f : 0.f);
        #pragma unroll
        for (int o = 16; o; o >>= 1) {
            float t = __shfl_xor_sync(0xffffffffu, v, o);
            v = ismax ? fmaxf(v, t) : (v + t);
        }
        if (lane == 0) sh[0] = v;
    }
    __syncthreads();
    return sh[0];
}

// fp32 -> fp16 convert pass (n multiple of 4)
__global__ void cvt_h(const float4* __restrict__ in, uint2* __restrict__ out, int n4)
{
    const int i = blockIdx.x * 256 + threadIdx.x;
    if (i >= n4) return;
    const float4 f = in[i];
    out[i] = make_uint2(cvt2(f.x, f.y), cvt2(f.z, f.w));
}

// Row stats, fp32 rows of 4096 (query)
__global__ void row_stats4k(const float* __restrict__ X, float* __restrict__ omax,
                            float* __restrict__ oinv)
{
    const long row = blockIdx.x;
    const float4* x = reinterpret_cast<const float4*>(X + row * 4096);
    float4 v[4];
    float m = -1e30f;
    #pragma unroll
    for (int j = 0; j < 4; j++) {
        v[j] = x[threadIdx.x + 256 * j];
        m = fmaxf(m, fmaxf(fmaxf(v[j].x, v[j].y), fmaxf(v[j].z, v[j].w)));
    }
    m = blockReduce(m, true);
    float s = 0.f;
    #pragma unroll
    for (int j = 0; j < 4; j++)
        s += __expf(v[j].x - m) + __expf(v[j].y - m) + __expf(v[j].z - m) + __expf(v[j].w - m);
    s = blockReduce(s, false);
    if (threadIdx.x == 0) { omax[row] = m; oinv[row] = 1.f / s; }
}

// Row stats, fp16 rows of 4096 (kf)
__global__ void row_stats4k_h(const __half* __restrict__ X, float* __restrict__ omax,
                              float* __restrict__ oinv)
{
    const long row = blockIdx.x;
    const uint4* x = reinterpret_cast<const uint4*>(X + row * 4096);  // 512 uint4/row
    uint4 v[2];
    v[0] = x[threadIdx.x];
    v[1] = x[threadIdx.x + 256];
    float f[16];
    #pragma unroll
    for (int j = 0; j < 2; j++) {
        const uint32_t* w = reinterpret_cast<const uint32_t*>(&v[j]);
        #pragma unroll
        for (int u = 0; u < 4; u++) {
            float2 p = h2f(w[u]);
            f[j * 8 + 2 * u] = p.x; f[j * 8 + 2 * u + 1] = p.y;
        }
    }
    float m = -1e30f;
    #pragma unroll
    for (int i = 0; i < 16; i++) m = fmaxf(m, f[i]);
    m = blockReduce(m, true);
    float s = 0.f;
    #pragma unroll
    for (int i = 0; i < 16; i++) s += __expf(f[i] - m);
    s = blockReduce(s, false);
    if (threadIdx.x == 0) { omax[row] = m; oinv[row] = 1.f / s; }
}

__global__ void softmax_inplace(float* __restrict__ X, int len)
{
    const long row = blockIdx.x;
    float* x = X + row * len;
    float m = -1e30f;
    for (int i = threadIdx.x; i < len; i += blockDim.x) m = fmaxf(m, x[i]);
    m = blockReduce(m, true);
    float s = 0.f;
    for (int i = threadIdx.x; i < len; i += blockDim.x) s += __expf(x[i] - m);
    s = blockReduce(s, false);
    const float inv = 1.f / s;
    for (int i = threadIdx.x; i < len; i += blockDim.x) x[i] = __expf(x[i] - m) * inv;
}

// L2-normalize fp32 rows of 256, output fp16
__global__ void norm_rows256h(const float* __restrict__ V, __half* __restrict__ out)
{
    const long row = blockIdx.x;
    const float x = V[row * 256 + threadIdx.x];
    const float s = blockReduce(x * x, false);
    out[row * 256 + threadIdx.x] = __float2half_rn(x * rsqrtf(s));
}

__global__ void qcol_norm(const float* __restrict__ q, float* __restrict__ out)
{
    const int b = blockIdx.y;
    const int n = blockIdx.x * 256 + threadIdx.x;
    const float* p = q + (long)b * 256 * 4096 + n;
    float s = 0.f;
    #pragma unroll 8
    for (int c = 0; c < 256; c++) { float v = p[(long)c * 4096]; s += v * v; }
    out[b * 4096 + n] = rsqrtf(s);
}

__global__ void bn_stats(const float* __restrict__ y, float* __restrict__ mean,
                         float* __restrict__ istd)
{
    const int o = blockIdx.x;
    float s = 0.f, s2 = 0.f;
    for (int b = 0; b < 16; b++) {
        const float* p = y + ((long)b * 512 + o) * 4096;
        for (int i = threadIdx.x; i < 4096; i += 256) {
            float v = p[i]; s += v; s2 += v * v;
        }
    }
    s = blockReduce(s, false);
    s2 = blockReduce(s2, false);
    if (threadIdx.x == 0) {
        float mu = s * (1.f / 65536.f);
        mean[o] = mu;
        istd[o] = 1.f / sqrtf(s2 * (1.f / 65536.f) - mu * mu + 1e-5f);
    }
}

__global__ void bn_apply(float* __restrict__ y, const float* __restrict__ mean,
                         const float* __restrict__ istd, const float* __restrict__ g,
                         const float* __restrict__ b)
{
    const long i = (long)blockIdx.x * 256 + threadIdx.x;
    const int o = (int)((i >> 12) & 511);
    float v = (y[i] - mean[o]) * istd[o] * g[o] + b[o];
    y[i] = v > 0.f ? v : 0.f;
}

// ---------------------------------------------------------------------------
// Host orchestration
// ---------------------------------------------------------------------------
struct Scratch {
    __half *kf, *cm, *kwh, *fwh, *kpbs, *qpb, *valh;
    float *kmax, *kinv, *qmax, *qinvs, *sim, *value, *qcol, *mean, *istd;
    cudaStream_t s2;
    cudaEvent_t evFork, evJoin;
};

static Scratch fetch_scratch() {
    Scratch s;
    cudaGetSymbolAddress((void**)&s.kf,    g_kf);
    cudaGetSymbolAddress((void**)&s.cm,    g_cm);
    cudaGetSymbolAddress((void**)&s.kwh,   g_kwh);
    cudaGetSymbolAddress((void**)&s.fwh,   g_fwh);
    cudaGetSymbolAddress((void**)&s.kpbs,  g_kpbs);
    cudaGetSymbolAddress((void**)&s.qpb,   g_qpb);
    cudaGetSymbolAddress((void**)&s.valh,  g_valh);
    cudaGetSymbolAddress((void**)&s.kmax,  g_kmax);
    cudaGetSymbolAddress((void**)&s.kinv,  g_kinv);
    cudaGetSymbolAddress((void**)&s.qmax,  g_qmax);
    cudaGetSymbolAddress((void**)&s.qinvs, g_qinvs);
    cudaGetSymbolAddress((void**)&s.sim,   g_sim);
    cudaGetSymbolAddress((void**)&s.value, g_value);
    cudaGetSymbolAddress((void**)&s.qcol,  g_qcol);
    cudaGetSymbolAddress((void**)&s.mean,  g_mean);
    cudaGetSymbolAddress((void**)&s.istd,  g_istd);
    cudaStreamCreateWithFlags(&s.s2, cudaStreamNonBlocking);
    cudaEventCreateWithFlags(&s.evFork, cudaEventDisableTiming);
    cudaEventCreateWithFlags(&s.evJoin, cudaEventDisableTiming);
    // raise smem limit for every instantiation used
    cudaFuncSetAttribute(mgemm<false, false, true,  false, true,  false, true,  false>, cudaFuncAttributeMaxDynamicSharedMemorySize, TG_SMEM);  // st1
    cudaFuncSetAttribute(mgemm<true,  true,  false, false, true,  true,  true,  false>, cudaFuncAttributeMaxDynamicSharedMemorySize, TG_SMEM);  // st3
    cudaFuncSetAttribute(mgemm<true,  true,  false, false, false, false, true,  false>, cudaFuncAttributeMaxDynamicSharedMemorySize, TG_SMEM);  // st4
    cudaFuncSetAttribute(mgemm<false, false, true,  false, true,  false, false, false>, cudaFuncAttributeMaxDynamicSharedMemorySize, TG_SMEM);  // 10a
    cudaFuncSetAttribute(mgemm<true,  false, false, false, true,  true,  false, false>, cudaFuncAttributeMaxDynamicSharedMemorySize, TG_SMEM);  // st5
    cudaFuncSetAttribute(mgemm<false, false, false, false, false, true,  false, false>, cudaFuncAttributeMaxDynamicSharedMemorySize, TG_SMEM);  // st7
    cudaFuncSetAttribute(mgemm<false, false, false, false, true,  false, true,  true >, cudaFuncAttributeMaxDynamicSharedMemorySize, TG_SMEM);  // st9
    cudaFuncSetAttribute(mgemm<false, false, false, true,  true,  true,  false, false>, cudaFuncAttributeMaxDynamicSharedMemorySize, TG_SMEM);  // 10b
    return s;
}

extern "C" void kernel_launch(void* const* d_in, const int* in_sizes, int n_in,
                              void* d_out, int out_size)
{
    (void)in_sizes; (void)n_in; (void)out_size;
    static Scratch s = fetch_scratch();  // first call is the non-captured correctness run

    const float* x     = (const float*)d_in[0];
    const float* query = (const float*)d_in[1];
    const float* refs  = (const float*)d_in[2];
    const float* K_w   = (const float*)d_in[3];
    const float* K_b   = (const float*)d_in[4];
    // d_in[5], d_in[6] = V_w, V_b : dead code in the reference.
    const float* f_w   = (const float*)d_in[7];
    const float* f_b   = (const float*)d_in[8];
    const float* bn_g  = (const float*)d_in[9];
    const float* bn_b  = (const float*)d_in[10];
    float* out = (float*)d_out;

    // 0) pre-convert weights to fp16 (before fork; both streams depend)
    cvt_h<<<128, 256>>>((const float4*)K_w, (uint2*)s.kwh, 32768);
    cvt_h<<<384, 256>>>((const float4*)f_w, (uint2*)s.fwh, 98304);

    // ---- fork: independent work on s2 ----
    cudaEventRecord(s.evFork, 0);
    cudaStreamWaitEvent(s.s2, s.evFork, 0);

    // s2: query branch (stats, q_pb -> fp16, qcol), then stage 10a
    row_stats4k<<<16 * 256, 256, 0, s.s2>>>(query, s.qmax, s.qinvs);
    mgemm<true, true, false, false, false, false, true, false><<<dim3(4, 2, 16), 128, TG_SMEM, s.s2>>>(
        query, query, s.qpb, 256, 256, 4096, 4096, 256L * 4096, 256L * 4096,
        16, 256L * 256, 0, 256,
        s.qmax, s.qinvs, nullptr, nullptr, 1.f);
    qcol_norm<<<dim3(16, 16), 256, 0, s.s2>>>(query, s.qcol);
    // 10a) out = f_w16[:, :512] @ x + f_b
    mgemm<false, false, true, false, true, false, false, false><<<dim3(64, 4, 16), 128, TG_SMEM, s.s2>>>(
        s.fwh, x, out, 512, 4096, 512, 768, 0, 512L * 4096,
        16, 512L * 4096, 0, 4096,
        nullptr, nullptr, f_b, nullptr, 1.f);

    // main: kf chain
    // 1) kf[z] = K_w16 @ refs[z] + K_b  -> fp16 kf
    mgemm<false, false, true, false, true, false, true, false><<<dim3(64, 2, 48), 128, TG_SMEM>>>(
        s.kwh, refs, s.kf, 256, 4096, 512, 512, 0, 512L * 4096,
        48, 256L * 4096, 0, 4096,
        nullptr, nullptr, K_b, nullptr, 1.f);

    // 2) kf softmax row stats (fp16 input)
    row_stats4k_h<<<48 * 256, 256>>>(s.kf, s.kmax, s.kinv);

    // 3) k_pb[z] = softmax(kf[z]) @ kf[z]^T  -> fp16 kpbs
    mgemm<true, true, false, false, true, true, true, false><<<dim3(4, 2, 48), 128, TG_SMEM>>>(
        s.kf, s.kf, s.kpbs, 256, 256, 4096, 4096, 256L * 4096, 256L * 4096,
        16, 768L * 256, 256L * 256, 256,
        s.kmax, s.kinv, nullptr, nullptr, 1.f);

    // ---- join s2 (q_pb + out ready) before stage 5 ----
    cudaEventRecord(s.evJoin, s.s2);
    cudaStreamWaitEvent(0, s.evJoin, 0);

    // 5) sim = (q_pb16 @ kpbs16^T) / sqrt(256)  -> fp32 sim
    mgemm<true, false, false, false, true, true, false, false><<<dim3(12, 2, 16), 128, TG_SMEM>>>(
        s.qpb, s.kpbs, s.sim, 256, 768, 256, 256, 256L * 256, 768L * 256,
        16, 256L * 768, 0, 768,
        nullptr, nullptr, nullptr, nullptr, 0.0625f);

    // 6) softmax over k (fp32, logit accuracy preserved)
    softmax_inplace<<<16 * 256, 256>>>(s.sim, 768);

    // 7) value = sim @ kpbs16 (NN)  -> fp32
    mgemm<false, false, false, false, false, true, false, false><<<dim3(4, 2, 16), 128, TG_SMEM>>>(
        s.sim, s.kpbs, s.value, 256, 256, 768, 768, 256L * 768, 768L * 256,
        16, 256L * 256, 0, 256,
        nullptr, nullptr, nullptr, nullptr, 1.f);

    // 8) normalize prototypes -> fp16
    norm_rows256h<<<16 * 256, 256>>>(s.value, s.valh);

    // 9) cm = (proto16 @ query) * qcol  -> fp16
    mgemm<false, false, false, false, true, false, true, true><<<dim3(64, 2, 16), 128, TG_SMEM>>>(
        s.valh, query, s.cm, 256, 4096, 256, 256, 256L * 256, 256L * 4096,
        16, 256L * 4096, 0, 4096,
        nullptr, nullptr, nullptr, s.qcol, 1.f);

    // 10b) out += f_w16[:, 512:] @ cm16   (ACCUM)
    mgemm<false, false, false, true, true, true, false, false><<<dim3(64, 4, 16), 128, TG_SMEM>>>(
        s.fwh + 512, s.cm, out, 512, 4096, 256, 768, 0, 256L * 4096,
        16, 512L * 4096, 0, 4096,
        nullptr, nullptr, nullptr, nullptr, 1.f);

    // 11) BatchNorm (batch stats) + ReLU
    bn_stats<<<512, 256>>>(out, s.mean, s.istd);
    bn_apply<<<131072, 256>>>(out, s.mean, s.istd, bn_g, bn_b);
}